// round 1
// baseline (speedup 1.0000x reference)
#include <cuda_runtime.h>
#include <math.h>

#define NTOK 4096
#define TT   2048
#define CC   1024
#define HH   16
#define HD   64
#define EE   8
#define CAPX 1024
#define HID  4096

// ---------------- scratch (device globals; no allocations) ----------------
__device__ float g_xmix[(size_t)NTOK*CC];          // 16 MB
__device__ float g_a   [(size_t)NTOK*CC];          // 16 MB  rmsnorm(x)
__device__ float g_qkv [(size_t)3*NTOK*CC];        // 48 MB
__device__ float g_o   [(size_t)NTOK*CC];          // 16 MB  attention out
__device__ float g_h   [(size_t)NTOK*CC];          // 16 MB  rmsnorm(x2)
__device__ float g_h1  [(size_t)EE*CAPX*HID];      // 128 MB
__device__ float g_oe  [(size_t)EE*CAPX*CC];       // 32 MB
__device__ float g_g0  [NTOK];
__device__ int   g_eid [NTOK];
__device__ int   g_idx [EE*CAPX];
__device__ int   g_cnt [EE];

// rotary inv-freq table: (1/1024)^(j/15) = 2^(-2j/3), exact-to-double values
__constant__ float c_rotinv[16] = {
    1.0f,
    0.6299605249474366f,
    0.39685026299204984f,
    0.25f,
    0.15749013123685915f,
    0.09921256574801246f,
    0.0625f,
    0.03937253280921479f,
    0.024803141437003115f,
    0.015625f,
    0.009843133202303697f,
    0.0062007853592507785f,
    0.00390625f,
    0.0024607833005759242f,
    0.0015501963398126947f,
    0.0009765625f
};

// ---------------- block reduce ----------------
__device__ __forceinline__ float blockReduceSum(float v) {
    __shared__ float sh[32];
    int lane = threadIdx.x & 31, w = threadIdx.x >> 5;
    #pragma unroll
    for (int o = 16; o; o >>= 1) v += __shfl_down_sync(0xffffffffu, v, o);
    if (lane == 0) sh[w] = v;
    __syncthreads();
    int nw = blockDim.x >> 5;
    if (w == 0) {
        v = (lane < nw) ? sh[lane] : 0.f;
        #pragma unroll
        for (int o = 16; o; o >>= 1) v += __shfl_down_sync(0xffffffffu, v, o);
        if (lane == 0) sh[0] = v;
    }
    __syncthreads();
    return sh[0];
}

// ---------------- 1) residual mix + rmsnorm ----------------
__global__ void mix_rms_kernel(const float* __restrict__ x, const float* __restrict__ x0,
                               const float* __restrict__ lambdas) {
    int row = blockIdx.x;
    float l0 = lambdas[0], l1 = lambdas[1];
    size_t off = (size_t)row * CC + threadIdx.x * 4;
    float4 a = *(const float4*)(x + off);
    float4 b = *(const float4*)(x0 + off);
    float4 v;
    v.x = l0*a.x + l1*b.x; v.y = l0*a.y + l1*b.y;
    v.z = l0*a.z + l1*b.z; v.w = l0*a.w + l1*b.w;
    *(float4*)(g_xmix + off) = v;
    float ss = v.x*v.x + v.y*v.y + v.z*v.z + v.w*v.w;
    float tot = blockReduceSum(ss);
    float sc = rsqrtf(tot * (1.0f/CC) + 1e-6f);
    float4 o; o.x = v.x*sc; o.y = v.y*sc; o.z = v.z*sc; o.w = v.w*sc;
    *(float4*)(g_a + off) = o;
}

// ---------------- 6) rmsnorm of x2 (reads d_out) ----------------
__global__ void rms2_kernel(const float* __restrict__ src) {
    int row = blockIdx.x;
    size_t off = (size_t)row * CC + threadIdx.x * 4;
    float4 v = *(const float4*)(src + off);
    float ss = v.x*v.x + v.y*v.y + v.z*v.z + v.w*v.w;
    float tot = blockReduceSum(ss);
    float sc = rsqrtf(tot * (1.0f/CC) + 1e-6f);
    float4 o; o.x = v.x*sc; o.y = v.y*sc; o.z = v.z*sc; o.w = v.w*sc;
    *(float4*)(g_h + off) = o;
}

// ---------------- generic NT GEMM: C[M,Nt] = A[M,K] * B[Nt,K]^T ----------------
// EPI: 0=none 1=+bias 2=+bias+resid 3=sq(relu(+bias))
template<int EPI, bool GATHER, bool SKIP>
__global__ __launch_bounds__(128)
void gemm_nt(const float* __restrict__ A, long aStride,
             const float* __restrict__ Bm, long bStride,
             float* __restrict__ Cm, long cStride,
             const float* __restrict__ bias, int biasStride,
             const float* __restrict__ resid,
             const int* __restrict__ rowIdx,
             const int* __restrict__ counts,
             int Nt, int Kd) {
    const int BM = 64, BN = 64, BK = 16;
    __shared__ float As[BK][BM];
    __shared__ float Bs[BK][BN];
    int z = blockIdx.z;
    int m0 = blockIdx.y * BM, n0 = blockIdx.x * BN;
    if (SKIP) { if (m0 >= counts[z]) return; }
    const float* Az = A + (size_t)z * aStride;
    const float* Bz = Bm + (size_t)z * bStride;
    float*       Cz = Cm + (size_t)z * cStride;
    int tid = threadIdx.x;
    int lr = tid >> 2;         // 0..31
    int lc = (tid & 3) * 4;    // 0,4,8,12
    int r0, r1;
    if (GATHER) {
        int i0 = rowIdx[z * CAPX + m0 + lr];
        int i1 = rowIdx[z * CAPX + m0 + lr + 32];
        r0 = min(i0, NTOK - 1); r1 = min(i1, NTOK - 1);
    } else { r0 = m0 + lr; r1 = r0 + 32; }
    const float* ap0 = Az + (size_t)r0 * Kd + lc;
    const float* ap1 = Az + (size_t)r1 * Kd + lc;
    const float* bp0 = Bz + (size_t)(n0 + lr) * Kd + lc;
    const float* bp1 = Bz + (size_t)(n0 + lr + 32) * Kd + lc;

    float acc[4][8];
    #pragma unroll
    for (int i = 0; i < 4; i++)
        #pragma unroll
        for (int j = 0; j < 8; j++) acc[i][j] = 0.f;

    int tm = (tid >> 3) * 4;   // 0..60
    int tn = (tid & 7) * 8;    // 0..56

    for (int k0 = 0; k0 < Kd; k0 += BK) {
        float4 a0 = *(const float4*)(ap0 + k0);
        float4 a1 = *(const float4*)(ap1 + k0);
        float4 b0 = *(const float4*)(bp0 + k0);
        float4 b1 = *(const float4*)(bp1 + k0);
        __syncthreads();
        As[lc+0][lr] = a0.x; As[lc+1][lr] = a0.y; As[lc+2][lr] = a0.z; As[lc+3][lr] = a0.w;
        As[lc+0][lr+32] = a1.x; As[lc+1][lr+32] = a1.y; As[lc+2][lr+32] = a1.z; As[lc+3][lr+32] = a1.w;
        Bs[lc+0][lr] = b0.x; Bs[lc+1][lr] = b0.y; Bs[lc+2][lr] = b0.z; Bs[lc+3][lr] = b0.w;
        Bs[lc+0][lr+32] = b1.x; Bs[lc+1][lr+32] = b1.y; Bs[lc+2][lr+32] = b1.z; Bs[lc+3][lr+32] = b1.w;
        __syncthreads();
        #pragma unroll
        for (int kk = 0; kk < BK; kk++) {
            float4 af  = *(const float4*)&As[kk][tm];
            float4 bf0 = *(const float4*)&Bs[kk][tn];
            float4 bf1 = *(const float4*)&Bs[kk][tn + 4];
            float a_[4] = {af.x, af.y, af.z, af.w};
            float b_[8] = {bf0.x, bf0.y, bf0.z, bf0.w, bf1.x, bf1.y, bf1.z, bf1.w};
            #pragma unroll
            for (int i = 0; i < 4; i++)
                #pragma unroll
                for (int j = 0; j < 8; j++)
                    acc[i][j] += a_[i] * b_[j];
        }
    }

    float bv[8];
    if (EPI >= 1) {
        #pragma unroll
        for (int j = 0; j < 8; j++) bv[j] = bias[(size_t)z * biasStride + n0 + tn + j];
    }
    #pragma unroll
    for (int i = 0; i < 4; i++) {
        int row = m0 + tm + i;
        float* cp = Cz + (size_t)row * Nt + n0 + tn;
        const float* rp = (EPI == 2) ? (resid + (size_t)row * Nt + n0 + tn) : nullptr;
        #pragma unroll
        for (int j = 0; j < 8; j += 4) {
            float vv[4];
            #pragma unroll
            for (int q = 0; q < 4; q++) {
                float t = acc[i][j + q];
                if (EPI == 1)      t += bv[j + q];
                else if (EPI == 2) t += bv[j + q] + rp[j + q];
                else if (EPI == 3) { t += bv[j + q]; t = t > 0.f ? t * t : 0.f; }
                vv[q] = t;
            }
            float4 v4; v4.x = vv[0]; v4.y = vv[1]; v4.z = vv[2]; v4.w = vv[3];
            *(float4*)(cp + j) = v4;
        }
    }
}

// ---------------- 3) per-head rmsnorm + rotary for q,k (in place) ----------------
__global__ void qk_rot_kernel() {
    int gw = blockIdx.x * (blockDim.x >> 5) + (threadIdx.x >> 5);
    int lane = threadIdx.x & 31;
    int qk = gw >> 16;              // / (NTOK*HH) = 65536
    int r  = gw & 65535;
    int n  = r >> 4;
    int h  = r & 15;
    float* p = g_qkv + (size_t)qk * NTOK * CC + (size_t)n * CC + h * HD;
    float x1 = p[lane], x2 = p[lane + 32];
    float ss = x1 * x1 + x2 * x2;
    #pragma unroll
    for (int o = 16; o; o >>= 1) ss += __shfl_xor_sync(0xffffffffu, ss, o);
    float sc = rsqrtf(ss * (1.0f/HD) + 1e-6f);
    x1 *= sc; x2 *= sc;
    int t = n & (TT - 1);
    float invj = (lane < 16) ? c_rotinv[lane] : 0.f;
    float th = (float)t * invj;
    float c = cosf(th), s = sinf(th);
    p[lane]      =  x1 * c + x2 * s;
    p[lane + 32] = -x1 * s + x2 * c;
}

// ---------------- 4) causal flash attention ----------------
__global__ __launch_bounds__(128)
void attn_kernel() {
    __shared__ float Ks[32 * 64];
    __shared__ float Vs[32 * 64];
    int bh = blockIdx.y;
    int b = bh >> 4, h = bh & 15;
    int tq = blockIdx.x * 128 + threadIdx.x;
    const float* qb_ = g_qkv + (size_t)(b * TT) * CC + h * HD;
    const float* kb_ = g_qkv + (size_t)NTOK * CC + (size_t)(b * TT) * CC + h * HD;
    const float* vb_ = g_qkv + (size_t)2 * NTOK * CC + (size_t)(b * TT) * CC + h * HD;
    float q[HD];
    #pragma unroll
    for (int d = 0; d < HD; d += 4) {
        float4 t = *(const float4*)(qb_ + (size_t)tq * CC + d);
        q[d] = t.x * 0.125f; q[d+1] = t.y * 0.125f; q[d+2] = t.z * 0.125f; q[d+3] = t.w * 0.125f;
    }
    float m = -1e30f, l = 0.f;
    float o[HD];
    #pragma unroll
    for (int d = 0; d < HD; d++) o[d] = 0.f;
    int ntiles = (blockIdx.x * 128 + 128) >> 5;
    for (int kt = 0; kt < ntiles; kt++) {
        int kb = kt * 32;
        __syncthreads();
        #pragma unroll
        for (int i = 0; i < 4; i++) {
            int f = threadIdx.x + i * 128;
            int r = f >> 4, c = (f & 15) * 4;
            *(float4*)(Ks + r * 64 + c) = *(const float4*)(kb_ + (size_t)(kb + r) * CC + c);
            *(float4*)(Vs + r * 64 + c) = *(const float4*)(vb_ + (size_t)(kb + r) * CC + c);
        }
        __syncthreads();
        float s[32];
        float mt = m;
        #pragma unroll
        for (int j = 0; j < 32; j++) {
            float acc = 0.f;
            const float* kr = Ks + j * 64;
            #pragma unroll
            for (int d = 0; d < HD; d += 4) {
                float4 kv = *(const float4*)(kr + d);
                acc += q[d]*kv.x + q[d+1]*kv.y + q[d+2]*kv.z + q[d+3]*kv.w;
            }
            s[j] = (kb + j <= tq) ? acc : -1e30f;
            mt = fmaxf(mt, s[j]);
        }
        float alpha = expf(m - mt);
        float psum = 0.f;
        #pragma unroll
        for (int j = 0; j < 32; j++) { s[j] = expf(s[j] - mt); psum += s[j]; }
        l = l * alpha + psum;
        #pragma unroll
        for (int d = 0; d < HD; d++) o[d] *= alpha;
        #pragma unroll
        for (int j = 0; j < 32; j++) {
            float p = s[j];
            const float* vr = Vs + j * 64;
            #pragma unroll
            for (int d = 0; d < HD; d += 4) {
                float4 vv = *(const float4*)(vr + d);
                o[d] += p*vv.x; o[d+1] += p*vv.y; o[d+2] += p*vv.z; o[d+3] += p*vv.w;
            }
        }
        m = mt;
    }
    float inv = 1.f / l;
    float* op = g_o + (size_t)(b * TT + tq) * CC + h * HD;
    #pragma unroll
    for (int d = 0; d < HD; d += 4) {
        float4 t; t.x = o[d]*inv; t.y = o[d+1]*inv; t.z = o[d+2]*inv; t.w = o[d+3]*inv;
        *(float4*)(op + d) = t;
    }
}

// ---------------- 7) router: logits, noisy top-2, gate0, eid ----------------
__global__ void router_kernel(const float* __restrict__ rw, const float* __restrict__ rb,
                              const float* __restrict__ nw, const float* __restrict__ nb,
                              const float* __restrict__ noise) {
    int n = blockIdx.x;
    int w = threadIdx.x >> 5, lane = threadIdx.x & 31;
    const float* hr = g_h + (size_t)n * CC;
    const float* wr = rw + (size_t)w * CC;
    const float* wn = nw + (size_t)w * CC;
    float s1 = 0.f, s2 = 0.f;
    for (int c = lane * 4; c < CC; c += 128) {
        float4 hv = *(const float4*)(hr + c);
        float4 r4 = *(const float4*)(wr + c);
        float4 n4 = *(const float4*)(wn + c);
        s1 += hv.x*r4.x + hv.y*r4.y + hv.z*r4.z + hv.w*r4.w;
        s2 += hv.x*n4.x + hv.y*n4.y + hv.z*n4.z + hv.w*n4.w;
    }
    #pragma unroll
    for (int o = 16; o; o >>= 1) {
        s1 += __shfl_xor_sync(0xffffffffu, s1, o);
        s2 += __shfl_xor_sync(0xffffffffu, s2, o);
    }
    __shared__ float lg[8], nl[8];
    if (lane == 0) { lg[w] = s1 + rb[w]; nl[w] = s2 + nb[w]; }
    __syncthreads();
    if (threadIdx.x == 0) {
        float nv[8];
        #pragma unroll
        for (int e = 0; e < 8; e++) {
            float xn = nl[e];
            float sp = (xn > 20.f) ? xn : log1pf(expf(xn));
            nv[e] = lg[e] + noise[(size_t)n * EE + e] * sp;
        }
        int i0 = 0; float v0 = nv[0];
        #pragma unroll
        for (int e = 1; e < 8; e++) if (nv[e] > v0) { v0 = nv[e]; i0 = e; }
        float v1 = -1e30f;
        #pragma unroll
        for (int e = 0; e < 8; e++) if (e != i0 && nv[e] > v1) { v1 = nv[e]; }
        float e1 = expf(v1 - v0);
        g_g0[n] = 1.f / (1.f + e1);
        g_eid[n] = i0;
    }
}

// ---------------- 8) per-expert capacity lists (ballot scan) ----------------
__global__ void build_idx_kernel() {
    int w = threadIdx.x >> 5, lane = threadIdx.x & 31;   // warp w = expert w
    int count = 0;
    for (int base = 0; base < NTOK; base += 32) {
        int t = base + lane;
        bool p = (g_eid[t] == w);
        unsigned msk = __ballot_sync(0xffffffffu, p);
        int pos = count + __popc(msk & ((1u << lane) - 1u));
        if (p && pos < CAPX) g_idx[w * CAPX + pos] = t;
        count += __popc(msk);
    }
    int c = min(count, CAPX);
    if (lane == 0) g_cnt[w] = c;
    for (int s = c + lane; s < CAPX; s += 32) g_idx[w * CAPX + s] = NTOK;  // sentinel
}

// ---------------- 11) scatter: out[token] += g0 * oe[slot] ----------------
__global__ void scatter_kernel(float* __restrict__ out) {
    int e = blockIdx.x >> 10;
    int slot = blockIdx.x & (CAPX - 1);
    if (slot >= g_cnt[e]) return;
    int t = g_idx[e * CAPX + slot];
    float g = g_g0[t];
    const float* src = g_oe + ((size_t)e * CAPX + slot) * CC;
    float* dst = out + (size_t)t * CC;
    int c = threadIdx.x * 4;
    float4 s = *(const float4*)(src + c);
    float4 d = *(const float4*)(dst + c);
    d.x += g * s.x; d.y += g * s.y; d.z += g * s.z; d.w += g * s.w;
    *(float4*)(dst + c) = d;
}

// ---------------- host launcher ----------------
extern "C" void kernel_launch(void* const* d_in, const int* in_sizes, int n_in,
                              void* d_out, int out_size) {
    const float* x        = (const float*)d_in[0];
    const float* x0       = (const float*)d_in[1];
    const float* noise    = (const float*)d_in[2];
    const float* lambdas  = (const float*)d_in[3];
    /* d_in[4] = lamb: (1-lamb)*v + lamb*v == v, unused */
    const float* qkv_w    = (const float*)d_in[5];
    const float* c_proj_w = (const float*)d_in[6];
    const float* c_proj_b = (const float*)d_in[7];
    const float* router_w = (const float*)d_in[8];
    const float* router_b = (const float*)d_in[9];
    const float* noise_w  = (const float*)d_in[10];
    const float* noise_b  = (const float*)d_in[11];
    const float* ew1      = (const float*)d_in[12];
    const float* eb1      = (const float*)d_in[13];
    const float* ew2      = (const float*)d_in[14];
    const float* eb2      = (const float*)d_in[15];
    float* out = (float*)d_out;

    void *p_a, *p_qkv, *p_o, *p_xmix, *p_h, *p_h1, *p_oe, *p_idx, *p_cnt;
    cudaGetSymbolAddress(&p_a,    g_a);
    cudaGetSymbolAddress(&p_qkv,  g_qkv);
    cudaGetSymbolAddress(&p_o,    g_o);
    cudaGetSymbolAddress(&p_xmix, g_xmix);
    cudaGetSymbolAddress(&p_h,    g_h);
    cudaGetSymbolAddress(&p_h1,   g_h1);
    cudaGetSymbolAddress(&p_oe,   g_oe);
    cudaGetSymbolAddress(&p_idx,  g_idx);
    cudaGetSymbolAddress(&p_cnt,  g_cnt);

    // 1) x = l0*x + l1*x0 ; a = rmsnorm(x)
    mix_rms_kernel<<<NTOK, 256>>>(x, x0, lambdas);

    // 2) qkv = a @ qkv_w[k]^T   (z = 0..2)
    gemm_nt<0, false, false><<<dim3(CC/64, NTOK/64, 3), 128>>>(
        (const float*)p_a, 0L, qkv_w, (long)CC*CC,
        (float*)p_qkv, (long)NTOK*CC,
        nullptr, 0, nullptr, nullptr, nullptr, CC, CC);

    // 3) per-head rmsnorm + rotary on q,k
    qk_rot_kernel<<<(2 * NTOK * HH) / 8, 256>>>();

    // 4) causal attention -> g_o (B,T,C layout)
    attn_kernel<<<dim3(TT/128, 2*HH), 128>>>();

    // 5) x2 = xmix + o @ c_proj_w^T + b  -> d_out
    gemm_nt<2, false, false><<<dim3(CC/64, NTOK/64, 1), 128>>>(
        (const float*)p_o, 0L, c_proj_w, 0L,
        out, 0L,
        c_proj_b, 0, (const float*)p_xmix, nullptr, nullptr, CC, CC);

    // 6) h = rmsnorm(x2)
    rms2_kernel<<<NTOK, 256>>>(out);

    // 7) router
    router_kernel<<<NTOK, 256>>>(router_w, router_b, noise_w, noise_b, noise);

    // 8) per-expert index lists
    build_idx_kernel<<<1, 256>>>();

    // 9) h1 = sq(relu(gather(h) @ ew1^T + eb1))   (gathered, capacity-skipped)
    gemm_nt<3, true, true><<<dim3(HID/64, CAPX/64, EE), 128>>>(
        (const float*)p_h, 0L, ew1, (long)HID*CC,
        (float*)p_h1, (long)CAPX*HID,
        eb1, HID, nullptr, (const int*)p_idx, (const int*)p_cnt, HID, CC);

    // 10) oe = h1 @ ew2^T + eb2
    gemm_nt<1, false, true><<<dim3(CC/64, CAPX/64, EE), 128>>>(
        (const float*)p_h1, (long)CAPX*HID, ew2, (long)CC*HID,
        (float*)p_oe, (long)CAPX*CC,
        eb2, CC, nullptr, nullptr, (const int*)p_cnt, CC, HID);

    // 11) out += g0 * oe (scatter; conflict-free)
    scatter_kernel<<<EE * CAPX, 256>>>(out);
}

// round 3
// speedup vs baseline: 2.7840x; 2.7840x over previous
#include <cuda_runtime.h>
#include <cuda_bf16.h>
#include <math.h>
#include <stdint.h>

#define NTOK 4096
#define TT   2048
#define CC   1024
#define HH   16
#define HD   64
#define EE   8
#define CAPX 1024
#define HID  4096

// tcgen05 is an arch-SPECIFIC feature: only emit it in the sm_103a/f pass.
#if defined(__CUDA_ARCH__)
# if (__CUDA_ARCH__ >= 1000) && (defined(__CUDA_ARCH_FEAT_SM103_ALL) || defined(__CUDA_ARCH_FEAT_SM100_ALL) || defined(__CUDA_ARCH_SPECIFIC__) || defined(__CUDA_ARCH_FAMILY_SPECIFIC__))
#  define USE_TC 1
# else
#  define USE_TC 0
# endif
#else
# define USE_TC 0
#endif

// ---------------- scratch (device globals; no allocations) ----------------
__device__ float g_xmix[(size_t)NTOK*CC];
__device__ float g_a   [(size_t)NTOK*CC];
__device__ float g_qkv [(size_t)3*NTOK*CC];
__device__ float g_o   [(size_t)NTOK*CC];
__device__ float g_h   [(size_t)NTOK*CC];
__device__ float g_h1  [(size_t)EE*CAPX*HID];
__device__ float g_oe  [(size_t)EE*CAPX*CC];
__device__ float g_g0  [NTOK];
__device__ int   g_eid [NTOK];
__device__ int   g_idx [EE*CAPX];
__device__ int   g_cnt [EE];

__constant__ float c_rotinv[16] = {
    1.0f, 0.6299605249474366f, 0.39685026299204984f, 0.25f,
    0.15749013123685915f, 0.09921256574801246f, 0.0625f, 0.03937253280921479f,
    0.024803141437003115f, 0.015625f, 0.009843133202303697f, 0.0062007853592507785f,
    0.00390625f, 0.0024607833005759242f, 0.0015501963398126947f, 0.0009765625f
};

// ================= tcgen05 helpers (only referenced when USE_TC) =================
__device__ __forceinline__ uint32_t smem_u32(const void* p) {
    uint32_t a;
    asm("{ .reg .u64 t; cvta.to.shared.u64 t, %1; cvt.u32.u64 %0, t; }" : "=r"(a) : "l"(p));
    return a;
}

#if USE_TC
__device__ __forceinline__ uint32_t elect_one() {
    uint32_t p;
    asm volatile("{\n\t.reg .pred p;\n\telect.sync _|p, 0xFFFFFFFF;\n\tselp.b32 %0, 1, 0, p;\n\t}" : "=r"(p));
    return p;
}
#define MBAR_INIT(addr, cnt) \
    asm volatile("mbarrier.init.shared.b64 [%0], %1;" :: "r"(addr), "r"(cnt) : "memory")
__device__ __forceinline__ void mbar_wait(uint32_t addr, int phase) {
    uint32_t done = 0;
    while (!done) {
        asm volatile("{\n\t.reg .pred p;\n\t"
            "mbarrier.try_wait.parity.acquire.cta.shared::cta.b64 p, [%1], %2, 0x989680;\n\t"
            "selp.b32 %0, 1, 0, p;\n\t}" : "=r"(done) : "r"(addr), "r"(phase) : "memory");
    }
}
#define TC_ALLOC(addr, n) \
    asm volatile("tcgen05.alloc.cta_group::1.sync.aligned.shared::cta.b32 [%0], %1;" :: "r"(addr), "r"(n) : "memory")
#define TC_DEALLOC(tm, n) \
    asm volatile("tcgen05.dealloc.cta_group::1.sync.aligned.b32 %0, %1;" :: "r"(tm), "r"(n))
#define TC_RELINQ() \
    asm volatile("tcgen05.relinquish_alloc_permit.cta_group::1.sync.aligned;")
#define TC_COMMIT(mbar) \
    asm volatile("tcgen05.commit.cta_group::1.mbarrier::arrive::one.shared::cluster.b64 [%0];" :: "r"(mbar) : "memory")
#define TC_FENCE_AFTER()  asm volatile("tcgen05.fence::after_thread_sync;" ::: "memory")
#define TC_FENCE_BEFORE() asm volatile("tcgen05.fence::before_thread_sync;" ::: "memory")
#define TC_WAIT_LD()      asm volatile("tcgen05.wait::ld.sync.aligned;" ::: "memory")

#define TC_LD_X32(r, a) \
    asm volatile("tcgen05.ld.sync.aligned.32x32b.x32.b32 " \
        "{%0,%1,%2,%3,%4,%5,%6,%7,%8,%9,%10,%11,%12,%13,%14,%15," \
        "%16,%17,%18,%19,%20,%21,%22,%23,%24,%25,%26,%27,%28,%29,%30,%31}, [%32];" \
        : "=r"((r)[0]),"=r"((r)[1]),"=r"((r)[2]),"=r"((r)[3]),"=r"((r)[4]),"=r"((r)[5]),"=r"((r)[6]),"=r"((r)[7]), \
          "=r"((r)[8]),"=r"((r)[9]),"=r"((r)[10]),"=r"((r)[11]),"=r"((r)[12]),"=r"((r)[13]),"=r"((r)[14]),"=r"((r)[15]), \
          "=r"((r)[16]),"=r"((r)[17]),"=r"((r)[18]),"=r"((r)[19]),"=r"((r)[20]),"=r"((r)[21]),"=r"((r)[22]),"=r"((r)[23]), \
          "=r"((r)[24]),"=r"((r)[25]),"=r"((r)[26]),"=r"((r)[27]),"=r"((r)[28]),"=r"((r)[29]),"=r"((r)[30]),"=r"((r)[31]) \
        : "r"(a))

__device__ __forceinline__ void mma_ss_bf16(uint32_t d, uint64_t ad, uint64_t bd,
                                            uint32_t idesc, uint32_t en) {
    asm volatile("{\n\t.reg .pred p;\n\tsetp.ne.u32 p, %4, 0;\n\t"
        "tcgen05.mma.cta_group::1.kind::f16 [%0], %1, %2, %3, {%5,%5,%5,%5}, p;\n\t}"
        :: "r"(d), "l"(ad), "l"(bd), "r"(idesc), "r"(en), "r"(0u) : "memory");
}

// SW128 desc: layout=2, version=1, SBO=64, LBO=1
__device__ __forceinline__ uint64_t make_desc(uint32_t base) {
    const uint64_t B = (uint64_t(2) << 61) | (uint64_t(1) << 46) | (uint64_t(64) << 32) | (uint64_t(1) << 16);
    return B | ((uint64_t)(base >> 4) & 0x3FFF);
}
#endif // USE_TC

__device__ __forceinline__ uint32_t sw128(uint32_t off) { return off ^ ((off >> 3) & 0x70); }

__device__ __forceinline__ void store_hilo(char* hi_base, char* lo_base,
                                           uint32_t byteoff, float4 v) {
    __nv_bfloat16 h0 = __float2bfloat16_rn(v.x);
    __nv_bfloat16 h1 = __float2bfloat16_rn(v.y);
    __nv_bfloat16 h2 = __float2bfloat16_rn(v.z);
    __nv_bfloat16 h3 = __float2bfloat16_rn(v.w);
    float l0 = v.x - __bfloat162float(h0);
    float l1 = v.y - __bfloat162float(h1);
    float l2 = v.z - __bfloat162float(h2);
    float l3 = v.w - __bfloat162float(h3);
    __nv_bfloat162 hp0; hp0.x = h0; hp0.y = h1;
    __nv_bfloat162 hp1; hp1.x = h2; hp1.y = h3;
    __nv_bfloat162 lp0 = __floats2bfloat162_rn(l0, l1);
    __nv_bfloat162 lp1 = __floats2bfloat162_rn(l2, l3);
    uint32_t so = sw128(byteoff);
    uint2 hv; hv.x = *(uint32_t*)&hp0; hv.y = *(uint32_t*)&hp1;
    uint2 lv; lv.x = *(uint32_t*)&lp0; lv.y = *(uint32_t*)&lp1;
    *(uint2*)(hi_base + so) = hv;
    *(uint2*)(lo_base + so) = lv;
}

// ======= GEMM: C[M,Nt] = A[M,K]*B[Nt,K]^T, tile 128x128 =======
// tcgen05 path: 3xBF16 split. Fallback path: SIMT fp32 (used only by the
// non-arch-specific PTX pass, which the runtime never selects when sm_103a
// SASS is present).
// EPI: 0=none 1=+bias 2=+bias+resid 3=sq(relu(+bias))
#define TILE_BYTES 16384
#define BUF_BYTES  65536
#define SMEM_TOTAL_TC (1024 + 2*BUF_BYTES)

template<int EPI, bool GATHER, bool SKIP>
__global__ __launch_bounds__(256)
void gemm_tc(const float* __restrict__ A, long aStride,
             const float* __restrict__ Bm, long bStride,
             float* __restrict__ Cm, long cStride,
             const float* __restrict__ bias, int biasStride,
             const float* __restrict__ resid,
             const int* __restrict__ rowIdx,
             const int* __restrict__ counts,
             int Nt, int Kd) {
    extern __shared__ char smem[];
    const int z = blockIdx.z;
    const int m0 = blockIdx.y * 128, n0 = blockIdx.x * 128;
    if (SKIP) { if (m0 >= counts[z]) return; }
    int tid = threadIdx.x, wid = tid >> 5, lane = tid & 31;

    const uint32_t OFF_TM = 0, OFF_MB = 8, OFF_RID = 64, OFF_TILE = 1024;
    int* s_rid = (int*)(smem + OFF_RID);

    if (tid < 128) {
        int r;
        if (GATHER) r = min(rowIdx[z * CAPX + m0 + tid], NTOK - 1);
        else        r = m0 + tid;
        s_rid[tid] = r;
    }

    const float* Az = A + (size_t)z * aStride;
    const float* Bz = Bm + (size_t)z * bStride;

#if USE_TC
    uint32_t sbase = smem_u32(smem);
    if (tid == 0) { MBAR_INIT(sbase + OFF_MB, 1); MBAR_INIT(sbase + OFF_MB + 8, 1); }
    if (wid == 0) { TC_ALLOC(sbase + OFF_TM, 128u); }
    __syncthreads();
    uint32_t tmem = *(uint32_t*)(smem + OFF_TM);

    const uint32_t idesc = (1u << 4) | (1u << 7) | (1u << 10) | (16u << 17) | (8u << 24);

    int nchunks = Kd >> 6;
    int ph0 = 0, ph1 = 0;

    for (int c = 0; c < nchunks; c++) {
        int buf = c & 1;
        char* tb = smem + OFF_TILE + buf * BUF_BYTES;
        if (c >= 2) {
            if (buf == 0) { mbar_wait(sbase + OFF_MB, ph0); ph0 ^= 1; }
            else          { mbar_wait(sbase + OFF_MB + 8, ph1); ph1 ^= 1; }
        }
        int k0 = c * 64;
        #pragma unroll
        for (int i = 0; i < 8; i++) {
            int f = tid + i * 256;
            int row = f >> 4, c4 = f & 15;
            const float4 v = *(const float4*)(Az + (size_t)s_rid[row] * Kd + k0 + c4 * 4);
            store_hilo(tb, tb + TILE_BYTES, (uint32_t)(row * 128 + c4 * 8), v);
        }
        #pragma unroll
        for (int i = 0; i < 8; i++) {
            int f = tid + i * 256;
            int row = f >> 4, c4 = f & 15;
            const float4 v = *(const float4*)(Bz + (size_t)(n0 + row) * Kd + k0 + c4 * 4);
            store_hilo(tb + 2 * TILE_BYTES, tb + 3 * TILE_BYTES, (uint32_t)(row * 128 + c4 * 8), v);
        }
        asm volatile("fence.proxy.async.shared::cta;" ::: "memory");
        __syncthreads();
        if (wid == 0) {
            if (elect_one()) {
                uint32_t base = sbase + OFF_TILE + buf * BUF_BYTES;
                uint64_t ah = make_desc(base);
                uint64_t al = make_desc(base + TILE_BYTES);
                uint64_t bh = make_desc(base + 2 * TILE_BYTES);
                uint64_t bl = make_desc(base + 3 * TILE_BYTES);
                #pragma unroll
                for (int ks = 0; ks < 4; ks++) {
                    uint64_t o = ks * 2;
                    mma_ss_bf16(tmem, ah + o, bh + o, idesc, (c > 0 || ks > 0) ? 1u : 0u);
                    mma_ss_bf16(tmem, ah + o, bl + o, idesc, 1u);
                    mma_ss_bf16(tmem, al + o, bh + o, idesc, 1u);
                }
                TC_COMMIT(sbase + OFF_MB + 8 * buf);
            }
        }
    }
    mbar_wait(sbase + OFF_MB, ph0);
    mbar_wait(sbase + OFF_MB + 8, ph1);
    TC_FENCE_AFTER();

    int colbase = (wid >> 2) * 64;
    int row = (wid & 3) * 32 + lane;
    uint32_t d_regs[64];
    TC_LD_X32(d_regs, tmem + colbase);
    TC_LD_X32(d_regs + 32, tmem + colbase + 32);
    TC_WAIT_LD();

    int gm = m0 + row;
    float* cp = Cm + (size_t)z * cStride + (size_t)gm * Nt + n0 + colbase;
    const float* rp = (EPI == 2) ? (resid + (size_t)gm * Nt + n0 + colbase) : nullptr;
    const float* bp = (EPI >= 1) ? (bias + (size_t)z * biasStride + n0 + colbase) : nullptr;
    #pragma unroll
    for (int j = 0; j < 64; j += 4) {
        float vv[4];
        #pragma unroll
        for (int q = 0; q < 4; q++) {
            float t = __uint_as_float(d_regs[j + q]);
            if (EPI == 1)      t += bp[j + q];
            else if (EPI == 2) t += bp[j + q] + rp[j + q];
            else if (EPI == 3) { t += bp[j + q]; t = t > 0.f ? t * t : 0.f; }
            vv[q] = t;
        }
        float4 v4; v4.x = vv[0]; v4.y = vv[1]; v4.z = vv[2]; v4.w = vv[3];
        *(float4*)(cp + j) = v4;
    }

    TC_FENCE_BEFORE();
    __syncthreads();
    if (wid == 0) { TC_RELINQ(); TC_DEALLOC(tmem, 128u); }

#else  // ---------------- SIMT fp32 fallback (compute_103 PTX pass) ----------------
    float* As = (float*)(smem + OFF_TILE);                 // [16][128]
    float* Bs = (float*)(smem + OFF_TILE + 16 * 128 * 4);  // [16][128]
    __syncthreads();
    int tm = (tid >> 4) * 8, tn = (tid & 15) * 8;
    float acc[8][8];
    #pragma unroll
    for (int i = 0; i < 8; i++)
        #pragma unroll
        for (int j = 0; j < 8; j++) acc[i][j] = 0.f;

    for (int k0 = 0; k0 < Kd; k0 += 16) {
        #pragma unroll
        for (int i = 0; i < 2; i++) {
            int f = tid + i * 256;
            int row = f >> 2, c4 = (f & 3) * 4;
            float4 va = *(const float4*)(Az + (size_t)s_rid[row] * Kd + k0 + c4);
            float4 vb = *(const float4*)(Bz + (size_t)(n0 + row) * Kd + k0 + c4);
            As[(c4+0)*128 + row] = va.x; As[(c4+1)*128 + row] = va.y;
            As[(c4+2)*128 + row] = va.z; As[(c4+3)*128 + row] = va.w;
            Bs[(c4+0)*128 + row] = vb.x; Bs[(c4+1)*128 + row] = vb.y;
            Bs[(c4+2)*128 + row] = vb.z; Bs[(c4+3)*128 + row] = vb.w;
        }
        __syncthreads();
        #pragma unroll
        for (int kk = 0; kk < 16; kk++) {
            float4 a0 = *(const float4*)&As[kk*128 + tm];
            float4 a1 = *(const float4*)&As[kk*128 + tm + 4];
            float4 b0 = *(const float4*)&Bs[kk*128 + tn];
            float4 b1 = *(const float4*)&Bs[kk*128 + tn + 4];
            float a_[8] = {a0.x,a0.y,a0.z,a0.w,a1.x,a1.y,a1.z,a1.w};
            float b_[8] = {b0.x,b0.y,b0.z,b0.w,b1.x,b1.y,b1.z,b1.w};
            #pragma unroll
            for (int i = 0; i < 8; i++)
                #pragma unroll
                for (int j = 0; j < 8; j++)
                    acc[i][j] += a_[i] * b_[j];
        }
        __syncthreads();
    }

    #pragma unroll
    for (int i = 0; i < 8; i++) {
        int gm = m0 + tm + i;
        float* cp = Cm + (size_t)z * cStride + (size_t)gm * Nt + n0 + tn;
        const float* rp = (EPI == 2) ? (resid + (size_t)gm * Nt + n0 + tn) : nullptr;
        #pragma unroll
        for (int j = 0; j < 8; j += 4) {
            float vv[4];
            #pragma unroll
            for (int q = 0; q < 4; q++) {
                float t = acc[i][j + q];
                if (EPI == 1)      t += bias[(size_t)z * biasStride + n0 + tn + j + q];
                else if (EPI == 2) t += bias[(size_t)z * biasStride + n0 + tn + j + q] + rp[j + q];
                else if (EPI == 3) { t += bias[(size_t)z * biasStride + n0 + tn + j + q]; t = t > 0.f ? t * t : 0.f; }
                vv[q] = t;
            }
            float4 v4; v4.x = vv[0]; v4.y = vv[1]; v4.z = vv[2]; v4.w = vv[3];
            *(float4*)(cp + j) = v4;
        }
    }
#endif
}

// ---------------- block reduce ----------------
__device__ __forceinline__ float blockReduceSum(float v) {
    __shared__ float sh[32];
    int lane = threadIdx.x & 31, w = threadIdx.x >> 5;
    #pragma unroll
    for (int o = 16; o; o >>= 1) v += __shfl_down_sync(0xffffffffu, v, o);
    if (lane == 0) sh[w] = v;
    __syncthreads();
    int nw = blockDim.x >> 5;
    if (w == 0) {
        v = (lane < nw) ? sh[lane] : 0.f;
        #pragma unroll
        for (int o = 16; o; o >>= 1) v += __shfl_down_sync(0xffffffffu, v, o);
        if (lane == 0) sh[0] = v;
    }
    __syncthreads();
    return sh[0];
}

// ---------------- 1) residual mix + rmsnorm ----------------
__global__ void mix_rms_kernel(const float* __restrict__ x, const float* __restrict__ x0,
                               const float* __restrict__ lambdas) {
    int row = blockIdx.x;
    float l0 = lambdas[0], l1 = lambdas[1];
    size_t off = (size_t)row * CC + threadIdx.x * 4;
    float4 a = *(const float4*)(x + off);
    float4 b = *(const float4*)(x0 + off);
    float4 v;
    v.x = l0*a.x + l1*b.x; v.y = l0*a.y + l1*b.y;
    v.z = l0*a.z + l1*b.z; v.w = l0*a.w + l1*b.w;
    *(float4*)(g_xmix + off) = v;
    float ss = v.x*v.x + v.y*v.y + v.z*v.z + v.w*v.w;
    float tot = blockReduceSum(ss);
    float sc = rsqrtf(tot * (1.0f/CC) + 1e-6f);
    float4 o; o.x = v.x*sc; o.y = v.y*sc; o.z = v.z*sc; o.w = v.w*sc;
    *(float4*)(g_a + off) = o;
}

// ---------------- 6) rmsnorm of x2 ----------------
__global__ void rms2_kernel(const float* __restrict__ src) {
    int row = blockIdx.x;
    size_t off = (size_t)row * CC + threadIdx.x * 4;
    float4 v = *(const float4*)(src + off);
    float ss = v.x*v.x + v.y*v.y + v.z*v.z + v.w*v.w;
    float tot = blockReduceSum(ss);
    float sc = rsqrtf(tot * (1.0f/CC) + 1e-6f);
    float4 o; o.x = v.x*sc; o.y = v.y*sc; o.z = v.z*sc; o.w = v.w*sc;
    *(float4*)(g_h + off) = o;
}

// ---------------- 3) per-head rmsnorm + rotary ----------------
__global__ void qk_rot_kernel() {
    int gw = blockIdx.x * (blockDim.x >> 5) + (threadIdx.x >> 5);
    int lane = threadIdx.x & 31;
    int qk = gw >> 16;
    int r  = gw & 65535;
    int n  = r >> 4;
    int h  = r & 15;
    float* p = g_qkv + (size_t)qk * NTOK * CC + (size_t)n * CC + h * HD;
    float x1 = p[lane], x2 = p[lane + 32];
    float ss = x1 * x1 + x2 * x2;
    #pragma unroll
    for (int o = 16; o; o >>= 1) ss += __shfl_xor_sync(0xffffffffu, ss, o);
    float sc = rsqrtf(ss * (1.0f/HD) + 1e-6f);
    x1 *= sc; x2 *= sc;
    int t = n & (TT - 1);
    float invj = (lane < 16) ? c_rotinv[lane] : 0.f;
    float th = (float)t * invj;
    float c = cosf(th), s = sinf(th);
    p[lane]      =  x1 * c + x2 * s;
    p[lane + 32] = -x1 * s + x2 * c;
}

// ---------------- 4) causal flash attention ----------------
__global__ __launch_bounds__(128)
void attn_kernel() {
    __shared__ float Ks[32 * 64];
    __shared__ float Vs[32 * 64];
    int bh = blockIdx.y;
    int b = bh >> 4, h = bh & 15;
    int tq = blockIdx.x * 128 + threadIdx.x;
    const float* qb_ = g_qkv + (size_t)(b * TT) * CC + h * HD;
    const float* kb_ = g_qkv + (size_t)NTOK * CC + (size_t)(b * TT) * CC + h * HD;
    const float* vb_ = g_qkv + (size_t)2 * NTOK * CC + (size_t)(b * TT) * CC + h * HD;
    float q[HD];
    #pragma unroll
    for (int d = 0; d < HD; d += 4) {
        float4 t = *(const float4*)(qb_ + (size_t)tq * CC + d);
        q[d] = t.x * 0.125f; q[d+1] = t.y * 0.125f; q[d+2] = t.z * 0.125f; q[d+3] = t.w * 0.125f;
    }
    float m = -1e30f, l = 0.f;
    float o[HD];
    #pragma unroll
    for (int d = 0; d < HD; d++) o[d] = 0.f;
    int ntiles = (blockIdx.x * 128 + 128) >> 5;
    for (int kt = 0; kt < ntiles; kt++) {
        int kb = kt * 32;
        __syncthreads();
        #pragma unroll
        for (int i = 0; i < 4; i++) {
            int f = threadIdx.x + i * 128;
            int r = f >> 4, c = (f & 15) * 4;
            *(float4*)(Ks + r * 64 + c) = *(const float4*)(kb_ + (size_t)(kb + r) * CC + c);
            *(float4*)(Vs + r * 64 + c) = *(const float4*)(vb_ + (size_t)(kb + r) * CC + c);
        }
        __syncthreads();
        float s[32];
        float mt = m;
        #pragma unroll
        for (int j = 0; j < 32; j++) {
            float acc = 0.f;
            const float* kr = Ks + j * 64;
            #pragma unroll
            for (int d = 0; d < HD; d += 4) {
                float4 kv = *(const float4*)(kr + d);
                acc += q[d]*kv.x + q[d+1]*kv.y + q[d+2]*kv.z + q[d+3]*kv.w;
            }
            s[j] = (kb + j <= tq) ? acc : -1e30f;
            mt = fmaxf(mt, s[j]);
        }
        float alpha = expf(m - mt);
        float psum = 0.f;
        #pragma unroll
        for (int j = 0; j < 32; j++) { s[j] = expf(s[j] - mt); psum += s[j]; }
        l = l * alpha + psum;
        #pragma unroll
        for (int d = 0; d < HD; d++) o[d] *= alpha;
        #pragma unroll
        for (int j = 0; j < 32; j++) {
            float p = s[j];
            const float* vr = Vs + j * 64;
            #pragma unroll
            for (int d = 0; d < HD; d += 4) {
                float4 vv = *(const float4*)(vr + d);
                o[d] += p*vv.x; o[d+1] += p*vv.y; o[d+2] += p*vv.z; o[d+3] += p*vv.w;
            }
        }
        m = mt;
    }
    float inv = 1.f / l;
    float* op = g_o + (size_t)(b * TT + tq) * CC + h * HD;
    #pragma unroll
    for (int d = 0; d < HD; d += 4) {
        float4 t; t.x = o[d]*inv; t.y = o[d+1]*inv; t.z = o[d+2]*inv; t.w = o[d+3]*inv;
        *(float4*)(op + d) = t;
    }
}

// ---------------- 7) router ----------------
__global__ void router_kernel(const float* __restrict__ rw, const float* __restrict__ rb,
                              const float* __restrict__ nw, const float* __restrict__ nb,
                              const float* __restrict__ noise) {
    int n = blockIdx.x;
    int w = threadIdx.x >> 5, lane = threadIdx.x & 31;
    const float* hr = g_h + (size_t)n * CC;
    const float* wr = rw + (size_t)w * CC;
    const float* wn = nw + (size_t)w * CC;
    float s1 = 0.f, s2 = 0.f;
    for (int c = lane * 4; c < CC; c += 128) {
        float4 hv = *(const float4*)(hr + c);
        float4 r4 = *(const float4*)(wr + c);
        float4 n4 = *(const float4*)(wn + c);
        s1 += hv.x*r4.x + hv.y*r4.y + hv.z*r4.z + hv.w*r4.w;
        s2 += hv.x*n4.x + hv.y*n4.y + hv.z*n4.z + hv.w*n4.w;
    }
    #pragma unroll
    for (int o = 16; o; o >>= 1) {
        s1 += __shfl_xor_sync(0xffffffffu, s1, o);
        s2 += __shfl_xor_sync(0xffffffffu, s2, o);
    }
    __shared__ float lg[8], nl[8];
    if (lane == 0) { lg[w] = s1 + rb[w]; nl[w] = s2 + nb[w]; }
    __syncthreads();
    if (threadIdx.x == 0) {
        float nv[8];
        #pragma unroll
        for (int e = 0; e < 8; e++) {
            float xn = nl[e];
            float sp = (xn > 20.f) ? xn : log1pf(expf(xn));
            nv[e] = lg[e] + noise[(size_t)n * EE + e] * sp;
        }
        int i0 = 0; float v0 = nv[0];
        #pragma unroll
        for (int e = 1; e < 8; e++) if (nv[e] > v0) { v0 = nv[e]; i0 = e; }
        float v1 = -1e30f;
        #pragma unroll
        for (int e = 0; e < 8; e++) if (e != i0 && nv[e] > v1) { v1 = nv[e]; }
        float e1 = expf(v1 - v0);
        g_g0[n] = 1.f / (1.f + e1);
        g_eid[n] = i0;
    }
}

// ---------------- 8) per-expert capacity lists ----------------
__global__ void build_idx_kernel() {
    int w = threadIdx.x >> 5, lane = threadIdx.x & 31;
    int count = 0;
    for (int base = 0; base < NTOK; base += 32) {
        int t = base + lane;
        bool p = (g_eid[t] == w);
        unsigned msk = __ballot_sync(0xffffffffu, p);
        int pos = count + __popc(msk & ((1u << lane) - 1u));
        if (p && pos < CAPX) g_idx[w * CAPX + pos] = t;
        count += __popc(msk);
    }
    int c = min(count, CAPX);
    if (lane == 0) g_cnt[w] = c;
    for (int s = c + lane; s < CAPX; s += 32) g_idx[w * CAPX + s] = NTOK;
}

// ---------------- 11) scatter ----------------
__global__ void scatter_kernel(float* __restrict__ out) {
    int e = blockIdx.x >> 10;
    int slot = blockIdx.x & (CAPX - 1);
    if (slot >= g_cnt[e]) return;
    int t = g_idx[e * CAPX + slot];
    float g = g_g0[t];
    const float* src = g_oe + ((size_t)e * CAPX + slot) * CC;
    float* dst = out + (size_t)t * CC;
    int c = threadIdx.x * 4;
    float4 s = *(const float4*)(src + c);
    float4 d = *(const float4*)(dst + c);
    d.x += g * s.x; d.y += g * s.y; d.z += g * s.z; d.w += g * s.w;
    *(float4*)(dst + c) = d;
}

// ---------------- host launcher ----------------
extern "C" void kernel_launch(void* const* d_in, const int* in_sizes, int n_in,
                              void* d_out, int out_size) {
    const float* x        = (const float*)d_in[0];
    const float* x0       = (const float*)d_in[1];
    const float* noise    = (const float*)d_in[2];
    const float* lambdas  = (const float*)d_in[3];
    const float* qkv_w    = (const float*)d_in[5];
    const float* c_proj_w = (const float*)d_in[6];
    const float* c_proj_b = (const float*)d_in[7];
    const float* router_w = (const float*)d_in[8];
    const float* router_b = (const float*)d_in[9];
    const float* noise_w  = (const float*)d_in[10];
    const float* noise_b  = (const float*)d_in[11];
    const float* ew1      = (const float*)d_in[12];
    const float* eb1      = (const float*)d_in[13];
    const float* ew2      = (const float*)d_in[14];
    const float* eb2      = (const float*)d_in[15];
    float* out = (float*)d_out;

    void *p_a, *p_qkv, *p_o, *p_xmix, *p_h, *p_h1, *p_oe, *p_idx, *p_cnt;
    cudaGetSymbolAddress(&p_a,    g_a);
    cudaGetSymbolAddress(&p_qkv,  g_qkv);
    cudaGetSymbolAddress(&p_o,    g_o);
    cudaGetSymbolAddress(&p_xmix, g_xmix);
    cudaGetSymbolAddress(&p_h,    g_h);
    cudaGetSymbolAddress(&p_h1,   g_h1);
    cudaGetSymbolAddress(&p_oe,   g_oe);
    cudaGetSymbolAddress(&p_idx,  g_idx);
    cudaGetSymbolAddress(&p_cnt,  g_cnt);

    cudaFuncSetAttribute(gemm_tc<0,false,false>, cudaFuncAttributeMaxDynamicSharedMemorySize, SMEM_TOTAL_TC);
    cudaFuncSetAttribute(gemm_tc<2,false,false>, cudaFuncAttributeMaxDynamicSharedMemorySize, SMEM_TOTAL_TC);
    cudaFuncSetAttribute(gemm_tc<3,true, true >, cudaFuncAttributeMaxDynamicSharedMemorySize, SMEM_TOTAL_TC);
    cudaFuncSetAttribute(gemm_tc<1,false,true >, cudaFuncAttributeMaxDynamicSharedMemorySize, SMEM_TOTAL_TC);

    // 1) residual mix + rmsnorm
    mix_rms_kernel<<<NTOK, 256>>>(x, x0, lambdas);

    // 2) qkv = a @ qkv_w[k]^T
    gemm_tc<0,false,false><<<dim3(CC/128, NTOK/128, 3), 256, SMEM_TOTAL_TC>>>(
        (const float*)p_a, 0L, qkv_w, (long)CC*CC,
        (float*)p_qkv, (long)NTOK*CC,
        nullptr, 0, nullptr, nullptr, nullptr, CC, CC);

    // 3) per-head rmsnorm + rotary
    qk_rot_kernel<<<(2 * NTOK * HH) / 8, 256>>>();

    // 4) attention
    attn_kernel<<<dim3(TT/128, 2*HH), 128>>>();

    // 5) x2 = xmix + o @ c_proj_w^T + b
    gemm_tc<2,false,false><<<dim3(CC/128, NTOK/128, 1), 256, SMEM_TOTAL_TC>>>(
        (const float*)p_o, 0L, c_proj_w, 0L,
        out, 0L,
        c_proj_b, 0, (const float*)p_xmix, nullptr, nullptr, CC, CC);

    // 6) h = rmsnorm(x2)
    rms2_kernel<<<NTOK, 256>>>(out);

    // 7) router
    router_kernel<<<NTOK, 256>>>(router_w, router_b, noise_w, noise_b, noise);

    // 8) per-expert index lists
    build_idx_kernel<<<1, 256>>>();

    // 9) h1 = sq(relu(gather(h) @ ew1^T + eb1))
    gemm_tc<3,true,true><<<dim3(HID/128, CAPX/128, EE), 256, SMEM_TOTAL_TC>>>(
        (const float*)p_h, 0L, ew1, (long)HID*CC,
        (float*)p_h1, (long)CAPX*HID,
        eb1, HID, nullptr, (const int*)p_idx, (const int*)p_cnt, HID, CC);

    // 10) oe = h1 @ ew2^T + eb2
    gemm_tc<1,false,true><<<dim3(CC/128, CAPX/128, EE), 256, SMEM_TOTAL_TC>>>(
        (const float*)p_h1, (long)CAPX*HID, ew2, (long)CC*HID,
        (float*)p_oe, (long)CAPX*CC,
        eb2, CC, nullptr, nullptr, (const int*)p_cnt, CC, HID);

    // 11) scatter
    scatter_kernel<<<EE * CAPX, 256>>>(out);
}

// round 4
// speedup vs baseline: 6.4488x; 2.3163x over previous
#include <cuda_runtime.h>
#include <cuda_bf16.h>
#include <math.h>
#include <stdint.h>

#define NTOK 4096
#define TT   2048
#define CC   1024
#define HH   16
#define HD   64
#define EE   8
#define CAPX 1024
#define HID  4096

// tcgen05 is arch-SPECIFIC: only emit in the sm_103a pass.
#if defined(__CUDA_ARCH__)
# if (__CUDA_ARCH__ >= 1000) && (defined(__CUDA_ARCH_FEAT_SM103_ALL) || defined(__CUDA_ARCH_FEAT_SM100_ALL) || defined(__CUDA_ARCH_SPECIFIC__) || defined(__CUDA_ARCH_FAMILY_SPECIFIC__))
#  define USE_TC 1
# else
#  define USE_TC 0
# endif
#else
# define USE_TC 0
#endif

typedef __nv_bfloat16 bf16;
typedef __nv_bfloat162 bf162;

// ---------------- scratch ----------------
__device__ float g_xmix[(size_t)NTOK*CC];
__device__ float g_qkv [(size_t)3*NTOK*CC];
__device__ float g_h   [(size_t)NTOK*CC];
__device__ float g_oe  [(size_t)EE*CAPX*CC];
__device__ float g_g0  [NTOK];
__device__ int   g_eid [NTOK];
__device__ int   g_idx [EE*CAPX];
__device__ int   g_cnt [EE];
// bf16 hi/lo planes: [0]=hi, [1]=lo
__device__ bf16 g_abf [2][(size_t)NTOK*CC];
__device__ bf16 g_obf [2][(size_t)NTOK*CC];
__device__ bf16 g_hbf [2][(size_t)NTOK*CC];
__device__ bf16 g_qbf [2][(size_t)NTOK*CC];      // [bh][t][d]
__device__ bf16 g_kbf [2][(size_t)NTOK*CC];      // [bh][t][d]
__device__ bf16 g_vT  [2][(size_t)NTOK*CC];      // [bh][d][t]
__device__ bf16 g_h1bf[2][(size_t)EE*CAPX*HID];
__device__ bf16 g_wqkv[2][(size_t)3*CC*CC];
__device__ bf16 g_wcp [2][(size_t)CC*CC];
__device__ bf16 g_we1 [2][(size_t)EE*HID*CC];
__device__ bf16 g_we2 [2][(size_t)EE*CC*HID];

__constant__ float c_rotinv[16] = {
    1.0f, 0.6299605249474366f, 0.39685026299204984f, 0.25f,
    0.15749013123685915f, 0.09921256574801246f, 0.0625f, 0.03937253280921479f,
    0.024803141437003115f, 0.015625f, 0.009843133202303697f, 0.0062007853592507785f,
    0.00390625f, 0.0024607833005759242f, 0.0015501963398126947f, 0.0009765625f
};

// ---------------- common helpers ----------------
__device__ __forceinline__ uint32_t smem_u32(const void* p) {
    uint32_t a;
    asm("{ .reg .u64 t; cvta.to.shared.u64 t, %1; cvt.u32.u64 %0, t; }" : "=r"(a) : "l"(p));
    return a;
}
__device__ __forceinline__ uint32_t sw128(uint32_t off) { return off ^ ((off >> 3) & 0x70); }

__device__ __forceinline__ void split4(float4 v, uint2& hv, uint2& lv) {
    bf16 h0 = __float2bfloat16_rn(v.x), h1 = __float2bfloat16_rn(v.y);
    bf16 h2 = __float2bfloat16_rn(v.z), h3 = __float2bfloat16_rn(v.w);
    bf162 hp0; hp0.x = h0; hp0.y = h1;
    bf162 hp1; hp1.x = h2; hp1.y = h3;
    bf162 lp0 = __floats2bfloat162_rn(v.x - __bfloat162float(h0), v.y - __bfloat162float(h1));
    bf162 lp1 = __floats2bfloat162_rn(v.z - __bfloat162float(h2), v.w - __bfloat162float(h3));
    hv.x = *(uint32_t*)&hp0; hv.y = *(uint32_t*)&hp1;
    lv.x = *(uint32_t*)&lp0; lv.y = *(uint32_t*)&lp1;
}

#if USE_TC
__device__ __forceinline__ uint32_t elect_one() {
    uint32_t p;
    asm volatile("{\n\t.reg .pred p;\n\telect.sync _|p, 0xFFFFFFFF;\n\tselp.b32 %0, 1, 0, p;\n\t}" : "=r"(p));
    return p;
}
#define MBAR_INIT(addr, cnt) \
    asm volatile("mbarrier.init.shared.b64 [%0], %1;" :: "r"(addr), "r"(cnt) : "memory")
__device__ __forceinline__ void mbar_wait(uint32_t addr, int phase) {
    uint32_t done = 0;
    while (!done) {
        asm volatile("{\n\t.reg .pred p;\n\t"
            "mbarrier.try_wait.parity.acquire.cta.shared::cta.b64 p, [%1], %2, 0x989680;\n\t"
            "selp.b32 %0, 1, 0, p;\n\t}" : "=r"(done) : "r"(addr), "r"(phase) : "memory");
    }
}
#define TC_ALLOC(addr, n) \
    asm volatile("tcgen05.alloc.cta_group::1.sync.aligned.shared::cta.b32 [%0], %1;" :: "r"(addr), "r"(n) : "memory")
#define TC_DEALLOC(tm, n) \
    asm volatile("tcgen05.dealloc.cta_group::1.sync.aligned.b32 %0, %1;" :: "r"(tm), "r"(n))
#define TC_RELINQ() \
    asm volatile("tcgen05.relinquish_alloc_permit.cta_group::1.sync.aligned;")
#define TC_COMMIT(mbar) \
    asm volatile("tcgen05.commit.cta_group::1.mbarrier::arrive::one.shared::cluster.b64 [%0];" :: "r"(mbar) : "memory")
#define TC_FENCE_AFTER()  asm volatile("tcgen05.fence::after_thread_sync;" ::: "memory")
#define TC_FENCE_BEFORE() asm volatile("tcgen05.fence::before_thread_sync;" ::: "memory")
#define TC_WAIT_LD()      asm volatile("tcgen05.wait::ld.sync.aligned;" ::: "memory")
#define TC_WAIT_ST()      asm volatile("tcgen05.wait::st.sync.aligned;" ::: "memory")

#define TC_LD_X32(r, a) \
    asm volatile("tcgen05.ld.sync.aligned.32x32b.x32.b32 " \
        "{%0,%1,%2,%3,%4,%5,%6,%7,%8,%9,%10,%11,%12,%13,%14,%15," \
        "%16,%17,%18,%19,%20,%21,%22,%23,%24,%25,%26,%27,%28,%29,%30,%31}, [%32];" \
        : "=r"((r)[0]),"=r"((r)[1]),"=r"((r)[2]),"=r"((r)[3]),"=r"((r)[4]),"=r"((r)[5]),"=r"((r)[6]),"=r"((r)[7]), \
          "=r"((r)[8]),"=r"((r)[9]),"=r"((r)[10]),"=r"((r)[11]),"=r"((r)[12]),"=r"((r)[13]),"=r"((r)[14]),"=r"((r)[15]), \
          "=r"((r)[16]),"=r"((r)[17]),"=r"((r)[18]),"=r"((r)[19]),"=r"((r)[20]),"=r"((r)[21]),"=r"((r)[22]),"=r"((r)[23]), \
          "=r"((r)[24]),"=r"((r)[25]),"=r"((r)[26]),"=r"((r)[27]),"=r"((r)[28]),"=r"((r)[29]),"=r"((r)[30]),"=r"((r)[31]) \
        : "r"(a))

#define TC_ST_X32(a, r) \
    asm volatile("tcgen05.st.sync.aligned.32x32b.x32.b32 [%0], " \
        "{%1,%2,%3,%4,%5,%6,%7,%8,%9,%10,%11,%12,%13,%14,%15,%16," \
        "%17,%18,%19,%20,%21,%22,%23,%24,%25,%26,%27,%28,%29,%30,%31,%32};" \
        :: "r"(a), \
           "r"((r)[0]),"r"((r)[1]),"r"((r)[2]),"r"((r)[3]),"r"((r)[4]),"r"((r)[5]),"r"((r)[6]),"r"((r)[7]), \
           "r"((r)[8]),"r"((r)[9]),"r"((r)[10]),"r"((r)[11]),"r"((r)[12]),"r"((r)[13]),"r"((r)[14]),"r"((r)[15]), \
           "r"((r)[16]),"r"((r)[17]),"r"((r)[18]),"r"((r)[19]),"r"((r)[20]),"r"((r)[21]),"r"((r)[22]),"r"((r)[23]), \
           "r"((r)[24]),"r"((r)[25]),"r"((r)[26]),"r"((r)[27]),"r"((r)[28]),"r"((r)[29]),"r"((r)[30]),"r"((r)[31]) \
        : "memory")

__device__ __forceinline__ void mma_ss_bf16(uint32_t d, uint64_t ad, uint64_t bd,
                                            uint32_t idesc, uint32_t en) {
    asm volatile("{\n\t.reg .pred p;\n\tsetp.ne.u32 p, %4, 0;\n\t"
        "tcgen05.mma.cta_group::1.kind::f16 [%0], %1, %2, %3, {%5,%5,%5,%5}, p;\n\t}"
        :: "r"(d), "l"(ad), "l"(bd), "r"(idesc), "r"(en), "r"(0u) : "memory");
}
__device__ __forceinline__ void mma_ts_bf16(uint32_t d, uint32_t a, uint64_t bd,
                                            uint32_t idesc, uint32_t en) {
    asm volatile("{\n\t.reg .pred p;\n\tsetp.ne.u32 p, %4, 0;\n\t"
        "tcgen05.mma.cta_group::1.kind::f16 [%0], [%1], %2, %3, {%5,%5,%5,%5}, p;\n\t}"
        :: "r"(d), "r"(a), "l"(bd), "r"(idesc), "r"(en), "r"(0u) : "memory");
}
__device__ __forceinline__ uint64_t make_desc(uint32_t base) {
    const uint64_t B = (uint64_t(2) << 61) | (uint64_t(1) << 46) | (uint64_t(64) << 32) | (uint64_t(1) << 16);
    return B | ((uint64_t)(base >> 4) & 0x3FFF);
}
#endif // USE_TC

// ---------------- weight/activation fp32 -> hi/lo bf16 ----------------
__global__ void conv_kernel(const float* __restrict__ src, bf16* __restrict__ hi,
                            bf16* __restrict__ lo, long n4) {
    long i = (long)blockIdx.x * blockDim.x + threadIdx.x;
    if (i >= n4) return;
    float4 v = ((const float4*)src)[i];
    uint2 hv, lv; split4(v, hv, lv);
    ((uint2*)hi)[i] = hv; ((uint2*)lo)[i] = lv;
}

// ======= bf16 GEMM: C[M,Nt] = A[M,K]*B[Nt,K]^T, 3-term hi/lo split, 128x128 tile =======
// EPI: 0=none 1=+bias 2=+bias+resid 3=sq(relu(+bias)) written as bf16 hi/lo
#define TILE_BYTES 16384
#define BUF_BYTES  65536
#define SMEM_TOTAL_TC (1024 + 2*BUF_BYTES)

template<int EPI, bool GATHER, bool SKIP>
__global__ __launch_bounds__(256)
void gemm_bf(const bf16* __restrict__ Ahi, const bf16* __restrict__ Alo, long aStride,
             const bf16* __restrict__ Bhi, const bf16* __restrict__ Blo, long bStride,
             float* __restrict__ Cf, bf16* __restrict__ Chi, bf16* __restrict__ Clo, long cStride,
             const float* __restrict__ bias, int biasStride,
             const float* __restrict__ resid,
             const int* __restrict__ rowIdx,
             const int* __restrict__ counts,
             int Nt, int Kd) {
    extern __shared__ char smem[];
    const int z = blockIdx.z;
    const int m0 = blockIdx.y * 128, n0 = blockIdx.x * 128;
    if (SKIP) { if (m0 >= counts[z]) return; }
    int tid = threadIdx.x, wid = tid >> 5, lane = tid & 31;

    const uint32_t OFF_TM = 0, OFF_MB = 8, OFF_RID = 64, OFF_TILE = 1024;
    int* s_rid = (int*)(smem + OFF_RID);
    if (tid < 128) {
        int r;
        if (GATHER) r = min(rowIdx[z * CAPX + m0 + tid], NTOK - 1);
        else        r = m0 + tid;
        s_rid[tid] = r;
    }
    const bf16* Ahz = Ahi + (size_t)z * aStride;
    const bf16* Alz = Alo + (size_t)z * aStride;
    const bf16* Bhz = Bhi + (size_t)z * bStride;
    const bf16* Blz = Blo + (size_t)z * bStride;

#if USE_TC
    uint32_t sbase = smem_u32(smem);
    if (tid == 0) { MBAR_INIT(sbase + OFF_MB, 1); MBAR_INIT(sbase + OFF_MB + 8, 1); }
    if (wid == 0) { TC_ALLOC(sbase + OFF_TM, 128u); }
    __syncthreads();
    uint32_t tmem = *(uint32_t*)(smem + OFF_TM);

    const uint32_t idesc = (1u << 4) | (1u << 7) | (1u << 10) | (16u << 17) | (8u << 24);

    int nchunks = Kd >> 6;
    int ph0 = 0, ph1 = 0;

    for (int c = 0; c < nchunks; c++) {
        int buf = c & 1;
        char* tb = smem + OFF_TILE + buf * BUF_BYTES;
        if (c >= 2) {
            if (buf == 0) { mbar_wait(sbase + OFF_MB, ph0); ph0 ^= 1; }
            else          { mbar_wait(sbase + OFF_MB + 8, ph1); ph1 ^= 1; }
        }
        int k0 = c * 64;
        // each tile: 128 rows x 64 bf16 = 1024 uint4; 4 per thread
        #pragma unroll
        for (int i = 0; i < 4; i++) {
            int f = tid + i * 256;
            int row = f >> 3, c8 = f & 7;
            uint32_t so = sw128((uint32_t)(row * 128 + c8 * 16));
            size_t aoff = (size_t)s_rid[row] * Kd + k0 + c8 * 8;
            size_t boff = (size_t)(n0 + row) * Kd + k0 + c8 * 8;
            *(uint4*)(tb + so)                  = *(const uint4*)(Ahz + aoff);
            *(uint4*)(tb + TILE_BYTES + so)     = *(const uint4*)(Alz + aoff);
            *(uint4*)(tb + 2 * TILE_BYTES + so) = *(const uint4*)(Bhz + boff);
            *(uint4*)(tb + 3 * TILE_BYTES + so) = *(const uint4*)(Blz + boff);
        }
        asm volatile("fence.proxy.async.shared::cta;" ::: "memory");
        __syncthreads();
        if (wid == 0) {
            if (elect_one()) {
                uint32_t base = sbase + OFF_TILE + buf * BUF_BYTES;
                uint64_t ah = make_desc(base);
                uint64_t al = make_desc(base + TILE_BYTES);
                uint64_t bh = make_desc(base + 2 * TILE_BYTES);
                uint64_t bl = make_desc(base + 3 * TILE_BYTES);
                #pragma unroll
                for (int ks = 0; ks < 4; ks++) {
                    uint64_t o = ks * 2;
                    mma_ss_bf16(tmem, ah + o, bh + o, idesc, (c > 0 || ks > 0) ? 1u : 0u);
                    mma_ss_bf16(tmem, ah + o, bl + o, idesc, 1u);
                    mma_ss_bf16(tmem, al + o, bh + o, idesc, 1u);
                }
                TC_COMMIT(sbase + OFF_MB + 8 * buf);
            }
        }
    }
    mbar_wait(sbase + OFF_MB, ph0);
    mbar_wait(sbase + OFF_MB + 8, ph1);
    TC_FENCE_AFTER();

    int colbase = (wid >> 2) * 64;
    int row = (wid & 3) * 32 + lane;
    uint32_t d_regs[64];
    TC_LD_X32(d_regs, tmem + colbase);
    TC_LD_X32(d_regs + 32, tmem + colbase + 32);
    TC_WAIT_LD();

    int gm = m0 + row;
    const float* rp = (EPI == 2) ? (resid + (size_t)gm * Nt + n0 + colbase) : nullptr;
    const float* bp = (EPI >= 1) ? (bias + (size_t)z * biasStride + n0 + colbase) : nullptr;
    if (EPI == 3) {
        bf16* chp = Chi + (size_t)z * cStride + (size_t)gm * Nt + n0 + colbase;
        bf16* clp = Clo + (size_t)z * cStride + (size_t)gm * Nt + n0 + colbase;
        #pragma unroll
        for (int j = 0; j < 64; j += 4) {
            float4 v;
            float t0 = __uint_as_float(d_regs[j+0]) + bp[j+0];
            float t1 = __uint_as_float(d_regs[j+1]) + bp[j+1];
            float t2 = __uint_as_float(d_regs[j+2]) + bp[j+2];
            float t3 = __uint_as_float(d_regs[j+3]) + bp[j+3];
            v.x = t0 > 0.f ? t0*t0 : 0.f; v.y = t1 > 0.f ? t1*t1 : 0.f;
            v.z = t2 > 0.f ? t2*t2 : 0.f; v.w = t3 > 0.f ? t3*t3 : 0.f;
            uint2 hv, lv; split4(v, hv, lv);
            *(uint2*)(chp + j) = hv; *(uint2*)(clp + j) = lv;
        }
    } else {
        float* cp = Cf + (size_t)z * cStride + (size_t)gm * Nt + n0 + colbase;
        #pragma unroll
        for (int j = 0; j < 64; j += 4) {
            float vv[4];
            #pragma unroll
            for (int q = 0; q < 4; q++) {
                float t = __uint_as_float(d_regs[j + q]);
                if (EPI == 1)      t += bp[j + q];
                else if (EPI == 2) t += bp[j + q] + rp[j + q];
                vv[q] = t;
            }
            float4 v4; v4.x = vv[0]; v4.y = vv[1]; v4.z = vv[2]; v4.w = vv[3];
            *(float4*)(cp + j) = v4;
        }
    }

    TC_FENCE_BEFORE();
    __syncthreads();
    if (wid == 0) { TC_RELINQ(); TC_DEALLOC(tmem, 128u); }

#else  // ---------------- SIMT fallback (compute_103 pass; never selected at runtime) ----------------
    float* As = (float*)(smem + OFF_TILE);
    float* Bs = (float*)(smem + OFF_TILE + 16 * 128 * 4);
    __syncthreads();
    int tm = (tid >> 4) * 8, tn = (tid & 15) * 8;
    float acc[8][8];
    #pragma unroll
    for (int i = 0; i < 8; i++)
        #pragma unroll
        for (int j = 0; j < 8; j++) acc[i][j] = 0.f;

    for (int k0 = 0; k0 < Kd; k0 += 16) {
        #pragma unroll
        for (int i = 0; i < 2; i++) {
            int f = tid + i * 256;
            int row = f >> 2, c4 = (f & 3) * 4;
            #pragma unroll
            for (int q = 0; q < 4; q++) {
                size_t ao = (size_t)s_rid[row] * Kd + k0 + c4 + q;
                size_t bo = (size_t)(n0 + row) * Kd + k0 + c4 + q;
                As[(c4+q)*128 + row] = __bfloat162float(Ahz[ao]) + __bfloat162float(Alz[ao]);
                Bs[(c4+q)*128 + row] = __bfloat162float(Bhz[bo]) + __bfloat162float(Blz[bo]);
            }
        }
        __syncthreads();
        #pragma unroll
        for (int kk = 0; kk < 16; kk++) {
            float a_[8], b_[8];
            #pragma unroll
            for (int q = 0; q < 8; q++) { a_[q] = As[kk*128 + tm + q]; b_[q] = Bs[kk*128 + tn + q]; }
            #pragma unroll
            for (int i = 0; i < 8; i++)
                #pragma unroll
                for (int j = 0; j < 8; j++)
                    acc[i][j] += a_[i] * b_[j];
        }
        __syncthreads();
    }
    #pragma unroll
    for (int i = 0; i < 8; i++) {
        int gm = m0 + tm + i;
        #pragma unroll
        for (int j = 0; j < 8; j++) {
            float t = acc[i][j];
            int col = n0 + tn + j;
            if (EPI >= 1) t += bias[(size_t)z * biasStride + col];
            if (EPI == 2) t += resid[(size_t)gm * Nt + col];
            if (EPI == 3) {
                t = t > 0.f ? t * t : 0.f;
                bf16 hv = __float2bfloat16_rn(t);
                Chi[(size_t)z * cStride + (size_t)gm * Nt + col] = hv;
                Clo[(size_t)z * cStride + (size_t)gm * Nt + col] = __float2bfloat16_rn(t - __bfloat162float(hv));
            } else {
                Cf[(size_t)z * cStride + (size_t)gm * Nt + col] = t;
            }
        }
    }
#endif
}

// ---------------- block reduce ----------------
__device__ __forceinline__ float blockReduceSum(float v) {
    __shared__ float sh[32];
    int lane = threadIdx.x & 31, w = threadIdx.x >> 5;
    #pragma unroll
    for (int o = 16; o; o >>= 1) v += __shfl_down_sync(0xffffffffu, v, o);
    if (lane == 0) sh[w] = v;
    __syncthreads();
    int nw = blockDim.x >> 5;
    if (w == 0) {
        v = (lane < nw) ? sh[lane] : 0.f;
        #pragma unroll
        for (int o = 16; o; o >>= 1) v += __shfl_down_sync(0xffffffffu, v, o);
        if (lane == 0) sh[0] = v;
    }
    __syncthreads();
    return sh[0];
}

// ---------------- 1) residual mix + rmsnorm -> abf hi/lo ----------------
__global__ void mix_rms_kernel(const float* __restrict__ x, const float* __restrict__ x0,
                               const float* __restrict__ lambdas) {
    int row = blockIdx.x;
    float l0 = lambdas[0], l1 = lambdas[1];
    size_t off = (size_t)row * CC + threadIdx.x * 4;
    float4 a = *(const float4*)(x + off);
    float4 b = *(const float4*)(x0 + off);
    float4 v;
    v.x = l0*a.x + l1*b.x; v.y = l0*a.y + l1*b.y;
    v.z = l0*a.z + l1*b.z; v.w = l0*a.w + l1*b.w;
    *(float4*)(g_xmix + off) = v;
    float ss = v.x*v.x + v.y*v.y + v.z*v.z + v.w*v.w;
    float tot = blockReduceSum(ss);
    float sc = rsqrtf(tot * (1.0f/CC) + 1e-6f);
    float4 o; o.x = v.x*sc; o.y = v.y*sc; o.z = v.z*sc; o.w = v.w*sc;
    uint2 hv, lv; split4(o, hv, lv);
    *(uint2*)(&g_abf[0][off]) = hv;
    *(uint2*)(&g_abf[1][off]) = lv;
}

// ---------------- 6) rmsnorm of x2 -> g_h fp32 + hbf hi/lo ----------------
__global__ void rms2_kernel(const float* __restrict__ src) {
    int row = blockIdx.x;
    size_t off = (size_t)row * CC + threadIdx.x * 4;
    float4 v = *(const float4*)(src + off);
    float ss = v.x*v.x + v.y*v.y + v.z*v.z + v.w*v.w;
    float tot = blockReduceSum(ss);
    float sc = rsqrtf(tot * (1.0f/CC) + 1e-6f);
    float4 o; o.x = v.x*sc; o.y = v.y*sc; o.z = v.z*sc; o.w = v.w*sc;
    *(float4*)(g_h + off) = o;
    uint2 hv, lv; split4(o, hv, lv);
    *(uint2*)(&g_hbf[0][off]) = hv;
    *(uint2*)(&g_hbf[1][off]) = lv;
}

// ---------------- 3) per-head rmsnorm + rotary -> qbf/kbf hi/lo [bh][t][d] ----------------
__global__ void qk_rot_kernel() {
    int gw = blockIdx.x * (blockDim.x >> 5) + (threadIdx.x >> 5);
    int lane = threadIdx.x & 31;
    int qk = gw >> 16;
    int r  = gw & 65535;
    int n  = r >> 4;
    int h  = r & 15;
    const float* p = g_qkv + (size_t)qk * NTOK * CC + (size_t)n * CC + h * HD;
    float x1 = p[lane], x2 = p[lane + 32];
    float ss = x1 * x1 + x2 * x2;
    #pragma unroll
    for (int o = 16; o; o >>= 1) ss += __shfl_xor_sync(0xffffffffu, ss, o);
    float sc = rsqrtf(ss * (1.0f/HD) + 1e-6f);
    x1 *= sc; x2 *= sc;
    int b = n >> 11, t = n & (TT - 1);
    float invj = (lane < 16) ? c_rotinv[lane] : 0.f;
    float th = (float)t * invj;
    float c = cosf(th), s = sinf(th);
    float y1 =  x1 * c + x2 * s;
    float y2 = -x1 * s + x2 * c;
    size_t base = ((size_t)(b * HH + h) * TT + t) * HD;
    bf16* hi = qk ? g_kbf[0] : g_qbf[0];
    bf16* lo = qk ? g_kbf[1] : g_qbf[1];
    bf16 h1 = __float2bfloat16_rn(y1), h2 = __float2bfloat16_rn(y2);
    hi[base + lane]      = h1;
    hi[base + lane + 32] = h2;
    lo[base + lane]      = __float2bfloat16_rn(y1 - __bfloat162float(h1));
    lo[base + lane + 32] = __float2bfloat16_rn(y2 - __bfloat162float(h2));
}

// ---------------- 3b) V transpose+convert: g_qkv[z=2] -> vT [bh][d][t] hi/lo ----------------
__global__ __launch_bounds__(256) void vT_kernel() {
    __shared__ float s[128][65];
    int tblk = blockIdx.x, bh = blockIdx.y;
    int b = bh >> 4, h = bh & 15;
    int t0 = tblk * 128;
    const float* vsrc = g_qkv + (size_t)2 * NTOK * CC;
    #pragma unroll
    for (int i = 0; i < 32; i++) {
        int f = threadIdx.x + i * 256;
        int t = f >> 6, d = f & 63;
        s[t][d] = vsrc[((size_t)(b * TT + t0 + t)) * CC + h * HD + d];
    }
    __syncthreads();
    #pragma unroll
    for (int i = 0; i < 32; i++) {
        int f = threadIdx.x + i * 256;
        int d = f >> 7, t = f & 127;
        float v = s[t][d];
        bf16 hv = __float2bfloat16_rn(v);
        size_t off = ((size_t)(bh * HD + d)) * TT + t0 + t;
        g_vT[0][off] = hv;
        g_vT[1][off] = __float2bfloat16_rn(v - __bfloat162float(hv));
    }
}

// ---------------- 4) tensor-core causal attention ----------------
// CTA = (qtile, bh). 256 threads. TMEM: S[0..127] fp32, P[128..191] bf16x2, O[192..255] fp32.
#define ASM_QHI 2048
#define ASM_QLO 18432
#define ASM_KHI 34816
#define ASM_KLO 51200
#define ASM_VHI 67584
#define ASM_VLO 83968
#define ASM_L2  128
#define SMEM_ATT (ASM_VLO + 16384)

__global__ __launch_bounds__(256) void attn_tc() {
    extern __shared__ char smem[];
    int qtile = blockIdx.x, bh = blockIdx.y;
    int b = bh >> 4, h = bh & 15;
    int q0 = qtile * 128;
    int tid = threadIdx.x, wid = tid >> 5, lane = tid & 31;
    int half = wid >> 2;
    int row = (wid & 3) * 32 + lane;      // q row within tile

    const bf16* qh_g = g_qbf[0] + ((size_t)bh * TT + q0) * HD;
    const bf16* ql_g = g_qbf[1] + ((size_t)bh * TT + q0) * HD;

#if USE_TC
    uint32_t sbase = smem_u32(smem);
    const uint32_t MB0 = sbase + 8, MB1 = sbase + 16;
    float* l2s = (float*)(smem + ASM_L2);
    if (tid == 0) { MBAR_INIT(MB0, 1); MBAR_INIT(MB1, 1); }
    if (wid == 0) { TC_ALLOC(sbase + 0, 256u); }
    __syncthreads();
    uint32_t tmem = *(uint32_t*)(smem + 0);
    const uint32_t S_OFF = 0, P_OFF = 128, O_OFF = 192;
    const uint32_t IDS = (1u<<4)|(1u<<7)|(1u<<10)|(16u<<17)|(8u<<24);  // N=128
    const uint32_t IDA = (1u<<4)|(1u<<7)|(1u<<10)|( 8u<<17)|(8u<<24);  // N=64

    // load Q tile (128 x 64) hi/lo into SW128 smem
    #pragma unroll
    for (int i = 0; i < 4; i++) {
        int f = tid + i * 256;
        int r = f >> 3, c8 = f & 7;
        uint32_t so = sw128((uint32_t)(r * 128 + c8 * 16));
        *(uint4*)(smem + ASM_QHI + so) = *(const uint4*)(qh_g + (size_t)r * HD + c8 * 8);
        *(uint4*)(smem + ASM_QLO + so) = *(const uint4*)(ql_g + (size_t)r * HD + c8 * 8);
    }

    float l = 0.f;
    int ph0 = 0, ph1 = 0;
    const uint64_t vstep[8] = {0, 2, 4, 6, 512, 514, 516, 518};

    for (int kt = 0; kt <= qtile; kt++) {
        int kb = kt * 128;
        if (kt > 0) { mbar_wait(MB1, ph1); ph1 ^= 1; }   // AV of prev done: K/V/P reusable
        __syncthreads();
        // load K tile (128 x 64) hi/lo
        const bf16* kh_g = g_kbf[0] + ((size_t)bh * TT + kb) * HD;
        const bf16* kl_g = g_kbf[1] + ((size_t)bh * TT + kb) * HD;
        #pragma unroll
        for (int i = 0; i < 4; i++) {
            int f = tid + i * 256;
            int r = f >> 3, c8 = f & 7;
            uint32_t so = sw128((uint32_t)(r * 128 + c8 * 16));
            *(uint4*)(smem + ASM_KHI + so) = *(const uint4*)(kh_g + (size_t)r * HD + c8 * 8);
            *(uint4*)(smem + ASM_KLO + so) = *(const uint4*)(kl_g + (size_t)r * HD + c8 * 8);
        }
        // load V^T tile (64 d x 128 k) hi/lo, blocked-atom SW128
        const bf16* vh_g = g_vT[0] + (size_t)bh * HD * TT + kb;
        const bf16* vl_g = g_vT[1] + (size_t)bh * HD * TT + kb;
        #pragma unroll
        for (int i = 0; i < 4; i++) {
            int f = tid + i * 256;
            int d = f >> 4, c16 = f & 15;
            uint32_t byte = (uint32_t)((d >> 3) * 1024 + (c16 >> 3) * 8192 + (d & 7) * 128 + (c16 & 7) * 16);
            uint32_t so = sw128(byte);
            *(uint4*)(smem + ASM_VHI + so) = *(const uint4*)(vh_g + (size_t)d * TT + c16 * 8);
            *(uint4*)(smem + ASM_VLO + so) = *(const uint4*)(vl_g + (size_t)d * TT + c16 * 8);
        }
        asm volatile("fence.proxy.async.shared::cta;" ::: "memory");
        __syncthreads();

        // S = Qhi*Khi + Qlo*Khi + Qhi*Klo
        if (wid == 0 && elect_one()) {
            uint64_t qh = make_desc(sbase + ASM_QHI);
            uint64_t ql = make_desc(sbase + ASM_QLO);
            uint64_t kh = make_desc(sbase + ASM_KHI);
            uint64_t kl = make_desc(sbase + ASM_KLO);
            #pragma unroll
            for (int ks = 0; ks < 4; ks++) {
                uint64_t o = ks * 2;
                mma_ss_bf16(tmem + S_OFF, qh + o, kh + o, IDS, ks > 0 ? 1u : 0u);
                mma_ss_bf16(tmem + S_OFF, qh + o, kl + o, IDS, 1u);
                mma_ss_bf16(tmem + S_OFF, ql + o, kh + o, IDS, 1u);
            }
            TC_COMMIT(MB0);
        }
        mbar_wait(MB0, ph0); ph0 ^= 1;
        TC_FENCE_AFTER();

        // softmax (no max-subtraction: |s| <= 8 by rmsnorm bound)
        uint32_t sr[64];
        TC_LD_X32(sr,      tmem + S_OFF + half * 64);
        TC_LD_X32(sr + 32, tmem + S_OFF + half * 64 + 32);
        TC_WAIT_LD();
        int qg = q0 + row;
        int kbase = kb + half * 64;
        bool maskTile = (kt == qtile);
        uint32_t pw[32];
        float lacc = 0.f;
        #pragma unroll
        for (int j2 = 0; j2 < 32; j2++) {
            float s0 = __uint_as_float(sr[2*j2])   * 0.125f;
            float s1 = __uint_as_float(sr[2*j2+1]) * 0.125f;
            float p0 = __expf(s0), p1 = __expf(s1);
            if (maskTile) {
                if (kbase + 2*j2     > qg) p0 = 0.f;
                if (kbase + 2*j2 + 1 > qg) p1 = 0.f;
            }
            bf162 pb = __floats2bfloat162_rn(p0, p1);
            lacc += __bfloat162float(pb.x) + __bfloat162float(pb.y);
            pw[j2] = *(uint32_t*)&pb;
        }
        l += lacc;
        TC_ST_X32(tmem + P_OFF + half * 32 + ((uint32_t)(wid & 3) << 21), pw);
        TC_WAIT_ST();
        __syncthreads();

        // O += P * (Vhi + Vlo)   (TS mode: P in TMEM)
        if (wid == 0 && elect_one()) {
            uint64_t vh = make_desc(sbase + ASM_VHI);
            uint64_t vl = make_desc(sbase + ASM_VLO);
            #pragma unroll
            for (int ks = 0; ks < 8; ks++) {
                uint32_t at = tmem + P_OFF + ks * 8;
                mma_ts_bf16(tmem + O_OFF, at, vh + vstep[ks], IDA, (kt > 0 || ks > 0) ? 1u : 0u);
                mma_ts_bf16(tmem + O_OFF, at, vl + vstep[ks], IDA, 1u);
            }
            TC_COMMIT(MB1);
        }
    }
    mbar_wait(MB1, ph1);
    TC_FENCE_AFTER();

    // l reduction across the two column-halves
    l2s[half * 128 + row] = l;
    __syncthreads();
    float inv = 1.f / (l2s[row] + l2s[128 + row]);

    uint32_t od[32];
    TC_LD_X32(od, tmem + O_OFF + half * 32);
    TC_WAIT_LD();
    int token = b * TT + q0 + row;
    bf16* ohp = g_obf[0] + (size_t)token * CC + h * HD + half * 32;
    bf16* olp = g_obf[1] + (size_t)token * CC + h * HD + half * 32;
    #pragma unroll
    for (int j = 0; j < 32; j += 4) {
        float4 v;
        v.x = __uint_as_float(od[j+0]) * inv;
        v.y = __uint_as_float(od[j+1]) * inv;
        v.z = __uint_as_float(od[j+2]) * inv;
        v.w = __uint_as_float(od[j+3]) * inv;
        uint2 hv, lv; split4(v, hv, lv);
        *(uint2*)(ohp + j) = hv; *(uint2*)(olp + j) = lv;
    }
    TC_FENCE_BEFORE();
    __syncthreads();
    if (wid == 0) { TC_RELINQ(); TC_DEALLOC(tmem, 256u); }

#else // ---------------- SIMT fallback attention ----------------
    // one thread per query (two passes of 128 threads); simple, correct
    for (int qq = tid; qq < 128; qq += 256) {
        int qg = q0 + qq;
        float q[HD], o[HD];
        #pragma unroll
        for (int d = 0; d < HD; d++) {
            q[d] = (__bfloat162float(qh_g[(size_t)qq*HD+d]) + __bfloat162float(ql_g[(size_t)qq*HD+d])) * 0.125f;
            o[d] = 0.f;
        }
        float l = 0.f;
        for (int k = 0; k <= qg - b*0; k++) {
            if (k > qg) break;
            const bf16* kh_g = g_kbf[0] + ((size_t)bh * TT + k) * HD;
            const bf16* kl_g = g_kbf[1] + ((size_t)bh * TT + k) * HD;
            float s = 0.f;
            #pragma unroll
            for (int d = 0; d < HD; d++)
                s += q[d] * (__bfloat162float(kh_g[d]) + __bfloat162float(kl_g[d]));
            float p = __expf(s);
            l += p;
            #pragma unroll
            for (int d = 0; d < HD; d++) {
                size_t vo = ((size_t)bh * HD + d) * TT + k;
                o[d] += p * (__bfloat162float(g_vT[0][vo]) + __bfloat162float(g_vT[1][vo]));
            }
        }
        float inv = 1.f / l;
        int token = b * TT + qg - q0 + q0;
        #pragma unroll
        for (int d = 0; d < HD; d++) {
            float v = o[d] * inv;
            bf16 hv = __float2bfloat16_rn(v);
            g_obf[0][(size_t)token * CC + h * HD + d] = hv;
            g_obf[1][(size_t)token * CC + h * HD + d] = __float2bfloat16_rn(v - __bfloat162float(hv));
        }
    }
#endif
}

// ---------------- 7) router ----------------
__global__ void router_kernel(const float* __restrict__ rw, const float* __restrict__ rb,
                              const float* __restrict__ nw, const float* __restrict__ nb,
                              const float* __restrict__ noise) {
    int n = blockIdx.x;
    int w = threadIdx.x >> 5, lane = threadIdx.x & 31;
    const float* hr = g_h + (size_t)n * CC;
    const float* wr = rw + (size_t)w * CC;
    const float* wn = nw + (size_t)w * CC;
    float s1 = 0.f, s2 = 0.f;
    for (int c = lane * 4; c < CC; c += 128) {
        float4 hv = *(const float4*)(hr + c);
        float4 r4 = *(const float4*)(wr + c);
        float4 n4 = *(const float4*)(wn + c);
        s1 += hv.x*r4.x + hv.y*r4.y + hv.z*r4.z + hv.w*r4.w;
        s2 += hv.x*n4.x + hv.y*n4.y + hv.z*n4.z + hv.w*n4.w;
    }
    #pragma unroll
    for (int o = 16; o; o >>= 1) {
        s1 += __shfl_xor_sync(0xffffffffu, s1, o);
        s2 += __shfl_xor_sync(0xffffffffu, s2, o);
    }
    __shared__ float lg[8], nl[8];
    if (lane == 0) { lg[w] = s1 + rb[w]; nl[w] = s2 + nb[w]; }
    __syncthreads();
    if (threadIdx.x == 0) {
        float nv[8];
        #pragma unroll
        for (int e = 0; e < 8; e++) {
            float xn = nl[e];
            float sp = (xn > 20.f) ? xn : log1pf(expf(xn));
            nv[e] = lg[e] + noise[(size_t)n * EE + e] * sp;
        }
        int i0 = 0; float v0 = nv[0];
        #pragma unroll
        for (int e = 1; e < 8; e++) if (nv[e] > v0) { v0 = nv[e]; i0 = e; }
        float v1 = -1e30f;
        #pragma unroll
        for (int e = 0; e < 8; e++) if (e != i0 && nv[e] > v1) { v1 = nv[e]; }
        float e1 = expf(v1 - v0);
        g_g0[n] = 1.f / (1.f + e1);
        g_eid[n] = i0;
    }
}

// ---------------- 8) per-expert capacity lists ----------------
__global__ void build_idx_kernel() {
    int w = threadIdx.x >> 5, lane = threadIdx.x & 31;
    int count = 0;
    for (int base = 0; base < NTOK; base += 32) {
        int t = base + lane;
        bool p = (g_eid[t] == w);
        unsigned msk = __ballot_sync(0xffffffffu, p);
        int pos = count + __popc(msk & ((1u << lane) - 1u));
        if (p && pos < CAPX) g_idx[w * CAPX + pos] = t;
        count += __popc(msk);
    }
    int c = min(count, CAPX);
    if (lane == 0) g_cnt[w] = c;
    for (int s = c + lane; s < CAPX; s += 32) g_idx[w * CAPX + s] = NTOK;
}

// ---------------- 11) scatter ----------------
__global__ void scatter_kernel(float* __restrict__ out) {
    int e = blockIdx.x >> 10;
    int slot = blockIdx.x & (CAPX - 1);
    if (slot >= g_cnt[e]) return;
    int t = g_idx[e * CAPX + slot];
    float g = g_g0[t];
    const float* src = g_oe + ((size_t)e * CAPX + slot) * CC;
    float* dst = out + (size_t)t * CC;
    int c = threadIdx.x * 4;
    float4 s = *(const float4*)(src + c);
    float4 d = *(const float4*)(dst + c);
    d.x += g * s.x; d.y += g * s.y; d.z += g * s.z; d.w += g * s.w;
    *(float4*)(dst + c) = d;
}

// ---------------- host launcher ----------------
extern "C" void kernel_launch(void* const* d_in, const int* in_sizes, int n_in,
                              void* d_out, int out_size) {
    const float* x        = (const float*)d_in[0];
    const float* x0       = (const float*)d_in[1];
    const float* noise    = (const float*)d_in[2];
    const float* lambdas  = (const float*)d_in[3];
    const float* qkv_w    = (const float*)d_in[5];
    const float* c_proj_w = (const float*)d_in[6];
    const float* c_proj_b = (const float*)d_in[7];
    const float* router_w = (const float*)d_in[8];
    const float* router_b = (const float*)d_in[9];
    const float* noise_w  = (const float*)d_in[10];
    const float* noise_b  = (const float*)d_in[11];
    const float* ew1      = (const float*)d_in[12];
    const float* eb1      = (const float*)d_in[13];
    const float* ew2      = (const float*)d_in[14];
    const float* eb2      = (const float*)d_in[15];
    float* out = (float*)d_out;

    void *p_qkv, *p_xmix, *p_h, *p_oe, *p_idx, *p_cnt;
    void *p_abf, *p_obf, *p_hbf, *p_h1bf, *p_wqkv, *p_wcp, *p_we1, *p_we2;
    cudaGetSymbolAddress(&p_qkv,  g_qkv);
    cudaGetSymbolAddress(&p_xmix, g_xmix);
    cudaGetSymbolAddress(&p_h,    g_h);
    cudaGetSymbolAddress(&p_oe,   g_oe);
    cudaGetSymbolAddress(&p_idx,  g_idx);
    cudaGetSymbolAddress(&p_cnt,  g_cnt);
    cudaGetSymbolAddress(&p_abf,  g_abf);
    cudaGetSymbolAddress(&p_obf,  g_obf);
    cudaGetSymbolAddress(&p_hbf,  g_hbf);
    cudaGetSymbolAddress(&p_h1bf, g_h1bf);
    cudaGetSymbolAddress(&p_wqkv, g_wqkv);
    cudaGetSymbolAddress(&p_wcp,  g_wcp);
    cudaGetSymbolAddress(&p_we1,  g_we1);
    cudaGetSymbolAddress(&p_we2,  g_we2);

    bf16* abf_h  = (bf16*)p_abf;   bf16* abf_l  = abf_h  + (size_t)NTOK*CC;
    bf16* obf_h  = (bf16*)p_obf;   bf16* obf_l  = obf_h  + (size_t)NTOK*CC;
    bf16* hbf_h  = (bf16*)p_hbf;   bf16* hbf_l  = hbf_h  + (size_t)NTOK*CC;
    bf16* h1_h   = (bf16*)p_h1bf;  bf16* h1_l   = h1_h   + (size_t)EE*CAPX*HID;
    bf16* wqkv_h = (bf16*)p_wqkv;  bf16* wqkv_l = wqkv_h + (size_t)3*CC*CC;
    bf16* wcp_h  = (bf16*)p_wcp;   bf16* wcp_l  = wcp_h  + (size_t)CC*CC;
    bf16* we1_h  = (bf16*)p_we1;   bf16* we1_l  = we1_h  + (size_t)EE*HID*CC;
    bf16* we2_h  = (bf16*)p_we2;   bf16* we2_l  = we2_h  + (size_t)EE*CC*HID;

    cudaFuncSetAttribute(gemm_bf<0,false,false>, cudaFuncAttributeMaxDynamicSharedMemorySize, SMEM_TOTAL_TC);
    cudaFuncSetAttribute(gemm_bf<2,false,false>, cudaFuncAttributeMaxDynamicSharedMemorySize, SMEM_TOTAL_TC);
    cudaFuncSetAttribute(gemm_bf<3,true, true >, cudaFuncAttributeMaxDynamicSharedMemorySize, SMEM_TOTAL_TC);
    cudaFuncSetAttribute(gemm_bf<1,false,true >, cudaFuncAttributeMaxDynamicSharedMemorySize, SMEM_TOTAL_TC);
    cudaFuncSetAttribute(attn_tc, cudaFuncAttributeMaxDynamicSharedMemorySize, SMEM_ATT);

    // weight conversions (independent of activations; launch first)
    conv_kernel<<<(3*CC*CC/4 + 255)/256, 256>>>(qkv_w,    wqkv_h, wqkv_l, (long)3*CC*CC/4);
    conv_kernel<<<(CC*CC/4 + 255)/256, 256>>>(c_proj_w, wcp_h,  wcp_l,  (long)CC*CC/4);
    conv_kernel<<<((long)EE*HID*CC/4 + 255)/256, 256>>>(ew1, we1_h, we1_l, (long)EE*HID*CC/4);
    conv_kernel<<<((long)EE*CC*HID/4 + 255)/256, 256>>>(ew2, we2_h, we2_l, (long)EE*CC*HID/4);

    // 1) residual mix + rmsnorm -> abf
    mix_rms_kernel<<<NTOK, 256>>>(x, x0, lambdas);

    // 2) qkv = a @ qkv_w^T  -> fp32 g_qkv
    gemm_bf<0,false,false><<<dim3(CC/128, NTOK/128, 3), 256, SMEM_TOTAL_TC>>>(
        abf_h, abf_l, 0L, wqkv_h, wqkv_l, (long)CC*CC,
        (float*)p_qkv, nullptr, nullptr, (long)NTOK*CC,
        nullptr, 0, nullptr, nullptr, nullptr, CC, CC);

    // 3) per-head rmsnorm + rotary -> qbf/kbf; V transpose -> vT
    qk_rot_kernel<<<(2 * NTOK * HH) / 8, 256>>>();
    vT_kernel<<<dim3(TT/128, 2*HH), 256>>>();

    // 4) attention -> obf
    attn_tc<<<dim3(TT/128, 2*HH), 256, SMEM_ATT>>>();

    // 5) x2 = xmix + o @ c_proj_w^T + b -> d_out
    gemm_bf<2,false,false><<<dim3(CC/128, NTOK/128, 1), 256, SMEM_TOTAL_TC>>>(
        obf_h, obf_l, 0L, wcp_h, wcp_l, 0L,
        out, nullptr, nullptr, 0L,
        c_proj_b, 0, (const float*)p_xmix, nullptr, nullptr, CC, CC);

    // 6) h = rmsnorm(x2) -> g_h + hbf
    rms2_kernel<<<NTOK, 256>>>(out);

    // 7) router, 8) index lists
    router_kernel<<<NTOK, 256>>>(router_w, router_b, noise_w, noise_b, noise);
    build_idx_kernel<<<1, 256>>>();

    // 9) h1 = sq(relu(gather(h) @ ew1^T + eb1)) -> h1 bf16 hi/lo
    gemm_bf<3,true,true><<<dim3(HID/128, CAPX/128, EE), 256, SMEM_TOTAL_TC>>>(
        hbf_h, hbf_l, 0L, we1_h, we1_l, (long)HID*CC,
        nullptr, h1_h, h1_l, (long)CAPX*HID,
        eb1, HID, nullptr, (const int*)p_idx, (const int*)p_cnt, HID, CC);

    // 10) oe = h1 @ ew2^T + eb2 -> fp32 g_oe
    gemm_bf<1,false,true><<<dim3(CC/128, CAPX/128, EE), 256, SMEM_TOTAL_TC>>>(
        h1_h, h1_l, (long)CAPX*HID, we2_h, we2_l, (long)CC*HID,
        (float*)p_oe, nullptr, nullptr, (long)CAPX*CC,
        eb2, CC, nullptr, nullptr, (const int*)p_cnt, CC, HID);

    // 11) scatter
    scatter_kernel<<<EE * CAPX, 256>>>(out);
}

// round 5
// speedup vs baseline: 10.3489x; 1.6048x over previous
#include <cuda_runtime.h>
#include <cuda_bf16.h>
#include <math.h>
#include <stdint.h>

#define NTOK 4096
#define TT   2048
#define CC   1024
#define HH   16
#define HD   64
#define EE   8
#define CAPX 1024
#define HID  4096

#if defined(__CUDA_ARCH__)
# if (__CUDA_ARCH__ >= 1000) && (defined(__CUDA_ARCH_FEAT_SM103_ALL) || defined(__CUDA_ARCH_FEAT_SM100_ALL) || defined(__CUDA_ARCH_SPECIFIC__) || defined(__CUDA_ARCH_FAMILY_SPECIFIC__))
#  define USE_TC 1
# else
#  define USE_TC 0
# endif
#else
# define USE_TC 0
#endif

typedef __nv_bfloat16 bf16;
typedef __nv_bfloat162 bf162;

// ---------------- scratch ----------------
__device__ float g_xmix[(size_t)NTOK*CC];
__device__ float g_qkv [(size_t)3*NTOK*CC];
__device__ float g_h   [(size_t)NTOK*CC];
__device__ float g_oe  [(size_t)EE*CAPX*CC];
__device__ float g_g0  [NTOK];
__device__ int   g_eid [NTOK];
__device__ int   g_idx [EE*CAPX];
__device__ int   g_cnt [EE];
__device__ bf16 g_abf [2][(size_t)NTOK*CC];
__device__ bf16 g_obf [2][(size_t)NTOK*CC];
__device__ bf16 g_hbf [2][(size_t)NTOK*CC];
__device__ bf16 g_qbf [2][(size_t)NTOK*CC];      // [bh][t][d]
__device__ bf16 g_kbf [2][(size_t)NTOK*CC];      // [bh][t][d]
__device__ bf16 g_vT  [2][(size_t)NTOK*CC];      // [bh][d][t]
__device__ bf16 g_h1bf[2][(size_t)EE*CAPX*HID];
__device__ bf16 g_wqkv[2][(size_t)3*CC*CC];
__device__ bf16 g_wcp [2][(size_t)CC*CC];
__device__ bf16 g_we1 [2][(size_t)EE*HID*CC];
__device__ bf16 g_we2 [2][(size_t)EE*CC*HID];

__constant__ float c_rotinv[16] = {
    1.0f, 0.6299605249474366f, 0.39685026299204984f, 0.25f,
    0.15749013123685915f, 0.09921256574801246f, 0.0625f, 0.03937253280921479f,
    0.024803141437003115f, 0.015625f, 0.009843133202303697f, 0.0062007853592507785f,
    0.00390625f, 0.0024607833005759242f, 0.0015501963398126947f, 0.0009765625f
};

// ---------------- helpers ----------------
__device__ __forceinline__ uint32_t smem_u32(const void* p) {
    uint32_t a;
    asm("{ .reg .u64 t; cvta.to.shared.u64 t, %1; cvt.u32.u64 %0, t; }" : "=r"(a) : "l"(p));
    return a;
}
__device__ __forceinline__ uint32_t sw128(uint32_t off) { return off ^ ((off >> 3) & 0x70); }

__device__ __forceinline__ void cpa16(uint32_t d, const void* s) {
    asm volatile("cp.async.cg.shared.global [%0], [%1], 16;" :: "r"(d), "l"(s) : "memory");
}
#define CPA_COMMIT() asm volatile("cp.async.commit_group;" ::: "memory")
#define CPA_WAIT(n)  asm volatile("cp.async.wait_group %0;" :: "n"(n) : "memory")

__device__ __forceinline__ void split4(float4 v, uint2& hv, uint2& lv) {
    bf16 h0 = __float2bfloat16_rn(v.x), h1 = __float2bfloat16_rn(v.y);
    bf16 h2 = __float2bfloat16_rn(v.z), h3 = __float2bfloat16_rn(v.w);
    bf162 hp0; hp0.x = h0; hp0.y = h1;
    bf162 hp1; hp1.x = h2; hp1.y = h3;
    bf162 lp0 = __floats2bfloat162_rn(v.x - __bfloat162float(h0), v.y - __bfloat162float(h1));
    bf162 lp1 = __floats2bfloat162_rn(v.z - __bfloat162float(h2), v.w - __bfloat162float(h3));
    hv.x = *(uint32_t*)&hp0; hv.y = *(uint32_t*)&hp1;
    lv.x = *(uint32_t*)&lp0; lv.y = *(uint32_t*)&lp1;
}

#if USE_TC
__device__ __forceinline__ uint32_t elect_one() {
    uint32_t p;
    asm volatile("{\n\t.reg .pred p;\n\telect.sync _|p, 0xFFFFFFFF;\n\tselp.b32 %0, 1, 0, p;\n\t}" : "=r"(p));
    return p;
}
#define MBAR_INIT(addr, cnt) \
    asm volatile("mbarrier.init.shared.b64 [%0], %1;" :: "r"(addr), "r"(cnt) : "memory")
__device__ __forceinline__ void mbar_wait(uint32_t addr, int phase) {
    uint32_t done = 0;
    while (!done) {
        asm volatile("{\n\t.reg .pred p;\n\t"
            "mbarrier.try_wait.parity.acquire.cta.shared::cta.b64 p, [%1], %2, 0x989680;\n\t"
            "selp.b32 %0, 1, 0, p;\n\t}" : "=r"(done) : "r"(addr), "r"(phase) : "memory");
    }
}
#define TC_ALLOC(addr, n) \
    asm volatile("tcgen05.alloc.cta_group::1.sync.aligned.shared::cta.b32 [%0], %1;" :: "r"(addr), "r"(n) : "memory")
#define TC_DEALLOC(tm, n) \
    asm volatile("tcgen05.dealloc.cta_group::1.sync.aligned.b32 %0, %1;" :: "r"(tm), "r"(n))
#define TC_RELINQ() \
    asm volatile("tcgen05.relinquish_alloc_permit.cta_group::1.sync.aligned;")
#define TC_COMMIT(mbar) \
    asm volatile("tcgen05.commit.cta_group::1.mbarrier::arrive::one.shared::cluster.b64 [%0];" :: "r"(mbar) : "memory")
#define TC_FENCE_AFTER()  asm volatile("tcgen05.fence::after_thread_sync;" ::: "memory")
#define TC_FENCE_BEFORE() asm volatile("tcgen05.fence::before_thread_sync;" ::: "memory")
#define TC_WAIT_LD()      asm volatile("tcgen05.wait::ld.sync.aligned;" ::: "memory")
#define TC_WAIT_ST()      asm volatile("tcgen05.wait::st.sync.aligned;" ::: "memory")

#define TC_LD_X32(r, a) \
    asm volatile("tcgen05.ld.sync.aligned.32x32b.x32.b32 " \
        "{%0,%1,%2,%3,%4,%5,%6,%7,%8,%9,%10,%11,%12,%13,%14,%15," \
        "%16,%17,%18,%19,%20,%21,%22,%23,%24,%25,%26,%27,%28,%29,%30,%31}, [%32];" \
        : "=r"((r)[0]),"=r"((r)[1]),"=r"((r)[2]),"=r"((r)[3]),"=r"((r)[4]),"=r"((r)[5]),"=r"((r)[6]),"=r"((r)[7]), \
          "=r"((r)[8]),"=r"((r)[9]),"=r"((r)[10]),"=r"((r)[11]),"=r"((r)[12]),"=r"((r)[13]),"=r"((r)[14]),"=r"((r)[15]), \
          "=r"((r)[16]),"=r"((r)[17]),"=r"((r)[18]),"=r"((r)[19]),"=r"((r)[20]),"=r"((r)[21]),"=r"((r)[22]),"=r"((r)[23]), \
          "=r"((r)[24]),"=r"((r)[25]),"=r"((r)[26]),"=r"((r)[27]),"=r"((r)[28]),"=r"((r)[29]),"=r"((r)[30]),"=r"((r)[31]) \
        : "r"(a))

#define TC_ST_X32(a, r) \
    asm volatile("tcgen05.st.sync.aligned.32x32b.x32.b32 [%0], " \
        "{%1,%2,%3,%4,%5,%6,%7,%8,%9,%10,%11,%12,%13,%14,%15,%16," \
        "%17,%18,%19,%20,%21,%22,%23,%24,%25,%26,%27,%28,%29,%30,%31,%32};" \
        :: "r"(a), \
           "r"((r)[0]),"r"((r)[1]),"r"((r)[2]),"r"((r)[3]),"r"((r)[4]),"r"((r)[5]),"r"((r)[6]),"r"((r)[7]), \
           "r"((r)[8]),"r"((r)[9]),"r"((r)[10]),"r"((r)[11]),"r"((r)[12]),"r"((r)[13]),"r"((r)[14]),"r"((r)[15]), \
           "r"((r)[16]),"r"((r)[17]),"r"((r)[18]),"r"((r)[19]),"r"((r)[20]),"r"((r)[21]),"r"((r)[22]),"r"((r)[23]), \
           "r"((r)[24]),"r"((r)[25]),"r"((r)[26]),"r"((r)[27]),"r"((r)[28]),"r"((r)[29]),"r"((r)[30]),"r"((r)[31]) \
        : "memory")

__device__ __forceinline__ void mma_ss_bf16(uint32_t d, uint64_t ad, uint64_t bd,
                                            uint32_t idesc, uint32_t en) {
    asm volatile("{\n\t.reg .pred p;\n\tsetp.ne.u32 p, %4, 0;\n\t"
        "tcgen05.mma.cta_group::1.kind::f16 [%0], %1, %2, %3, {%5,%5,%5,%5}, p;\n\t}"
        :: "r"(d), "l"(ad), "l"(bd), "r"(idesc), "r"(en), "r"(0u) : "memory");
}
__device__ __forceinline__ void mma_ts_bf16(uint32_t d, uint32_t a, uint64_t bd,
                                            uint32_t idesc, uint32_t en) {
    asm volatile("{\n\t.reg .pred p;\n\tsetp.ne.u32 p, %4, 0;\n\t"
        "tcgen05.mma.cta_group::1.kind::f16 [%0], [%1], %2, %3, {%5,%5,%5,%5}, p;\n\t}"
        :: "r"(d), "r"(a), "l"(bd), "r"(idesc), "r"(en), "r"(0u) : "memory");
}
__device__ __forceinline__ uint64_t make_desc(uint32_t base) {
    const uint64_t B = (uint64_t(2) << 61) | (uint64_t(1) << 46) | (uint64_t(64) << 32) | (uint64_t(1) << 16);
    return B | ((uint64_t)(base >> 4) & 0x3FFF);
}
#endif // USE_TC

// ---------------- fp32 -> hi/lo bf16 ----------------
__global__ void conv_kernel(const float* __restrict__ src, bf16* __restrict__ hi,
                            bf16* __restrict__ lo, long n4) {
    long i = (long)blockIdx.x * blockDim.x + threadIdx.x;
    if (i >= n4) return;
    float4 v = ((const float4*)src)[i];
    uint2 hv, lv; split4(v, hv, lv);
    ((uint2*)hi)[i] = hv; ((uint2*)lo)[i] = lv;
}

// ======= bf16 GEMM (3-term split, 128x128 tile, cp.async mainloop) =======
#define TILE_BYTES 16384
#define BUF_BYTES  65536
#define SMEM_TOTAL_TC (1024 + 2*BUF_BYTES)

template<int EPI, bool GATHER, bool SKIP>
__global__ __launch_bounds__(256)
void gemm_bf(const bf16* __restrict__ Ahi, const bf16* __restrict__ Alo, long aStride,
             const bf16* __restrict__ Bhi, const bf16* __restrict__ Blo, long bStride,
             float* __restrict__ Cf, bf16* __restrict__ Chi, bf16* __restrict__ Clo, long cStride,
             const float* __restrict__ bias, int biasStride,
             const float* __restrict__ resid,
             const int* __restrict__ rowIdx,
             const int* __restrict__ counts,
             int Nt, int Kd) {
    extern __shared__ char smem[];
    const int z = blockIdx.z;
    const int m0 = blockIdx.y * 128, n0 = blockIdx.x * 128;
    if (SKIP) { if (m0 >= counts[z]) return; }
    int tid = threadIdx.x, wid = tid >> 5, lane = tid & 31;

    const uint32_t OFF_MB = 8, OFF_RID = 64, OFF_TILE = 1024;
    int* s_rid = (int*)(smem + OFF_RID);
    if (tid < 128) {
        int r;
        if (GATHER) r = min(rowIdx[z * CAPX + m0 + tid], NTOK - 1);
        else        r = m0 + tid;
        s_rid[tid] = r;
    }
    const bf16* Ahz = Ahi + (size_t)z * aStride;
    const bf16* Alz = Alo + (size_t)z * aStride;
    const bf16* Bhz = Bhi + (size_t)z * bStride;
    const bf16* Blz = Blo + (size_t)z * bStride;

#if USE_TC
    uint32_t sbase = smem_u32(smem);
    if (tid == 0) { MBAR_INIT(sbase + OFF_MB, 1); MBAR_INIT(sbase + OFF_MB + 8, 1); }
    if (wid == 0) { TC_ALLOC(sbase + 0, 128u); }
    __syncthreads();
    uint32_t tmem = *(uint32_t*)(smem + 0);

    const uint32_t idesc = (1u << 4) | (1u << 7) | (1u << 10) | (16u << 17) | (8u << 24);

    int nchunks = Kd >> 6;
    int ph0 = 0, ph1 = 0;

    for (int c = 0; c < nchunks; c++) {
        int buf = c & 1;
        uint32_t tb = sbase + OFF_TILE + buf * BUF_BYTES;
        if (c >= 2) {
            if (buf == 0) { mbar_wait(sbase + OFF_MB, ph0); ph0 ^= 1; }
            else          { mbar_wait(sbase + OFF_MB + 8, ph1); ph1 ^= 1; }
        }
        int k0 = c * 64;
        #pragma unroll
        for (int i = 0; i < 4; i++) {
            int f = tid + i * 256;
            int row = f >> 3, c8 = f & 7;
            uint32_t so = sw128((uint32_t)(row * 128 + c8 * 16));
            size_t aoff = (size_t)s_rid[row] * Kd + k0 + c8 * 8;
            size_t boff = (size_t)(n0 + row) * Kd + k0 + c8 * 8;
            cpa16(tb + so,                  Ahz + aoff);
            cpa16(tb + TILE_BYTES + so,     Alz + aoff);
            cpa16(tb + 2 * TILE_BYTES + so, Bhz + boff);
            cpa16(tb + 3 * TILE_BYTES + so, Blz + boff);
        }
        CPA_COMMIT();
        CPA_WAIT(0);
        asm volatile("fence.proxy.async.shared::cta;" ::: "memory");
        __syncthreads();
        if (wid == 0) {
            if (elect_one()) {
                uint64_t ah = make_desc(tb);
                uint64_t al = make_desc(tb + TILE_BYTES);
                uint64_t bh = make_desc(tb + 2 * TILE_BYTES);
                uint64_t bl = make_desc(tb + 3 * TILE_BYTES);
                #pragma unroll
                for (int ks = 0; ks < 4; ks++) {
                    uint64_t o = ks * 2;
                    mma_ss_bf16(tmem, ah + o, bh + o, idesc, (c > 0 || ks > 0) ? 1u : 0u);
                    mma_ss_bf16(tmem, ah + o, bl + o, idesc, 1u);
                    mma_ss_bf16(tmem, al + o, bh + o, idesc, 1u);
                }
                TC_COMMIT(sbase + OFF_MB + 8 * buf);
            }
        }
    }
    mbar_wait(sbase + OFF_MB, ph0);
    mbar_wait(sbase + OFF_MB + 8, ph1);
    TC_FENCE_AFTER();

    int colbase = (wid >> 2) * 64;
    int row = (wid & 3) * 32 + lane;
    uint32_t d_regs[64];
    TC_LD_X32(d_regs, tmem + colbase);
    TC_LD_X32(d_regs + 32, tmem + colbase + 32);
    TC_WAIT_LD();

    int gm = m0 + row;
    const float* rp = (EPI == 2) ? (resid + (size_t)gm * Nt + n0 + colbase) : nullptr;
    const float* bp = (EPI >= 1) ? (bias + (size_t)z * biasStride + n0 + colbase) : nullptr;
    if (EPI == 3) {
        bf16* chp = Chi + (size_t)z * cStride + (size_t)gm * Nt + n0 + colbase;
        bf16* clp = Clo + (size_t)z * cStride + (size_t)gm * Nt + n0 + colbase;
        #pragma unroll
        for (int j = 0; j < 64; j += 4) {
            float4 v;
            float t0 = __uint_as_float(d_regs[j+0]) + bp[j+0];
            float t1 = __uint_as_float(d_regs[j+1]) + bp[j+1];
            float t2 = __uint_as_float(d_regs[j+2]) + bp[j+2];
            float t3 = __uint_as_float(d_regs[j+3]) + bp[j+3];
            v.x = t0 > 0.f ? t0*t0 : 0.f; v.y = t1 > 0.f ? t1*t1 : 0.f;
            v.z = t2 > 0.f ? t2*t2 : 0.f; v.w = t3 > 0.f ? t3*t3 : 0.f;
            uint2 hv, lv; split4(v, hv, lv);
            *(uint2*)(chp + j) = hv; *(uint2*)(clp + j) = lv;
        }
    } else {
        float* cp = Cf + (size_t)z * cStride + (size_t)gm * Nt + n0 + colbase;
        #pragma unroll
        for (int j = 0; j < 64; j += 4) {
            float vv[4];
            #pragma unroll
            for (int q = 0; q < 4; q++) {
                float t = __uint_as_float(d_regs[j + q]);
                if (EPI == 1)      t += bp[j + q];
                else if (EPI == 2) t += bp[j + q] + rp[j + q];
                vv[q] = t;
            }
            float4 v4; v4.x = vv[0]; v4.y = vv[1]; v4.z = vv[2]; v4.w = vv[3];
            *(float4*)(cp + j) = v4;
        }
    }

    TC_FENCE_BEFORE();
    __syncthreads();
    if (wid == 0) { TC_RELINQ(); TC_DEALLOC(tmem, 128u); }

#else  // SIMT fallback
    float* As = (float*)(smem + OFF_TILE);
    float* Bs = (float*)(smem + OFF_TILE + 16 * 128 * 4);
    __syncthreads();
    int tm = (tid >> 4) * 8, tn = (tid & 15) * 8;
    float acc[8][8];
    #pragma unroll
    for (int i = 0; i < 8; i++)
        #pragma unroll
        for (int j = 0; j < 8; j++) acc[i][j] = 0.f;

    for (int k0 = 0; k0 < Kd; k0 += 16) {
        #pragma unroll
        for (int i = 0; i < 2; i++) {
            int f = tid + i * 256;
            int row = f >> 2, c4 = (f & 3) * 4;
            #pragma unroll
            for (int q = 0; q < 4; q++) {
                size_t ao = (size_t)s_rid[row] * Kd + k0 + c4 + q;
                size_t bo = (size_t)(n0 + row) * Kd + k0 + c4 + q;
                As[(c4+q)*128 + row] = __bfloat162float(Ahz[ao]) + __bfloat162float(Alz[ao]);
                Bs[(c4+q)*128 + row] = __bfloat162float(Bhz[bo]) + __bfloat162float(Blz[bo]);
            }
        }
        __syncthreads();
        #pragma unroll
        for (int kk = 0; kk < 16; kk++) {
            float a_[8], b_[8];
            #pragma unroll
            for (int q = 0; q < 8; q++) { a_[q] = As[kk*128 + tm + q]; b_[q] = Bs[kk*128 + tn + q]; }
            #pragma unroll
            for (int i = 0; i < 8; i++)
                #pragma unroll
                for (int j = 0; j < 8; j++)
                    acc[i][j] += a_[i] * b_[j];
        }
        __syncthreads();
    }
    #pragma unroll
    for (int i = 0; i < 8; i++) {
        int gm = m0 + tm + i;
        #pragma unroll
        for (int j = 0; j < 8; j++) {
            float t = acc[i][j];
            int col = n0 + tn + j;
            if (EPI >= 1) t += bias[(size_t)z * biasStride + col];
            if (EPI == 2) t += resid[(size_t)gm * Nt + col];
            if (EPI == 3) {
                t = t > 0.f ? t * t : 0.f;
                bf16 hv = __float2bfloat16_rn(t);
                Chi[(size_t)z * cStride + (size_t)gm * Nt + col] = hv;
                Clo[(size_t)z * cStride + (size_t)gm * Nt + col] = __float2bfloat16_rn(t - __bfloat162float(hv));
            } else {
                Cf[(size_t)z * cStride + (size_t)gm * Nt + col] = t;
            }
        }
    }
#endif
}

// ---------------- block reduce ----------------
__device__ __forceinline__ float blockReduceSum(float v) {
    __shared__ float sh[32];
    int lane = threadIdx.x & 31, w = threadIdx.x >> 5;
    #pragma unroll
    for (int o = 16; o; o >>= 1) v += __shfl_down_sync(0xffffffffu, v, o);
    if (lane == 0) sh[w] = v;
    __syncthreads();
    int nw = blockDim.x >> 5;
    if (w == 0) {
        v = (lane < nw) ? sh[lane] : 0.f;
        #pragma unroll
        for (int o = 16; o; o >>= 1) v += __shfl_down_sync(0xffffffffu, v, o);
        if (lane == 0) sh[0] = v;
    }
    __syncthreads();
    return sh[0];
}

// ---------------- 1) residual mix + rmsnorm ----------------
__global__ void mix_rms_kernel(const float* __restrict__ x, const float* __restrict__ x0,
                               const float* __restrict__ lambdas) {
    int row = blockIdx.x;
    float l0 = lambdas[0], l1 = lambdas[1];
    size_t off = (size_t)row * CC + threadIdx.x * 4;
    float4 a = *(const float4*)(x + off);
    float4 b = *(const float4*)(x0 + off);
    float4 v;
    v.x = l0*a.x + l1*b.x; v.y = l0*a.y + l1*b.y;
    v.z = l0*a.z + l1*b.z; v.w = l0*a.w + l1*b.w;
    *(float4*)(g_xmix + off) = v;
    float ss = v.x*v.x + v.y*v.y + v.z*v.z + v.w*v.w;
    float tot = blockReduceSum(ss);
    float sc = rsqrtf(tot * (1.0f/CC) + 1e-6f);
    float4 o; o.x = v.x*sc; o.y = v.y*sc; o.z = v.z*sc; o.w = v.w*sc;
    uint2 hv, lv; split4(o, hv, lv);
    *(uint2*)(&g_abf[0][off]) = hv;
    *(uint2*)(&g_abf[1][off]) = lv;
}

// ---------------- 6) rmsnorm of x2 ----------------
__global__ void rms2_kernel(const float* __restrict__ src) {
    int row = blockIdx.x;
    size_t off = (size_t)row * CC + threadIdx.x * 4;
    float4 v = *(const float4*)(src + off);
    float ss = v.x*v.x + v.y*v.y + v.z*v.z + v.w*v.w;
    float tot = blockReduceSum(ss);
    float sc = rsqrtf(tot * (1.0f/CC) + 1e-6f);
    float4 o; o.x = v.x*sc; o.y = v.y*sc; o.z = v.z*sc; o.w = v.w*sc;
    *(float4*)(g_h + off) = o;
    uint2 hv, lv; split4(o, hv, lv);
    *(uint2*)(&g_hbf[0][off]) = hv;
    *(uint2*)(&g_hbf[1][off]) = lv;
}

// ---------------- 3) per-head rmsnorm + rotary ----------------
__global__ void qk_rot_kernel() {
    int gw = blockIdx.x * (blockDim.x >> 5) + (threadIdx.x >> 5);
    int lane = threadIdx.x & 31;
    int qk = gw >> 16;
    int r  = gw & 65535;
    int n  = r >> 4;
    int h  = r & 15;
    const float* p = g_qkv + (size_t)qk * NTOK * CC + (size_t)n * CC + h * HD;
    float x1 = p[lane], x2 = p[lane + 32];
    float ss = x1 * x1 + x2 * x2;
    #pragma unroll
    for (int o = 16; o; o >>= 1) ss += __shfl_xor_sync(0xffffffffu, ss, o);
    float sc = rsqrtf(ss * (1.0f/HD) + 1e-6f);
    x1 *= sc; x2 *= sc;
    int b = n >> 11, t = n & (TT - 1);
    float invj = (lane < 16) ? c_rotinv[lane] : 0.f;
    float th = (float)t * invj;
    float c = cosf(th), s = sinf(th);
    float y1 =  x1 * c + x2 * s;
    float y2 = -x1 * s + x2 * c;
    size_t base = ((size_t)(b * HH + h) * TT + t) * HD;
    bf16* hi = qk ? g_kbf[0] : g_qbf[0];
    bf16* lo = qk ? g_kbf[1] : g_qbf[1];
    bf16 h1 = __float2bfloat16_rn(y1), h2 = __float2bfloat16_rn(y2);
    hi[base + lane]      = h1;
    hi[base + lane + 32] = h2;
    lo[base + lane]      = __float2bfloat16_rn(y1 - __bfloat162float(h1));
    lo[base + lane + 32] = __float2bfloat16_rn(y2 - __bfloat162float(h2));
}

// ---------------- 3b) V transpose+convert ----------------
__global__ __launch_bounds__(256) void vT_kernel() {
    __shared__ float s[128][65];
    int tblk = blockIdx.x, bh = blockIdx.y;
    int b = bh >> 4, h = bh & 15;
    int t0 = tblk * 128;
    const float* vsrc = g_qkv + (size_t)2 * NTOK * CC;
    #pragma unroll
    for (int i = 0; i < 32; i++) {
        int f = threadIdx.x + i * 256;
        int t = f >> 6, d = f & 63;
        s[t][d] = vsrc[((size_t)(b * TT + t0 + t)) * CC + h * HD + d];
    }
    __syncthreads();
    #pragma unroll
    for (int i = 0; i < 32; i++) {
        int f = threadIdx.x + i * 256;
        int d = f >> 7, t = f & 127;
        float v = s[t][d];
        bf16 hv = __float2bfloat16_rn(v);
        size_t off = ((size_t)(bh * HD + d)) * TT + t0 + t;
        g_vT[0][off] = hv;
        g_vT[1][off] = __float2bfloat16_rn(v - __bfloat162float(hv));
    }
}

// ---------------- 4) pipelined tensor-core causal attention ----------------
// TMEM: S0@0(128), S1@128(128), O@256(64), P0@320(64), P1@384(64)
#define AT_QHI 2048
#define AT_QLO (AT_QHI + 16384)
#define AT_KBUF 34816
#define AT_VBUF (AT_KBUF + 2*32768)
#define SMEM_ATT (AT_VBUF + 2*32768)
#define AT_L2 128

__global__ __launch_bounds__(256) void attn_tc() {
    extern __shared__ char smem[];
    int qtile = gridDim.x - 1 - blockIdx.x;   // LPT: biggest CTAs first
    int bh = blockIdx.y;
    int b = bh >> 4, h = bh & 15;
    int q0 = qtile * 128;
    int tid = threadIdx.x, wid = tid >> 5, lane = tid & 31;
    int half = wid >> 2;
    int row = (wid & 3) * 32 + lane;

    const bf16* qh_g = g_qbf[0] + ((size_t)bh * TT + q0) * HD;
    const bf16* ql_g = g_qbf[1] + ((size_t)bh * TT + q0) * HD;

#if USE_TC
    uint32_t sbase = smem_u32(smem);
    const uint32_t MBS = sbase + 8, MBA = sbase + 16;
    float* l2s = (float*)(smem + AT_L2);
    if (tid == 0) { MBAR_INIT(MBS, 1); MBAR_INIT(MBA, 1); }

    // prolog copies: Q + K(0) + V(0)
    {
        const bf16* kh_g = g_kbf[0] + ((size_t)bh * TT) * HD;
        const bf16* kl_g = g_kbf[1] + ((size_t)bh * TT) * HD;
        const bf16* vh_g = g_vT[0] + (size_t)bh * HD * TT;
        const bf16* vl_g = g_vT[1] + (size_t)bh * HD * TT;
        #pragma unroll
        for (int i = 0; i < 4; i++) {
            int f = tid + i * 256;
            int r = f >> 3, c8 = f & 7;
            uint32_t so = sw128((uint32_t)(r * 128 + c8 * 16));
            cpa16(sbase + AT_QHI + so, qh_g + (size_t)r * HD + c8 * 8);
            cpa16(sbase + AT_QLO + so, ql_g + (size_t)r * HD + c8 * 8);
            cpa16(sbase + AT_KBUF + so,         kh_g + (size_t)r * HD + c8 * 8);
            cpa16(sbase + AT_KBUF + 16384 + so, kl_g + (size_t)r * HD + c8 * 8);
        }
        #pragma unroll
        for (int i = 0; i < 4; i++) {
            int f = tid + i * 256;
            int d = f >> 4, c16 = f & 15;
            uint32_t byte = (uint32_t)((d >> 3) * 1024 + (c16 >> 3) * 8192 + (d & 7) * 128 + (c16 & 7) * 16);
            uint32_t so = sw128(byte);
            cpa16(sbase + AT_VBUF + so,         vh_g + (size_t)d * TT + c16 * 8);
            cpa16(sbase + AT_VBUF + 16384 + so, vl_g + (size_t)d * TT + c16 * 8);
        }
        CPA_COMMIT();
    }
    if (wid == 0) { TC_ALLOC(sbase + 0, 512u); }
    __syncthreads();
    uint32_t tmem = *(uint32_t*)(smem + 0);
    const uint32_t S0 = 0, O_OFF = 256, P0 = 320;
    const uint32_t IDS = (1u<<4)|(1u<<7)|(1u<<10)|(16u<<17)|(8u<<24);  // N=128
    const uint32_t IDA = (1u<<4)|(1u<<7)|(1u<<10)|( 8u<<17)|(8u<<24);  // N=64

    CPA_WAIT(0);
    asm volatile("fence.proxy.async.shared::cta;" ::: "memory");
    __syncthreads();

    uint64_t qhd = make_desc(sbase + AT_QHI);
    uint64_t qld = make_desc(sbase + AT_QLO);

    // issue S(0)
    if (wid == 0 && elect_one()) {
        uint64_t kh = make_desc(sbase + AT_KBUF);
        uint64_t kl = make_desc(sbase + AT_KBUF + 16384);
        #pragma unroll
        for (int ks = 0; ks < 4; ks++) {
            uint64_t o = ks * 2;
            mma_ss_bf16(tmem + S0, qhd + o, kh + o, IDS, ks > 0 ? 1u : 0u);
            mma_ss_bf16(tmem + S0, qhd + o, kl + o, IDS, 1u);
            mma_ss_bf16(tmem + S0, qld + o, kh + o, IDS, 1u);
        }
        TC_COMMIT(MBS);
    }

    float l = 0.f;
    int phS = 0, phA = 0;

    for (int kt = 0; kt <= qtile; kt++) {
        int sbuf = kt & 1;
        // prefetch K(kt+1)
        if (kt < qtile) {
            uint32_t kb = sbase + AT_KBUF + ((kt + 1) & 1) * 32768;
            const bf16* kh_g = g_kbf[0] + ((size_t)bh * TT + (kt + 1) * 128) * HD;
            const bf16* kl_g = g_kbf[1] + ((size_t)bh * TT + (kt + 1) * 128) * HD;
            #pragma unroll
            for (int i = 0; i < 4; i++) {
                int f = tid + i * 256;
                int r = f >> 3, c8 = f & 7;
                uint32_t so = sw128((uint32_t)(r * 128 + c8 * 16));
                cpa16(kb + so,         kh_g + (size_t)r * HD + c8 * 8);
                cpa16(kb + 16384 + so, kl_g + (size_t)r * HD + c8 * 8);
            }
            CPA_COMMIT();
        }
        // wait S(kt)
        mbar_wait(MBS, phS); phS ^= 1;
        TC_FENCE_AFTER();

        // LDTM + exp, interleaved halves
        uint32_t sr[64];
        TC_LD_X32(sr, tmem + S0 + sbuf * 128 + half * 64);
        TC_WAIT_LD();
        TC_LD_X32(sr + 32, tmem + S0 + sbuf * 128 + half * 64 + 32);

        int qg = q0 + row;
        int kbase = kt * 128 + half * 64;
        bool maskTile = (kt == qtile);
        uint32_t pw[32];
        float lacc = 0.f;
        #pragma unroll
        for (int j2 = 0; j2 < 16; j2++) {
            float s0v = __uint_as_float(sr[2*j2])   * 0.125f;
            float s1v = __uint_as_float(sr[2*j2+1]) * 0.125f;
            float p0 = __expf(s0v), p1 = __expf(s1v);
            if (maskTile) {
                if (kbase + 2*j2     > qg) p0 = 0.f;
                if (kbase + 2*j2 + 1 > qg) p1 = 0.f;
            }
            bf162 pb = __floats2bfloat162_rn(p0, p1);
            lacc += __bfloat162float(pb.x) + __bfloat162float(pb.y);
            pw[j2] = *(uint32_t*)&pb;
        }
        TC_WAIT_LD();
        #pragma unroll
        for (int j2 = 16; j2 < 32; j2++) {
            float s0v = __uint_as_float(sr[2*j2])   * 0.125f;
            float s1v = __uint_as_float(sr[2*j2+1]) * 0.125f;
            float p0 = __expf(s0v), p1 = __expf(s1v);
            if (maskTile) {
                if (kbase + 2*j2     > qg) p0 = 0.f;
                if (kbase + 2*j2 + 1 > qg) p1 = 0.f;
            }
            bf162 pb = __floats2bfloat162_rn(p0, p1);
            lacc += __bfloat162float(pb.x) + __bfloat162float(pb.y);
            pw[j2] = *(uint32_t*)&pb;
        }
        l += lacc;

        // wait AV(kt-1): frees V buf[(kt+1)&1] and P[kt&1]
        if (kt > 0) { mbar_wait(MBA, phA); phA ^= 1; }

        // prefetch V(kt+1)
        if (kt < qtile) {
            uint32_t vb = sbase + AT_VBUF + ((kt + 1) & 1) * 32768;
            const bf16* vh_g = g_vT[0] + (size_t)bh * HD * TT + (kt + 1) * 128;
            const bf16* vl_g = g_vT[1] + (size_t)bh * HD * TT + (kt + 1) * 128;
            #pragma unroll
            for (int i = 0; i < 4; i++) {
                int f = tid + i * 256;
                int d = f >> 4, c16 = f & 15;
                uint32_t byte = (uint32_t)((d >> 3) * 1024 + (c16 >> 3) * 8192 + (d & 7) * 128 + (c16 & 7) * 16);
                uint32_t so = sw128(byte);
                cpa16(vb + so,         vh_g + (size_t)d * TT + c16 * 8);
                cpa16(vb + 16384 + so, vl_g + (size_t)d * TT + c16 * 8);
            }
            CPA_COMMIT();
        }

        // store P(kt)
        TC_ST_X32(tmem + P0 + sbuf * 64 + half * 32 + ((uint32_t)(wid & 3) << 21), pw);
        TC_WAIT_ST();

        // K(kt+1) must be resident (leave V(kt+1) in flight)
        if (kt < qtile) { CPA_WAIT(1); } else { CPA_WAIT(0); }
        asm volatile("fence.proxy.async.shared::cta;" ::: "memory");
        TC_FENCE_BEFORE();
        __syncthreads();

        if (wid == 0 && elect_one()) {
            TC_FENCE_AFTER();
            if (kt < qtile) {
                uint32_t kb = sbase + AT_KBUF + ((kt + 1) & 1) * 32768;
                uint64_t kh = make_desc(kb);
                uint64_t kl = make_desc(kb + 16384);
                uint32_t sd = tmem + S0 + ((kt + 1) & 1) * 128;
                #pragma unroll
                for (int ks = 0; ks < 4; ks++) {
                    uint64_t o = ks * 2;
                    mma_ss_bf16(sd, qhd + o, kh + o, IDS, ks > 0 ? 1u : 0u);
                    mma_ss_bf16(sd, qhd + o, kl + o, IDS, 1u);
                    mma_ss_bf16(sd, qld + o, kh + o, IDS, 1u);
                }
                TC_COMMIT(MBS);
            }
            {
                uint32_t vb = sbase + AT_VBUF + sbuf * 32768;
                uint64_t vh = make_desc(vb);
                uint64_t vl = make_desc(vb + 16384);
                #pragma unroll
                for (int ks = 0; ks < 8; ks++) {
                    uint64_t vo = (uint64_t)((ks & 3) * 2 + (ks >> 2) * 512);
                    uint32_t at = tmem + P0 + sbuf * 64 + ks * 8;
                    mma_ts_bf16(tmem + O_OFF, at, vh + vo, IDA, (kt > 0 || ks > 0) ? 1u : 0u);
                    mma_ts_bf16(tmem + O_OFF, at, vl + vo, IDA, 1u);
                }
                TC_COMMIT(MBA);
            }
        }
    }
    mbar_wait(MBA, phA);
    TC_FENCE_AFTER();

    l2s[half * 128 + row] = l;
    __syncthreads();
    float inv = 1.f / (l2s[row] + l2s[128 + row]);

    uint32_t od[32];
    TC_LD_X32(od, tmem + O_OFF + half * 32);
    TC_WAIT_LD();
    int token = b * TT + q0 + row;
    bf16* ohp = g_obf[0] + (size_t)token * CC + h * HD + half * 32;
    bf16* olp = g_obf[1] + (size_t)token * CC + h * HD + half * 32;
    #pragma unroll
    for (int j = 0; j < 32; j += 4) {
        float4 v;
        v.x = __uint_as_float(od[j+0]) * inv;
        v.y = __uint_as_float(od[j+1]) * inv;
        v.z = __uint_as_float(od[j+2]) * inv;
        v.w = __uint_as_float(od[j+3]) * inv;
        uint2 hv, lv; split4(v, hv, lv);
        *(uint2*)(ohp + j) = hv; *(uint2*)(olp + j) = lv;
    }
    TC_FENCE_BEFORE();
    __syncthreads();
    if (wid == 0) { TC_RELINQ(); TC_DEALLOC(tmem, 512u); }

#else // SIMT fallback attention
    for (int qq = tid; qq < 128; qq += 256) {
        int qg = q0 + qq;
        float q[HD], o[HD];
        #pragma unroll
        for (int d = 0; d < HD; d++) {
            q[d] = (__bfloat162float(qh_g[(size_t)qq*HD+d]) + __bfloat162float(ql_g[(size_t)qq*HD+d])) * 0.125f;
            o[d] = 0.f;
        }
        float l = 0.f;
        for (int k = 0; k <= qg; k++) {
            const bf16* kh_g = g_kbf[0] + ((size_t)bh * TT + k) * HD;
            const bf16* kl_g = g_kbf[1] + ((size_t)bh * TT + k) * HD;
            float s = 0.f;
            #pragma unroll
            for (int d = 0; d < HD; d++)
                s += q[d] * (__bfloat162float(kh_g[d]) + __bfloat162float(kl_g[d]));
            float p = __expf(s);
            l += p;
            #pragma unroll
            for (int d = 0; d < HD; d++) {
                size_t vo = ((size_t)bh * HD + d) * TT + k;
                o[d] += p * (__bfloat162float(g_vT[0][vo]) + __bfloat162float(g_vT[1][vo]));
            }
        }
        float inv = 1.f / l;
        int token = b * TT + qg;
        #pragma unroll
        for (int d = 0; d < HD; d++) {
            float v = o[d] * inv;
            bf16 hv = __float2bfloat16_rn(v);
            g_obf[0][(size_t)token * CC + h * HD + d] = hv;
            g_obf[1][(size_t)token * CC + h * HD + d] = __float2bfloat16_rn(v - __bfloat162float(hv));
        }
    }
#endif
}

// ---------------- 7) router ----------------
__global__ void router_kernel(const float* __restrict__ rw, const float* __restrict__ rb,
                              const float* __restrict__ nw, const float* __restrict__ nb,
                              const float* __restrict__ noise) {
    int n = blockIdx.x;
    int w = threadIdx.x >> 5, lane = threadIdx.x & 31;
    const float* hr = g_h + (size_t)n * CC;
    const float* wr = rw + (size_t)w * CC;
    const float* wn = nw + (size_t)w * CC;
    float s1 = 0.f, s2 = 0.f;
    for (int c = lane * 4; c < CC; c += 128) {
        float4 hv = *(const float4*)(hr + c);
        float4 r4 = *(const float4*)(wr + c);
        float4 n4 = *(const float4*)(wn + c);
        s1 += hv.x*r4.x + hv.y*r4.y + hv.z*r4.z + hv.w*r4.w;
        s2 += hv.x*n4.x + hv.y*n4.y + hv.z*n4.z + hv.w*n4.w;
    }
    #pragma unroll
    for (int o = 16; o; o >>= 1) {
        s1 += __shfl_xor_sync(0xffffffffu, s1, o);
        s2 += __shfl_xor_sync(0xffffffffu, s2, o);
    }
    __shared__ float lg[8], nl[8];
    if (lane == 0) { lg[w] = s1 + rb[w]; nl[w] = s2 + nb[w]; }
    __syncthreads();
    if (threadIdx.x == 0) {
        float nv[8];
        #pragma unroll
        for (int e = 0; e < 8; e++) {
            float xn = nl[e];
            float sp = (xn > 20.f) ? xn : log1pf(expf(xn));
            nv[e] = lg[e] + noise[(size_t)n * EE + e] * sp;
        }
        int i0 = 0; float v0 = nv[0];
        #pragma unroll
        for (int e = 1; e < 8; e++) if (nv[e] > v0) { v0 = nv[e]; i0 = e; }
        float v1 = -1e30f;
        #pragma unroll
        for (int e = 0; e < 8; e++) if (e != i0 && nv[e] > v1) { v1 = nv[e]; }
        float e1 = expf(v1 - v0);
        g_g0[n] = 1.f / (1.f + e1);
        g_eid[n] = i0;
    }
}

// ---------------- 8) per-expert capacity lists ----------------
__global__ void build_idx_kernel() {
    int w = threadIdx.x >> 5, lane = threadIdx.x & 31;
    int count = 0;
    for (int base = 0; base < NTOK; base += 32) {
        int t = base + lane;
        bool p = (g_eid[t] == w);
        unsigned msk = __ballot_sync(0xffffffffu, p);
        int pos = count + __popc(msk & ((1u << lane) - 1u));
        if (p && pos < CAPX) g_idx[w * CAPX + pos] = t;
        count += __popc(msk);
    }
    int c = min(count, CAPX);
    if (lane == 0) g_cnt[w] = c;
    for (int s = c + lane; s < CAPX; s += 32) g_idx[w * CAPX + s] = NTOK;
}

// ---------------- 11) scatter ----------------
__global__ void scatter_kernel(float* __restrict__ out) {
    int e = blockIdx.x >> 10;
    int slot = blockIdx.x & (CAPX - 1);
    if (slot >= g_cnt[e]) return;
    int t = g_idx[e * CAPX + slot];
    float g = g_g0[t];
    const float* src = g_oe + ((size_t)e * CAPX + slot) * CC;
    float* dst = out + (size_t)t * CC;
    int c = threadIdx.x * 4;
    float4 s = *(const float4*)(src + c);
    float4 d = *(const float4*)(dst + c);
    d.x += g * s.x; d.y += g * s.y; d.z += g * s.z; d.w += g * s.w;
    *(float4*)(dst + c) = d;
}

// ---------------- host launcher ----------------
extern "C" void kernel_launch(void* const* d_in, const int* in_sizes, int n_in,
                              void* d_out, int out_size) {
    const float* x        = (const float*)d_in[0];
    const float* x0       = (const float*)d_in[1];
    const float* noise    = (const float*)d_in[2];
    const float* lambdas  = (const float*)d_in[3];
    const float* qkv_w    = (const float*)d_in[5];
    const float* c_proj_w = (const float*)d_in[6];
    const float* c_proj_b = (const float*)d_in[7];
    const float* router_w = (const float*)d_in[8];
    const float* router_b = (const float*)d_in[9];
    const float* noise_w  = (const float*)d_in[10];
    const float* noise_b  = (const float*)d_in[11];
    const float* ew1      = (const float*)d_in[12];
    const float* eb1      = (const float*)d_in[13];
    const float* ew2      = (const float*)d_in[14];
    const float* eb2      = (const float*)d_in[15];
    float* out = (float*)d_out;

    void *p_qkv, *p_xmix, *p_h, *p_oe, *p_idx, *p_cnt;
    void *p_abf, *p_obf, *p_hbf, *p_h1bf, *p_wqkv, *p_wcp, *p_we1, *p_we2;
    cudaGetSymbolAddress(&p_qkv,  g_qkv);
    cudaGetSymbolAddress(&p_xmix, g_xmix);
    cudaGetSymbolAddress(&p_h,    g_h);
    cudaGetSymbolAddress(&p_oe,   g_oe);
    cudaGetSymbolAddress(&p_idx,  g_idx);
    cudaGetSymbolAddress(&p_cnt,  g_cnt);
    cudaGetSymbolAddress(&p_abf,  g_abf);
    cudaGetSymbolAddress(&p_obf,  g_obf);
    cudaGetSymbolAddress(&p_hbf,  g_hbf);
    cudaGetSymbolAddress(&p_h1bf, g_h1bf);
    cudaGetSymbolAddress(&p_wqkv, g_wqkv);
    cudaGetSymbolAddress(&p_wcp,  g_wcp);
    cudaGetSymbolAddress(&p_we1,  g_we1);
    cudaGetSymbolAddress(&p_we2,  g_we2);

    bf16* abf_h  = (bf16*)p_abf;   bf16* abf_l  = abf_h  + (size_t)NTOK*CC;
    bf16* obf_h  = (bf16*)p_obf;   bf16* obf_l  = obf_h  + (size_t)NTOK*CC;
    bf16* hbf_h  = (bf16*)p_hbf;   bf16* hbf_l  = hbf_h  + (size_t)NTOK*CC;
    bf16* h1_h   = (bf16*)p_h1bf;  bf16* h1_l   = h1_h   + (size_t)EE*CAPX*HID;
    bf16* wqkv_h = (bf16*)p_wqkv;  bf16* wqkv_l = wqkv_h + (size_t)3*CC*CC;
    bf16* wcp_h  = (bf16*)p_wcp;   bf16* wcp_l  = wcp_h  + (size_t)CC*CC;
    bf16* we1_h  = (bf16*)p_we1;   bf16* we1_l  = we1_h  + (size_t)EE*HID*CC;
    bf16* we2_h  = (bf16*)p_we2;   bf16* we2_l  = we2_h  + (size_t)EE*CC*HID;

    cudaFuncSetAttribute(gemm_bf<0,false,false>, cudaFuncAttributeMaxDynamicSharedMemorySize, SMEM_TOTAL_TC);
    cudaFuncSetAttribute(gemm_bf<2,false,false>, cudaFuncAttributeMaxDynamicSharedMemorySize, SMEM_TOTAL_TC);
    cudaFuncSetAttribute(gemm_bf<3,true, true >, cudaFuncAttributeMaxDynamicSharedMemorySize, SMEM_TOTAL_TC);
    cudaFuncSetAttribute(gemm_bf<1,false,true >, cudaFuncAttributeMaxDynamicSharedMemorySize, SMEM_TOTAL_TC);
    cudaFuncSetAttribute(attn_tc, cudaFuncAttributeMaxDynamicSharedMemorySize, SMEM_ATT);

    conv_kernel<<<(3*CC*CC/4 + 255)/256, 256>>>(qkv_w,    wqkv_h, wqkv_l, (long)3*CC*CC/4);
    conv_kernel<<<(CC*CC/4 + 255)/256, 256>>>(c_proj_w, wcp_h,  wcp_l,  (long)CC*CC/4);
    conv_kernel<<<((long)EE*HID*CC/4 + 255)/256, 256>>>(ew1, we1_h, we1_l, (long)EE*HID*CC/4);
    conv_kernel<<<((long)EE*CC*HID/4 + 255)/256, 256>>>(ew2, we2_h, we2_l, (long)EE*CC*HID/4);

    mix_rms_kernel<<<NTOK, 256>>>(x, x0, lambdas);

    gemm_bf<0,false,false><<<dim3(CC/128, NTOK/128, 3), 256, SMEM_TOTAL_TC>>>(
        abf_h, abf_l, 0L, wqkv_h, wqkv_l, (long)CC*CC,
        (float*)p_qkv, nullptr, nullptr, (long)NTOK*CC,
        nullptr, 0, nullptr, nullptr, nullptr, CC, CC);

    qk_rot_kernel<<<(2 * NTOK * HH) / 8, 256>>>();
    vT_kernel<<<dim3(TT/128, 2*HH), 256>>>();

    attn_tc<<<dim3(TT/128, 2*HH), 256, SMEM_ATT>>>();

    gemm_bf<2,false,false><<<dim3(CC/128, NTOK/128, 1), 256, SMEM_TOTAL_TC>>>(
        obf_h, obf_l, 0L, wcp_h, wcp_l, 0L,
        out, nullptr, nullptr, 0L,
        c_proj_b, 0, (const float*)p_xmix, nullptr, nullptr, CC, CC);

    rms2_kernel<<<NTOK, 256>>>(out);

    router_kernel<<<NTOK, 256>>>(router_w, router_b, noise_w, noise_b, noise);
    build_idx_kernel<<<1, 256>>>();

    gemm_bf<3,true,true><<<dim3(HID/128, CAPX/128, EE), 256, SMEM_TOTAL_TC>>>(
        hbf_h, hbf_l, 0L, we1_h, we1_l, (long)HID*CC,
        nullptr, h1_h, h1_l, (long)CAPX*HID,
        eb1, HID, nullptr, (const int*)p_idx, (const int*)p_cnt, HID, CC);

    gemm_bf<1,false,true><<<dim3(CC/128, CAPX/128, EE), 256, SMEM_TOTAL_TC>>>(
        h1_h, h1_l, (long)CAPX*HID, we2_h, we2_l, (long)CC*HID,
        (float*)p_oe, nullptr, nullptr, (long)CAPX*CC,
        eb2, CC, nullptr, nullptr, (const int*)p_cnt, CC, HID);

    scatter_kernel<<<EE * CAPX, 256>>>(out);
}

// round 6
// speedup vs baseline: 11.2473x; 1.0868x over previous
#include <cuda_runtime.h>
#include <cuda_bf16.h>
#include <math.h>
#include <stdint.h>

#define NTOK 4096
#define TT   2048
#define CC   1024
#define HH   16
#define HD   64
#define EE   8
#define CAPX 1024
#define HID  4096

#if defined(__CUDA_ARCH__)
# if (__CUDA_ARCH__ >= 1000) && (defined(__CUDA_ARCH_FEAT_SM103_ALL) || defined(__CUDA_ARCH_FEAT_SM100_ALL) || defined(__CUDA_ARCH_SPECIFIC__) || defined(__CUDA_ARCH_FAMILY_SPECIFIC__))
#  define USE_TC 1
# else
#  define USE_TC 0
# endif
#else
# define USE_TC 0
#endif

typedef __nv_bfloat16 bf16;
typedef __nv_bfloat162 bf162;

// ---------------- scratch ----------------
__device__ float g_xmix[(size_t)NTOK*CC];
__device__ float g_qkv [(size_t)3*NTOK*CC];
__device__ float g_h   [(size_t)NTOK*CC];
__device__ float g_g0  [NTOK];
__device__ int   g_eid [NTOK];
__device__ int   g_idx [EE*CAPX];
__device__ int   g_cnt [EE];
__device__ bf16 g_abf [2][(size_t)NTOK*CC];
__device__ bf16 g_obf [2][(size_t)NTOK*CC];
__device__ bf16 g_hbf [2][(size_t)NTOK*CC];
__device__ bf16 g_qbf [2][(size_t)NTOK*CC];      // [bh][t][d]
__device__ bf16 g_kbf [2][(size_t)NTOK*CC];      // [bh][t][d]
__device__ bf16 g_vT  [2][(size_t)NTOK*CC];      // [bh][d][t]
__device__ bf16 g_h1bf[2][(size_t)EE*CAPX*HID];
__device__ bf16 g_wqkv[2][(size_t)3*CC*CC];
__device__ bf16 g_wcp [2][(size_t)CC*CC];
__device__ bf16 g_we1 [2][(size_t)EE*HID*CC];
__device__ bf16 g_we2 [2][(size_t)EE*CC*HID];

__constant__ float c_rotinv[16] = {
    1.0f, 0.6299605249474366f, 0.39685026299204984f, 0.25f,
    0.15749013123685915f, 0.09921256574801246f, 0.0625f, 0.03937253280921479f,
    0.024803141437003115f, 0.015625f, 0.009843133202303697f, 0.0062007853592507785f,
    0.00390625f, 0.0024607833005759242f, 0.0015501963398126947f, 0.0009765625f
};

// ---------------- helpers ----------------
__device__ __forceinline__ uint32_t smem_u32(const void* p) {
    uint32_t a;
    asm("{ .reg .u64 t; cvta.to.shared.u64 t, %1; cvt.u32.u64 %0, t; }" : "=r"(a) : "l"(p));
    return a;
}
__device__ __forceinline__ uint32_t sw128(uint32_t off) { return off ^ ((off >> 3) & 0x70); }

__device__ __forceinline__ void cpa16(uint32_t d, const void* s) {
    asm volatile("cp.async.cg.shared.global [%0], [%1], 16;" :: "r"(d), "l"(s) : "memory");
}
#define CPA_COMMIT() asm volatile("cp.async.commit_group;" ::: "memory")
#define CPA_WAIT(n)  asm volatile("cp.async.wait_group %0;" :: "n"(n) : "memory")

__device__ __forceinline__ void split4(float4 v, uint2& hv, uint2& lv) {
    bf16 h0 = __float2bfloat16_rn(v.x), h1 = __float2bfloat16_rn(v.y);
    bf16 h2 = __float2bfloat16_rn(v.z), h3 = __float2bfloat16_rn(v.w);
    bf162 hp0; hp0.x = h0; hp0.y = h1;
    bf162 hp1; hp1.x = h2; hp1.y = h3;
    bf162 lp0 = __floats2bfloat162_rn(v.x - __bfloat162float(h0), v.y - __bfloat162float(h1));
    bf162 lp1 = __floats2bfloat162_rn(v.z - __bfloat162float(h2), v.w - __bfloat162float(h3));
    hv.x = *(uint32_t*)&hp0; hv.y = *(uint32_t*)&hp1;
    lv.x = *(uint32_t*)&lp0; lv.y = *(uint32_t*)&lp1;
}

#if USE_TC
__device__ __forceinline__ uint32_t elect_one() {
    uint32_t p;
    asm volatile("{\n\t.reg .pred p;\n\telect.sync _|p, 0xFFFFFFFF;\n\tselp.b32 %0, 1, 0, p;\n\t}" : "=r"(p));
    return p;
}
#define MBAR_INIT(addr, cnt) \
    asm volatile("mbarrier.init.shared.b64 [%0], %1;" :: "r"(addr), "r"(cnt) : "memory")
__device__ __forceinline__ void mbar_wait(uint32_t addr, int phase) {
    uint32_t done = 0;
    while (!done) {
        asm volatile("{\n\t.reg .pred p;\n\t"
            "mbarrier.try_wait.parity.acquire.cta.shared::cta.b64 p, [%1], %2, 0x989680;\n\t"
            "selp.b32 %0, 1, 0, p;\n\t}" : "=r"(done) : "r"(addr), "r"(phase) : "memory");
    }
}
#define TC_ALLOC(addr, n) \
    asm volatile("tcgen05.alloc.cta_group::1.sync.aligned.shared::cta.b32 [%0], %1;" :: "r"(addr), "r"(n) : "memory")
#define TC_DEALLOC(tm, n) \
    asm volatile("tcgen05.dealloc.cta_group::1.sync.aligned.b32 %0, %1;" :: "r"(tm), "r"(n))
#define TC_RELINQ() \
    asm volatile("tcgen05.relinquish_alloc_permit.cta_group::1.sync.aligned;")
#define TC_COMMIT(mbar) \
    asm volatile("tcgen05.commit.cta_group::1.mbarrier::arrive::one.shared::cluster.b64 [%0];" :: "r"(mbar) : "memory")
#define TC_FENCE_AFTER()  asm volatile("tcgen05.fence::after_thread_sync;" ::: "memory")
#define TC_FENCE_BEFORE() asm volatile("tcgen05.fence::before_thread_sync;" ::: "memory")
#define TC_WAIT_LD()      asm volatile("tcgen05.wait::ld.sync.aligned;" ::: "memory")
#define TC_WAIT_ST()      asm volatile("tcgen05.wait::st.sync.aligned;" ::: "memory")

#define TC_LD_X32(r, a) \
    asm volatile("tcgen05.ld.sync.aligned.32x32b.x32.b32 " \
        "{%0,%1,%2,%3,%4,%5,%6,%7,%8,%9,%10,%11,%12,%13,%14,%15," \
        "%16,%17,%18,%19,%20,%21,%22,%23,%24,%25,%26,%27,%28,%29,%30,%31}, [%32];" \
        : "=r"((r)[0]),"=r"((r)[1]),"=r"((r)[2]),"=r"((r)[3]),"=r"((r)[4]),"=r"((r)[5]),"=r"((r)[6]),"=r"((r)[7]), \
          "=r"((r)[8]),"=r"((r)[9]),"=r"((r)[10]),"=r"((r)[11]),"=r"((r)[12]),"=r"((r)[13]),"=r"((r)[14]),"=r"((r)[15]), \
          "=r"((r)[16]),"=r"((r)[17]),"=r"((r)[18]),"=r"((r)[19]),"=r"((r)[20]),"=r"((r)[21]),"=r"((r)[22]),"=r"((r)[23]), \
          "=r"((r)[24]),"=r"((r)[25]),"=r"((r)[26]),"=r"((r)[27]),"=r"((r)[28]),"=r"((r)[29]),"=r"((r)[30]),"=r"((r)[31]) \
        : "r"(a))

#define TC_ST_X32(a, r) \
    asm volatile("tcgen05.st.sync.aligned.32x32b.x32.b32 [%0], " \
        "{%1,%2,%3,%4,%5,%6,%7,%8,%9,%10,%11,%12,%13,%14,%15,%16," \
        "%17,%18,%19,%20,%21,%22,%23,%24,%25,%26,%27,%28,%29,%30,%31,%32};" \
        :: "r"(a), \
           "r"((r)[0]),"r"((r)[1]),"r"((r)[2]),"r"((r)[3]),"r"((r)[4]),"r"((r)[5]),"r"((r)[6]),"r"((r)[7]), \
           "r"((r)[8]),"r"((r)[9]),"r"((r)[10]),"r"((r)[11]),"r"((r)[12]),"r"((r)[13]),"r"((r)[14]),"r"((r)[15]), \
           "r"((r)[16]),"r"((r)[17]),"r"((r)[18]),"r"((r)[19]),"r"((r)[20]),"r"((r)[21]),"r"((r)[22]),"r"((r)[23]), \
           "r"((r)[24]),"r"((r)[25]),"r"((r)[26]),"r"((r)[27]),"r"((r)[28]),"r"((r)[29]),"r"((r)[30]),"r"((r)[31]) \
        : "memory")

__device__ __forceinline__ void mma_ss_bf16(uint32_t d, uint64_t ad, uint64_t bd,
                                            uint32_t idesc, uint32_t en) {
    asm volatile("{\n\t.reg .pred p;\n\tsetp.ne.u32 p, %4, 0;\n\t"
        "tcgen05.mma.cta_group::1.kind::f16 [%0], %1, %2, %3, {%5,%5,%5,%5}, p;\n\t}"
        :: "r"(d), "l"(ad), "l"(bd), "r"(idesc), "r"(en), "r"(0u) : "memory");
}
__device__ __forceinline__ void mma_ts_bf16(uint32_t d, uint32_t a, uint64_t bd,
                                            uint32_t idesc, uint32_t en) {
    asm volatile("{\n\t.reg .pred p;\n\tsetp.ne.u32 p, %4, 0;\n\t"
        "tcgen05.mma.cta_group::1.kind::f16 [%0], [%1], %2, %3, {%5,%5,%5,%5}, p;\n\t}"
        :: "r"(d), "r"(a), "l"(bd), "r"(idesc), "r"(en), "r"(0u) : "memory");
}
__device__ __forceinline__ uint64_t make_desc(uint32_t base) {
    const uint64_t B = (uint64_t(2) << 61) | (uint64_t(1) << 46) | (uint64_t(64) << 32) | (uint64_t(1) << 16);
    return B | ((uint64_t)(base >> 4) & 0x3FFF);
}
#endif // USE_TC

// ---------------- fp32 -> hi/lo bf16 ----------------
__global__ void conv_kernel(const float* __restrict__ src, bf16* __restrict__ hi,
                            bf16* __restrict__ lo, long n4) {
    long i = (long)blockIdx.x * blockDim.x + threadIdx.x;
    if (i >= n4) return;
    float4 v = ((const float4*)src)[i];
    uint2 hv, lv; split4(v, hv, lv);
    ((uint2*)hi)[i] = hv; ((uint2*)lo)[i] = lv;
}

// ======= bf16 GEMM: 128x256 tile, 3-term hi/lo split =======
// buf layout: AH@0(16K) AL@16K BH@32K(32K) BL@64K(32K) = 96K/buf
// EPI: 0=none 1=+bias 2=+bias+resid 3=sq(relu(+bias))->bf16 hi/lo 4=scatter-out += g0*(acc+bias)
#define A_PL 16384
#define B_PL 32768
#define BUF_BYTES 98304
#define SMEM_TOTAL_TC (1024 + 2*BUF_BYTES)

template<int EPI, bool GATHER, bool SKIP>
__global__ __launch_bounds__(256)
void gemm_bf(const bf16* __restrict__ Ahi, const bf16* __restrict__ Alo, long aStride,
             const bf16* __restrict__ Bhi, const bf16* __restrict__ Blo, long bStride,
             float* __restrict__ Cf, bf16* __restrict__ Chi, bf16* __restrict__ Clo, long cStride,
             const float* __restrict__ bias, int biasStride,
             const float* __restrict__ resid,
             const int* __restrict__ rowIdx,
             const int* __restrict__ counts,
             const float* __restrict__ g0,
             int Nt, int Kd) {
    extern __shared__ char smem[];
    const int z = blockIdx.z;
    const int m0 = blockIdx.y * 128, n0 = blockIdx.x * 256;
    int cnt = 0;
    if (SKIP) { cnt = counts[z]; if (m0 >= cnt) return; }
    int tid = threadIdx.x, wid = tid >> 5, lane = tid & 31;

    const uint32_t OFF_MB = 8, OFF_RID = 64, OFF_TILE = 1024;
    int* s_rid = (int*)(smem + OFF_RID);
    if (tid < 128) {
        int r;
        if (GATHER) r = min(rowIdx[z * CAPX + m0 + tid], NTOK - 1);
        else        r = m0 + tid;
        s_rid[tid] = r;
    }
    const bf16* Ahz = Ahi + (size_t)z * aStride;
    const bf16* Alz = Alo + (size_t)z * aStride;
    const bf16* Bhz = Bhi + (size_t)z * bStride;
    const bf16* Blz = Blo + (size_t)z * bStride;

#if USE_TC
    uint32_t sbase = smem_u32(smem);
    if (tid == 0) { MBAR_INIT(sbase + OFF_MB, 1); MBAR_INIT(sbase + OFF_MB + 8, 1); }
    if (wid == 0) { TC_ALLOC(sbase + 0, 256u); }
    __syncthreads();
    uint32_t tmem = *(uint32_t*)(smem + 0);

    const uint32_t idesc = (1u << 4) | (1u << 7) | (1u << 10) | (32u << 17) | (8u << 24); // N=256

    int nchunks = Kd >> 6;
    int ph0 = 0, ph1 = 0;

    for (int c = 0; c < nchunks; c++) {
        int buf = c & 1;
        uint32_t tb = sbase + OFF_TILE + buf * BUF_BYTES;
        if (c >= 2) {
            if (buf == 0) { mbar_wait(sbase + OFF_MB, ph0); ph0 ^= 1; }
            else          { mbar_wait(sbase + OFF_MB + 8, ph1); ph1 ^= 1; }
        }
        int k0 = c * 64;
        // A: 128 rows x 64 bf16 per plane = 1024 16B lines
        #pragma unroll
        for (int i = 0; i < 4; i++) {
            int f = tid + i * 256;
            int row = f >> 3, c8 = f & 7;
            uint32_t so = sw128((uint32_t)(row * 128 + c8 * 16));
            size_t aoff = (size_t)s_rid[row] * Kd + k0 + c8 * 8;
            cpa16(tb + so,        Ahz + aoff);
            cpa16(tb + A_PL + so, Alz + aoff);
        }
        // B: 256 rows x 64 bf16 per plane = 2048 16B lines
        #pragma unroll
        for (int i = 0; i < 8; i++) {
            int f = tid + i * 256;
            int row = f >> 3, c8 = f & 7;
            uint32_t so = sw128((uint32_t)(row * 128 + c8 * 16));
            size_t boff = (size_t)(n0 + row) * Kd + k0 + c8 * 8;
            cpa16(tb + 2 * A_PL + so,        Bhz + boff);
            cpa16(tb + 2 * A_PL + B_PL + so, Blz + boff);
        }
        CPA_COMMIT();
        CPA_WAIT(0);
        asm volatile("fence.proxy.async.shared::cta;" ::: "memory");
        __syncthreads();
        if (wid == 0) {
            if (elect_one()) {
                uint64_t ah = make_desc(tb);
                uint64_t al = make_desc(tb + A_PL);
                uint64_t bh = make_desc(tb + 2 * A_PL);
                uint64_t bl = make_desc(tb + 2 * A_PL + B_PL);
                #pragma unroll
                for (int ks = 0; ks < 4; ks++) {
                    uint64_t o = ks * 2;
                    mma_ss_bf16(tmem, ah + o, bh + o, idesc, (c > 0 || ks > 0) ? 1u : 0u);
                    mma_ss_bf16(tmem, ah + o, bl + o, idesc, 1u);
                    mma_ss_bf16(tmem, al + o, bh + o, idesc, 1u);
                }
                TC_COMMIT(sbase + OFF_MB + 8 * buf);
            }
        }
    }
    mbar_wait(sbase + OFF_MB, ph0);
    mbar_wait(sbase + OFF_MB + 8, ph1);
    TC_FENCE_AFTER();

    // epilogue: warpgroup half covers 128 cols; process in two 64-col groups
    int colbase = (wid >> 2) * 128;
    int row = (wid & 3) * 32 + lane;
    int gm = m0 + row;

    int token = 0; float gg = 0.f; bool valid4 = true;
    if (EPI == 4) {
        valid4 = (gm < cnt);
        if (valid4) { token = rowIdx[z * CAPX + gm]; gg = g0[token]; }
    }

    #pragma unroll
    for (int g2 = 0; g2 < 2; g2++) {
        int co = colbase + g2 * 64;
        uint32_t dr[64];
        TC_LD_X32(dr,      tmem + co);
        TC_LD_X32(dr + 32, tmem + co + 32);
        TC_WAIT_LD();

        const float* bp = (EPI >= 1) ? (bias + (size_t)z * biasStride + n0 + co) : nullptr;
        if (EPI == 3) {
            bf16* chp = Chi + (size_t)z * cStride + (size_t)gm * Nt + n0 + co;
            bf16* clp = Clo + (size_t)z * cStride + (size_t)gm * Nt + n0 + co;
            #pragma unroll
            for (int j = 0; j < 64; j += 4) {
                float4 v;
                float t0 = __uint_as_float(dr[j+0]) + bp[j+0];
                float t1 = __uint_as_float(dr[j+1]) + bp[j+1];
                float t2 = __uint_as_float(dr[j+2]) + bp[j+2];
                float t3 = __uint_as_float(dr[j+3]) + bp[j+3];
                v.x = t0 > 0.f ? t0*t0 : 0.f; v.y = t1 > 0.f ? t1*t1 : 0.f;
                v.z = t2 > 0.f ? t2*t2 : 0.f; v.w = t3 > 0.f ? t3*t3 : 0.f;
                uint2 hv, lv; split4(v, hv, lv);
                *(uint2*)(chp + j) = hv; *(uint2*)(clp + j) = lv;
            }
        } else if (EPI == 4) {
            if (valid4) {
                float* op = Cf + (size_t)token * Nt + n0 + co;
                #pragma unroll
                for (int j = 0; j < 64; j += 4) {
                    float4 o = *(float4*)(op + j);
                    o.x += gg * (__uint_as_float(dr[j+0]) + bp[j+0]);
                    o.y += gg * (__uint_as_float(dr[j+1]) + bp[j+1]);
                    o.z += gg * (__uint_as_float(dr[j+2]) + bp[j+2]);
                    o.w += gg * (__uint_as_float(dr[j+3]) + bp[j+3]);
                    *(float4*)(op + j) = o;
                }
            }
        } else {
            const float* rp = (EPI == 2) ? (resid + (size_t)gm * Nt + n0 + co) : nullptr;
            float* cp = Cf + (size_t)z * cStride + (size_t)gm * Nt + n0 + co;
            #pragma unroll
            for (int j = 0; j < 64; j += 4) {
                float vv[4];
                #pragma unroll
                for (int q = 0; q < 4; q++) {
                    float t = __uint_as_float(dr[j + q]);
                    if (EPI == 1)      t += bp[j + q];
                    else if (EPI == 2) t += bp[j + q] + rp[j + q];
                    vv[q] = t;
                }
                float4 v4; v4.x = vv[0]; v4.y = vv[1]; v4.z = vv[2]; v4.w = vv[3];
                *(float4*)(cp + j) = v4;
            }
        }
    }

    TC_FENCE_BEFORE();
    __syncthreads();
    if (wid == 0) { TC_RELINQ(); TC_DEALLOC(tmem, 256u); }

#else  // SIMT fallback (compute_103 pass; never selected at runtime)
    float* As = (float*)(smem + OFF_TILE);
    float* Bs = (float*)(smem + OFF_TILE + 16 * 128 * 4);
    __syncthreads();
    int tm = (tid >> 4) * 8, tn = (tid & 15) * 8;
    for (int nsub = 0; nsub < 2; nsub++) {
        int n0s = n0 + nsub * 128;
        float acc[8][8];
        #pragma unroll
        for (int i = 0; i < 8; i++)
            #pragma unroll
            for (int j = 0; j < 8; j++) acc[i][j] = 0.f;
        for (int k0 = 0; k0 < Kd; k0 += 16) {
            #pragma unroll
            for (int i = 0; i < 2; i++) {
                int f = tid + i * 256;
                int row = f >> 2, c4 = (f & 3) * 4;
                #pragma unroll
                for (int q = 0; q < 4; q++) {
                    size_t ao = (size_t)s_rid[row] * Kd + k0 + c4 + q;
                    size_t bo = (size_t)(n0s + row) * Kd + k0 + c4 + q;
                    As[(c4+q)*128 + row] = __bfloat162float(Ahz[ao]) + __bfloat162float(Alz[ao]);
                    Bs[(c4+q)*128 + row] = __bfloat162float(Bhz[bo]) + __bfloat162float(Blz[bo]);
                }
            }
            __syncthreads();
            #pragma unroll
            for (int kk = 0; kk < 16; kk++) {
                float a_[8], b_[8];
                #pragma unroll
                for (int q = 0; q < 8; q++) { a_[q] = As[kk*128 + tm + q]; b_[q] = Bs[kk*128 + tn + q]; }
                #pragma unroll
                for (int i = 0; i < 8; i++)
                    #pragma unroll
                    for (int j = 0; j < 8; j++)
                        acc[i][j] += a_[i] * b_[j];
            }
            __syncthreads();
        }
        #pragma unroll
        for (int i = 0; i < 8; i++) {
            int gm = m0 + tm + i;
            #pragma unroll
            for (int j = 0; j < 8; j++) {
                float t = acc[i][j];
                int col = n0s + tn + j;
                if (EPI >= 1) t += bias[(size_t)z * biasStride + col];
                if (EPI == 2) t += resid[(size_t)gm * Nt + col];
                if (EPI == 3) {
                    t = t > 0.f ? t * t : 0.f;
                    bf16 hv = __float2bfloat16_rn(t);
                    Chi[(size_t)z * cStride + (size_t)gm * Nt + col] = hv;
                    Clo[(size_t)z * cStride + (size_t)gm * Nt + col] = __float2bfloat16_rn(t - __bfloat162float(hv));
                } else if (EPI == 4) {
                    if (gm < cnt) {
                        int token = rowIdx[z * CAPX + gm];
                        atomicAdd(&Cf[(size_t)token * Nt + col], g0[token] * t);
                    }
                } else {
                    Cf[(size_t)z * cStride + (size_t)gm * Nt + col] = t;
                }
            }
        }
    }
#endif
}

// ---------------- block reduce ----------------
__device__ __forceinline__ float blockReduceSum(float v) {
    __shared__ float sh[32];
    int lane = threadIdx.x & 31, w = threadIdx.x >> 5;
    #pragma unroll
    for (int o = 16; o; o >>= 1) v += __shfl_down_sync(0xffffffffu, v, o);
    if (lane == 0) sh[w] = v;
    __syncthreads();
    int nw = blockDim.x >> 5;
    if (w == 0) {
        v = (lane < nw) ? sh[lane] : 0.f;
        #pragma unroll
        for (int o = 16; o; o >>= 1) v += __shfl_down_sync(0xffffffffu, v, o);
        if (lane == 0) sh[0] = v;
    }
    __syncthreads();
    return sh[0];
}

// ---------------- 1) residual mix + rmsnorm ----------------
__global__ void mix_rms_kernel(const float* __restrict__ x, const float* __restrict__ x0,
                               const float* __restrict__ lambdas) {
    int row = blockIdx.x;
    float l0 = lambdas[0], l1 = lambdas[1];
    size_t off = (size_t)row * CC + threadIdx.x * 4;
    float4 a = *(const float4*)(x + off);
    float4 b = *(const float4*)(x0 + off);
    float4 v;
    v.x = l0*a.x + l1*b.x; v.y = l0*a.y + l1*b.y;
    v.z = l0*a.z + l1*b.z; v.w = l0*a.w + l1*b.w;
    *(float4*)(g_xmix + off) = v;
    float ss = v.x*v.x + v.y*v.y + v.z*v.z + v.w*v.w;
    float tot = blockReduceSum(ss);
    float sc = rsqrtf(tot * (1.0f/CC) + 1e-6f);
    float4 o; o.x = v.x*sc; o.y = v.y*sc; o.z = v.z*sc; o.w = v.w*sc;
    uint2 hv, lv; split4(o, hv, lv);
    *(uint2*)(&g_abf[0][off]) = hv;
    *(uint2*)(&g_abf[1][off]) = lv;
}

// ---------------- 6) rmsnorm of x2 ----------------
__global__ void rms2_kernel(const float* __restrict__ src) {
    int row = blockIdx.x;
    size_t off = (size_t)row * CC + threadIdx.x * 4;
    float4 v = *(const float4*)(src + off);
    float ss = v.x*v.x + v.y*v.y + v.z*v.z + v.w*v.w;
    float tot = blockReduceSum(ss);
    float sc = rsqrtf(tot * (1.0f/CC) + 1e-6f);
    float4 o; o.x = v.x*sc; o.y = v.y*sc; o.z = v.z*sc; o.w = v.w*sc;
    *(float4*)(g_h + off) = o;
    uint2 hv, lv; split4(o, hv, lv);
    *(uint2*)(&g_hbf[0][off]) = hv;
    *(uint2*)(&g_hbf[1][off]) = lv;
}

// ---------------- 3) per-head rmsnorm + rotary ----------------
__global__ void qk_rot_kernel() {
    int gw = blockIdx.x * (blockDim.x >> 5) + (threadIdx.x >> 5);
    int lane = threadIdx.x & 31;
    int qk = gw >> 16;
    int r  = gw & 65535;
    int n  = r >> 4;
    int h  = r & 15;
    const float* p = g_qkv + (size_t)qk * NTOK * CC + (size_t)n * CC + h * HD;
    float x1 = p[lane], x2 = p[lane + 32];
    float ss = x1 * x1 + x2 * x2;
    #pragma unroll
    for (int o = 16; o; o >>= 1) ss += __shfl_xor_sync(0xffffffffu, ss, o);
    float sc = rsqrtf(ss * (1.0f/HD) + 1e-6f);
    x1 *= sc; x2 *= sc;
    int b = n >> 11, t = n & (TT - 1);
    float invj = (lane < 16) ? c_rotinv[lane] : 0.f;
    float th = (float)t * invj;
    float c = cosf(th), s = sinf(th);
    float y1 =  x1 * c + x2 * s;
    float y2 = -x1 * s + x2 * c;
    size_t base = ((size_t)(b * HH + h) * TT + t) * HD;
    bf16* hi = qk ? g_kbf[0] : g_qbf[0];
    bf16* lo = qk ? g_kbf[1] : g_qbf[1];
    bf16 h1 = __float2bfloat16_rn(y1), h2 = __float2bfloat16_rn(y2);
    hi[base + lane]      = h1;
    hi[base + lane + 32] = h2;
    lo[base + lane]      = __float2bfloat16_rn(y1 - __bfloat162float(h1));
    lo[base + lane + 32] = __float2bfloat16_rn(y2 - __bfloat162float(h2));
}

// ---------------- 3b) V transpose+convert ----------------
__global__ __launch_bounds__(256) void vT_kernel() {
    __shared__ float s[128][65];
    int tblk = blockIdx.x, bh = blockIdx.y;
    int b = bh >> 4, h = bh & 15;
    int t0 = tblk * 128;
    const float* vsrc = g_qkv + (size_t)2 * NTOK * CC;
    #pragma unroll
    for (int i = 0; i < 32; i++) {
        int f = threadIdx.x + i * 256;
        int t = f >> 6, d = f & 63;
        s[t][d] = vsrc[((size_t)(b * TT + t0 + t)) * CC + h * HD + d];
    }
    __syncthreads();
    #pragma unroll
    for (int i = 0; i < 32; i++) {
        int f = threadIdx.x + i * 256;
        int d = f >> 7, t = f & 127;
        float v = s[t][d];
        bf16 hv = __float2bfloat16_rn(v);
        size_t off = ((size_t)(bh * HD + d)) * TT + t0 + t;
        g_vT[0][off] = hv;
        g_vT[1][off] = __float2bfloat16_rn(v - __bfloat162float(hv));
    }
}

// ---------------- 4) pipelined tensor-core causal attention ----------------
#define AT_QHI 2048
#define AT_QLO (AT_QHI + 16384)
#define AT_KBUF 34816
#define AT_VBUF (AT_KBUF + 2*32768)
#define SMEM_ATT (AT_VBUF + 2*32768)
#define AT_L2 128

__global__ __launch_bounds__(256) void attn_tc() {
    extern __shared__ char smem[];
    int qtile = gridDim.x - 1 - blockIdx.x;   // LPT: biggest CTAs first
    int bh = blockIdx.y;
    int b = bh >> 4, h = bh & 15;
    int q0 = qtile * 128;
    int tid = threadIdx.x, wid = tid >> 5, lane = tid & 31;
    int half = wid >> 2;
    int row = (wid & 3) * 32 + lane;

    const bf16* qh_g = g_qbf[0] + ((size_t)bh * TT + q0) * HD;
    const bf16* ql_g = g_qbf[1] + ((size_t)bh * TT + q0) * HD;

#if USE_TC
    uint32_t sbase = smem_u32(smem);
    const uint32_t MBS = sbase + 8, MBA = sbase + 16;
    float* l2s = (float*)(smem + AT_L2);
    if (tid == 0) { MBAR_INIT(MBS, 1); MBAR_INIT(MBA, 1); }

    {
        const bf16* kh_g = g_kbf[0] + ((size_t)bh * TT) * HD;
        const bf16* kl_g = g_kbf[1] + ((size_t)bh * TT) * HD;
        const bf16* vh_g = g_vT[0] + (size_t)bh * HD * TT;
        const bf16* vl_g = g_vT[1] + (size_t)bh * HD * TT;
        #pragma unroll
        for (int i = 0; i < 4; i++) {
            int f = tid + i * 256;
            int r = f >> 3, c8 = f & 7;
            uint32_t so = sw128((uint32_t)(r * 128 + c8 * 16));
            cpa16(sbase + AT_QHI + so, qh_g + (size_t)r * HD + c8 * 8);
            cpa16(sbase + AT_QLO + so, ql_g + (size_t)r * HD + c8 * 8);
            cpa16(sbase + AT_KBUF + so,         kh_g + (size_t)r * HD + c8 * 8);
            cpa16(sbase + AT_KBUF + 16384 + so, kl_g + (size_t)r * HD + c8 * 8);
        }
        #pragma unroll
        for (int i = 0; i < 4; i++) {
            int f = tid + i * 256;
            int d = f >> 4, c16 = f & 15;
            uint32_t byte = (uint32_t)((d >> 3) * 1024 + (c16 >> 3) * 8192 + (d & 7) * 128 + (c16 & 7) * 16);
            uint32_t so = sw128(byte);
            cpa16(sbase + AT_VBUF + so,         vh_g + (size_t)d * TT + c16 * 8);
            cpa16(sbase + AT_VBUF + 16384 + so, vl_g + (size_t)d * TT + c16 * 8);
        }
        CPA_COMMIT();
    }
    if (wid == 0) { TC_ALLOC(sbase + 0, 512u); }
    __syncthreads();
    uint32_t tmem = *(uint32_t*)(smem + 0);
    const uint32_t S0 = 0, O_OFF = 256, P0 = 320;
    const uint32_t IDS = (1u<<4)|(1u<<7)|(1u<<10)|(16u<<17)|(8u<<24);  // N=128
    const uint32_t IDA = (1u<<4)|(1u<<7)|(1u<<10)|( 8u<<17)|(8u<<24);  // N=64

    CPA_WAIT(0);
    asm volatile("fence.proxy.async.shared::cta;" ::: "memory");
    __syncthreads();

    uint64_t qhd = make_desc(sbase + AT_QHI);
    uint64_t qld = make_desc(sbase + AT_QLO);

    if (wid == 0 && elect_one()) {
        uint64_t kh = make_desc(sbase + AT_KBUF);
        uint64_t kl = make_desc(sbase + AT_KBUF + 16384);
        #pragma unroll
        for (int ks = 0; ks < 4; ks++) {
            uint64_t o = ks * 2;
            mma_ss_bf16(tmem + S0, qhd + o, kh + o, IDS, ks > 0 ? 1u : 0u);
            mma_ss_bf16(tmem + S0, qhd + o, kl + o, IDS, 1u);
            mma_ss_bf16(tmem + S0, qld + o, kh + o, IDS, 1u);
        }
        TC_COMMIT(MBS);
    }

    float l = 0.f;
    int phS = 0, phA = 0;

    for (int kt = 0; kt <= qtile; kt++) {
        int sbuf = kt & 1;
        if (kt < qtile) {
            uint32_t kb = sbase + AT_KBUF + ((kt + 1) & 1) * 32768;
            const bf16* kh_g = g_kbf[0] + ((size_t)bh * TT + (kt + 1) * 128) * HD;
            const bf16* kl_g = g_kbf[1] + ((size_t)bh * TT + (kt + 1) * 128) * HD;
            #pragma unroll
            for (int i = 0; i < 4; i++) {
                int f = tid + i * 256;
                int r = f >> 3, c8 = f & 7;
                uint32_t so = sw128((uint32_t)(r * 128 + c8 * 16));
                cpa16(kb + so,         kh_g + (size_t)r * HD + c8 * 8);
                cpa16(kb + 16384 + so, kl_g + (size_t)r * HD + c8 * 8);
            }
            CPA_COMMIT();
        }
        mbar_wait(MBS, phS); phS ^= 1;
        TC_FENCE_AFTER();

        uint32_t sr[64];
        TC_LD_X32(sr, tmem + S0 + sbuf * 128 + half * 64);
        TC_WAIT_LD();
        TC_LD_X32(sr + 32, tmem + S0 + sbuf * 128 + half * 64 + 32);

        int qg = q0 + row;
        int kbase = kt * 128 + half * 64;
        bool maskTile = (kt == qtile);
        uint32_t pw[32];
        float lacc = 0.f;
        #pragma unroll
        for (int j2 = 0; j2 < 16; j2++) {
            float s0v = __uint_as_float(sr[2*j2])   * 0.125f;
            float s1v = __uint_as_float(sr[2*j2+1]) * 0.125f;
            float p0 = __expf(s0v), p1 = __expf(s1v);
            if (maskTile) {
                if (kbase + 2*j2     > qg) p0 = 0.f;
                if (kbase + 2*j2 + 1 > qg) p1 = 0.f;
            }
            bf162 pb = __floats2bfloat162_rn(p0, p1);
            lacc += __bfloat162float(pb.x) + __bfloat162float(pb.y);
            pw[j2] = *(uint32_t*)&pb;
        }
        TC_WAIT_LD();
        #pragma unroll
        for (int j2 = 16; j2 < 32; j2++) {
            float s0v = __uint_as_float(sr[2*j2])   * 0.125f;
            float s1v = __uint_as_float(sr[2*j2+1]) * 0.125f;
            float p0 = __expf(s0v), p1 = __expf(s1v);
            if (maskTile) {
                if (kbase + 2*j2     > qg) p0 = 0.f;
                if (kbase + 2*j2 + 1 > qg) p1 = 0.f;
            }
            bf162 pb = __floats2bfloat162_rn(p0, p1);
            lacc += __bfloat162float(pb.x) + __bfloat162float(pb.y);
            pw[j2] = *(uint32_t*)&pb;
        }
        l += lacc;

        if (kt > 0) { mbar_wait(MBA, phA); phA ^= 1; }

        if (kt < qtile) {
            uint32_t vb = sbase + AT_VBUF + ((kt + 1) & 1) * 32768;
            const bf16* vh_g = g_vT[0] + (size_t)bh * HD * TT + (kt + 1) * 128;
            const bf16* vl_g = g_vT[1] + (size_t)bh * HD * TT + (kt + 1) * 128;
            #pragma unroll
            for (int i = 0; i < 4; i++) {
                int f = tid + i * 256;
                int d = f >> 4, c16 = f & 15;
                uint32_t byte = (uint32_t)((d >> 3) * 1024 + (c16 >> 3) * 8192 + (d & 7) * 128 + (c16 & 7) * 16);
                uint32_t so = sw128(byte);
                cpa16(vb + so,         vh_g + (size_t)d * TT + c16 * 8);
                cpa16(vb + 16384 + so, vl_g + (size_t)d * TT + c16 * 8);
            }
            CPA_COMMIT();
        }

        TC_ST_X32(tmem + P0 + sbuf * 64 + half * 32 + ((uint32_t)(wid & 3) << 21), pw);
        TC_WAIT_ST();

        if (kt < qtile) { CPA_WAIT(1); } else { CPA_WAIT(0); }
        asm volatile("fence.proxy.async.shared::cta;" ::: "memory");
        TC_FENCE_BEFORE();
        __syncthreads();

        if (wid == 0 && elect_one()) {
            TC_FENCE_AFTER();
            if (kt < qtile) {
                uint32_t kb = sbase + AT_KBUF + ((kt + 1) & 1) * 32768;
                uint64_t kh = make_desc(kb);
                uint64_t kl = make_desc(kb + 16384);
                uint32_t sd = tmem + S0 + ((kt + 1) & 1) * 128;
                #pragma unroll
                for (int ks = 0; ks < 4; ks++) {
                    uint64_t o = ks * 2;
                    mma_ss_bf16(sd, qhd + o, kh + o, IDS, ks > 0 ? 1u : 0u);
                    mma_ss_bf16(sd, qhd + o, kl + o, IDS, 1u);
                    mma_ss_bf16(sd, qld + o, kh + o, IDS, 1u);
                }
                TC_COMMIT(MBS);
            }
            {
                uint32_t vb = sbase + AT_VBUF + sbuf * 32768;
                uint64_t vh = make_desc(vb);
                uint64_t vl = make_desc(vb + 16384);
                #pragma unroll
                for (int ks = 0; ks < 8; ks++) {
                    uint64_t vo = (uint64_t)((ks & 3) * 2 + (ks >> 2) * 512);
                    uint32_t at = tmem + P0 + sbuf * 64 + ks * 8;
                    mma_ts_bf16(tmem + O_OFF, at, vh + vo, IDA, (kt > 0 || ks > 0) ? 1u : 0u);
                    mma_ts_bf16(tmem + O_OFF, at, vl + vo, IDA, 1u);
                }
                TC_COMMIT(MBA);
            }
        }
    }
    mbar_wait(MBA, phA);
    TC_FENCE_AFTER();

    l2s[half * 128 + row] = l;
    __syncthreads();
    float inv = 1.f / (l2s[row] + l2s[128 + row]);

    uint32_t od[32];
    TC_LD_X32(od, tmem + O_OFF + half * 32);
    TC_WAIT_LD();
    int token = b * TT + q0 + row;
    bf16* ohp = g_obf[0] + (size_t)token * CC + h * HD + half * 32;
    bf16* olp = g_obf[1] + (size_t)token * CC + h * HD + half * 32;
    #pragma unroll
    for (int j = 0; j < 32; j += 4) {
        float4 v;
        v.x = __uint_as_float(od[j+0]) * inv;
        v.y = __uint_as_float(od[j+1]) * inv;
        v.z = __uint_as_float(od[j+2]) * inv;
        v.w = __uint_as_float(od[j+3]) * inv;
        uint2 hv, lv; split4(v, hv, lv);
        *(uint2*)(ohp + j) = hv; *(uint2*)(olp + j) = lv;
    }
    TC_FENCE_BEFORE();
    __syncthreads();
    if (wid == 0) { TC_RELINQ(); TC_DEALLOC(tmem, 512u); }

#else // SIMT fallback attention
    for (int qq = tid; qq < 128; qq += 256) {
        int qg = q0 + qq;
        float q[HD], o[HD];
        #pragma unroll
        for (int d = 0; d < HD; d++) {
            q[d] = (__bfloat162float(qh_g[(size_t)qq*HD+d]) + __bfloat162float(ql_g[(size_t)qq*HD+d])) * 0.125f;
            o[d] = 0.f;
        }
        float l = 0.f;
        for (int k = 0; k <= qg; k++) {
            const bf16* kh_g = g_kbf[0] + ((size_t)bh * TT + k) * HD;
            const bf16* kl_g = g_kbf[1] + ((size_t)bh * TT + k) * HD;
            float s = 0.f;
            #pragma unroll
            for (int d = 0; d < HD; d++)
                s += q[d] * (__bfloat162float(kh_g[d]) + __bfloat162float(kl_g[d]));
            float p = __expf(s);
            l += p;
            #pragma unroll
            for (int d = 0; d < HD; d++) {
                size_t vo = ((size_t)bh * HD + d) * TT + k;
                o[d] += p * (__bfloat162float(g_vT[0][vo]) + __bfloat162float(g_vT[1][vo]));
            }
        }
        float inv = 1.f / l;
        int token = b * TT + qg;
        #pragma unroll
        for (int d = 0; d < HD; d++) {
            float v = o[d] * inv;
            bf16 hv = __float2bfloat16_rn(v);
            g_obf[0][(size_t)token * CC + h * HD + d] = hv;
            g_obf[1][(size_t)token * CC + h * HD + d] = __float2bfloat16_rn(v - __bfloat162float(hv));
        }
    }
#endif
}

// ---------------- 7) router ----------------
__global__ void router_kernel(const float* __restrict__ rw, const float* __restrict__ rb,
                              const float* __restrict__ nw, const float* __restrict__ nb,
                              const float* __restrict__ noise) {
    int n = blockIdx.x;
    int w = threadIdx.x >> 5, lane = threadIdx.x & 31;
    const float* hr = g_h + (size_t)n * CC;
    const float* wr = rw + (size_t)w * CC;
    const float* wn = nw + (size_t)w * CC;
    float s1 = 0.f, s2 = 0.f;
    for (int c = lane * 4; c < CC; c += 128) {
        float4 hv = *(const float4*)(hr + c);
        float4 r4 = *(const float4*)(wr + c);
        float4 n4 = *(const float4*)(wn + c);
        s1 += hv.x*r4.x + hv.y*r4.y + hv.z*r4.z + hv.w*r4.w;
        s2 += hv.x*n4.x + hv.y*n4.y + hv.z*n4.z + hv.w*n4.w;
    }
    #pragma unroll
    for (int o = 16; o; o >>= 1) {
        s1 += __shfl_xor_sync(0xffffffffu, s1, o);
        s2 += __shfl_xor_sync(0xffffffffu, s2, o);
    }
    __shared__ float lg[8], nl[8];
    if (lane == 0) { lg[w] = s1 + rb[w]; nl[w] = s2 + nb[w]; }
    __syncthreads();
    if (threadIdx.x == 0) {
        float nv[8];
        #pragma unroll
        for (int e = 0; e < 8; e++) {
            float xn = nl[e];
            float sp = (xn > 20.f) ? xn : log1pf(expf(xn));
            nv[e] = lg[e] + noise[(size_t)n * EE + e] * sp;
        }
        int i0 = 0; float v0 = nv[0];
        #pragma unroll
        for (int e = 1; e < 8; e++) if (nv[e] > v0) { v0 = nv[e]; i0 = e; }
        float v1 = -1e30f;
        #pragma unroll
        for (int e = 0; e < 8; e++) if (e != i0 && nv[e] > v1) { v1 = nv[e]; }
        float e1 = expf(v1 - v0);
        g_g0[n] = 1.f / (1.f + e1);
        g_eid[n] = i0;
    }
}

// ---------------- 8) per-expert capacity lists ----------------
__global__ void build_idx_kernel() {
    int w = threadIdx.x >> 5, lane = threadIdx.x & 31;
    int count = 0;
    for (int base = 0; base < NTOK; base += 32) {
        int t = base + lane;
        bool p = (g_eid[t] == w);
        unsigned msk = __ballot_sync(0xffffffffu, p);
        int pos = count + __popc(msk & ((1u << lane) - 1u));
        if (p && pos < CAPX) g_idx[w * CAPX + pos] = t;
        count += __popc(msk);
    }
    int c = min(count, CAPX);
    if (lane == 0) g_cnt[w] = c;
    for (int s = c + lane; s < CAPX; s += 32) g_idx[w * CAPX + s] = NTOK;
}

// ---------------- host launcher ----------------
extern "C" void kernel_launch(void* const* d_in, const int* in_sizes, int n_in,
                              void* d_out, int out_size) {
    const float* x        = (const float*)d_in[0];
    const float* x0       = (const float*)d_in[1];
    const float* noise    = (const float*)d_in[2];
    const float* lambdas  = (const float*)d_in[3];
    const float* qkv_w    = (const float*)d_in[5];
    const float* c_proj_w = (const float*)d_in[6];
    const float* c_proj_b = (const float*)d_in[7];
    const float* router_w = (const float*)d_in[8];
    const float* router_b = (const float*)d_in[9];
    const float* noise_w  = (const float*)d_in[10];
    const float* noise_b  = (const float*)d_in[11];
    const float* ew1      = (const float*)d_in[12];
    const float* eb1      = (const float*)d_in[13];
    const float* ew2      = (const float*)d_in[14];
    const float* eb2      = (const float*)d_in[15];
    float* out = (float*)d_out;

    void *p_qkv, *p_xmix, *p_h, *p_idx, *p_cnt, *p_g0;
    void *p_abf, *p_obf, *p_hbf, *p_h1bf, *p_wqkv, *p_wcp, *p_we1, *p_we2;
    cudaGetSymbolAddress(&p_qkv,  g_qkv);
    cudaGetSymbolAddress(&p_xmix, g_xmix);
    cudaGetSymbolAddress(&p_h,    g_h);
    cudaGetSymbolAddress(&p_idx,  g_idx);
    cudaGetSymbolAddress(&p_cnt,  g_cnt);
    cudaGetSymbolAddress(&p_g0,   g_g0);
    cudaGetSymbolAddress(&p_abf,  g_abf);
    cudaGetSymbolAddress(&p_obf,  g_obf);
    cudaGetSymbolAddress(&p_hbf,  g_hbf);
    cudaGetSymbolAddress(&p_h1bf, g_h1bf);
    cudaGetSymbolAddress(&p_wqkv, g_wqkv);
    cudaGetSymbolAddress(&p_wcp,  g_wcp);
    cudaGetSymbolAddress(&p_we1,  g_we1);
    cudaGetSymbolAddress(&p_we2,  g_we2);

    bf16* abf_h  = (bf16*)p_abf;   bf16* abf_l  = abf_h  + (size_t)NTOK*CC;
    bf16* obf_h  = (bf16*)p_obf;   bf16* obf_l  = obf_h  + (size_t)NTOK*CC;
    bf16* hbf_h  = (bf16*)p_hbf;   bf16* hbf_l  = hbf_h  + (size_t)NTOK*CC;
    bf16* h1_h   = (bf16*)p_h1bf;  bf16* h1_l   = h1_h   + (size_t)EE*CAPX*HID;
    bf16* wqkv_h = (bf16*)p_wqkv;  bf16* wqkv_l = wqkv_h + (size_t)3*CC*CC;
    bf16* wcp_h  = (bf16*)p_wcp;   bf16* wcp_l  = wcp_h  + (size_t)CC*CC;
    bf16* we1_h  = (bf16*)p_we1;   bf16* we1_l  = we1_h  + (size_t)EE*HID*CC;
    bf16* we2_h  = (bf16*)p_we2;   bf16* we2_l  = we2_h  + (size_t)EE*CC*HID;

    cudaFuncSetAttribute(gemm_bf<0,false,false>, cudaFuncAttributeMaxDynamicSharedMemorySize, SMEM_TOTAL_TC);
    cudaFuncSetAttribute(gemm_bf<2,false,false>, cudaFuncAttributeMaxDynamicSharedMemorySize, SMEM_TOTAL_TC);
    cudaFuncSetAttribute(gemm_bf<3,true, true >, cudaFuncAttributeMaxDynamicSharedMemorySize, SMEM_TOTAL_TC);
    cudaFuncSetAttribute(gemm_bf<4,false,true >, cudaFuncAttributeMaxDynamicSharedMemorySize, SMEM_TOTAL_TC);
    cudaFuncSetAttribute(attn_tc, cudaFuncAttributeMaxDynamicSharedMemorySize, SMEM_ATT);

    conv_kernel<<<(3*CC*CC/4 + 255)/256, 256>>>(qkv_w,    wqkv_h, wqkv_l, (long)3*CC*CC/4);
    conv_kernel<<<(CC*CC/4 + 255)/256, 256>>>(c_proj_w, wcp_h,  wcp_l,  (long)CC*CC/4);
    conv_kernel<<<((long)EE*HID*CC/4 + 255)/256, 256>>>(ew1, we1_h, we1_l, (long)EE*HID*CC/4);
    conv_kernel<<<((long)EE*CC*HID/4 + 255)/256, 256>>>(ew2, we2_h, we2_l, (long)EE*CC*HID/4);

    mix_rms_kernel<<<NTOK, 256>>>(x, x0, lambdas);

    // 2) qkv = a @ qkv_w^T  (N-tile 256)
    gemm_bf<0,false,false><<<dim3(CC/256, NTOK/128, 3), 256, SMEM_TOTAL_TC>>>(
        abf_h, abf_l, 0L, wqkv_h, wqkv_l, (long)CC*CC,
        (float*)p_qkv, nullptr, nullptr, (long)NTOK*CC,
        nullptr, 0, nullptr, nullptr, nullptr, nullptr, CC, CC);

    qk_rot_kernel<<<(2 * NTOK * HH) / 8, 256>>>();
    vT_kernel<<<dim3(TT/128, 2*HH), 256>>>();

    attn_tc<<<dim3(TT/128, 2*HH), 256, SMEM_ATT>>>();

    // 5) x2 = xmix + o @ c_proj_w^T + b
    gemm_bf<2,false,false><<<dim3(CC/256, NTOK/128, 1), 256, SMEM_TOTAL_TC>>>(
        obf_h, obf_l, 0L, wcp_h, wcp_l, 0L,
        out, nullptr, nullptr, 0L,
        c_proj_b, 0, (const float*)p_xmix, nullptr, nullptr, nullptr, CC, CC);

    rms2_kernel<<<NTOK, 256>>>(out);

    router_kernel<<<NTOK, 256>>>(router_w, router_b, noise_w, noise_b, noise);
    build_idx_kernel<<<1, 256>>>();

    // 9) h1 = sq(relu(gather(h) @ ew1^T + eb1))
    gemm_bf<3,true,true><<<dim3(HID/256, CAPX/128, EE), 256, SMEM_TOTAL_TC>>>(
        hbf_h, hbf_l, 0L, we1_h, we1_l, (long)HID*CC,
        nullptr, h1_h, h1_l, (long)CAPX*HID,
        eb1, HID, nullptr, (const int*)p_idx, (const int*)p_cnt, nullptr, HID, CC);

    // 10) out[token] += g0 * (h1 @ ew2^T + eb2)   (fused scatter epilogue)
    gemm_bf<4,false,true><<<dim3(CC/256, CAPX/128, EE), 256, SMEM_TOTAL_TC>>>(
        h1_h, h1_l, (long)CAPX*HID, we2_h, we2_l, (long)CC*HID,
        out, nullptr, nullptr, 0L,
        eb2, CC, nullptr, (const int*)p_idx, (const int*)p_cnt, (const float*)p_g0, CC, HID);
}

// round 7
// speedup vs baseline: 12.1850x; 1.0834x over previous
#include <cuda_runtime.h>
#include <cuda_bf16.h>
#include <math.h>
#include <stdint.h>

#define NTOK 4096
#define TT   2048
#define CC   1024
#define HH   16
#define HD   64
#define EE   8
#define CAPX 1024
#define HID  4096

#if defined(__CUDA_ARCH__)
# if (__CUDA_ARCH__ >= 1000) && (defined(__CUDA_ARCH_FEAT_SM103_ALL) || defined(__CUDA_ARCH_FEAT_SM100_ALL) || defined(__CUDA_ARCH_SPECIFIC__) || defined(__CUDA_ARCH_FAMILY_SPECIFIC__))
#  define USE_TC 1
# else
#  define USE_TC 0
# endif
#else
# define USE_TC 0
#endif

typedef __nv_bfloat16 bf16;
typedef __nv_bfloat162 bf162;

// ---------------- scratch ----------------
__device__ float g_xmix[(size_t)NTOK*CC];
__device__ float g_qkv [(size_t)3*NTOK*CC];
__device__ float g_h   [(size_t)NTOK*CC];
__device__ float g_g0  [NTOK];
__device__ int   g_eid [NTOK];
__device__ int   g_idx [EE*CAPX];
__device__ int   g_cnt [EE];
__device__ bf16 g_abf [2][(size_t)NTOK*CC];
__device__ bf16 g_obf [2][(size_t)NTOK*CC];
__device__ bf16 g_hbf [2][(size_t)NTOK*CC];
__device__ bf16 g_qbf [2][(size_t)NTOK*CC];      // [bh][t][d]
__device__ bf16 g_kbf [2][(size_t)NTOK*CC];      // [bh][t][d]
__device__ bf16 g_vT  [2][(size_t)NTOK*CC];      // [bh][d][t]
__device__ bf16 g_h1bf[2][(size_t)EE*CAPX*HID];
__device__ bf16 g_wqkv[2][(size_t)3*CC*CC];
__device__ bf16 g_wcp [2][(size_t)CC*CC];
__device__ bf16 g_we1 [2][(size_t)EE*HID*CC];
__device__ bf16 g_we2 [2][(size_t)EE*CC*HID];

__constant__ float c_rotinv[16] = {
    1.0f, 0.6299605249474366f, 0.39685026299204984f, 0.25f,
    0.15749013123685915f, 0.09921256574801246f, 0.0625f, 0.03937253280921479f,
    0.024803141437003115f, 0.015625f, 0.009843133202303697f, 0.0062007853592507785f,
    0.00390625f, 0.0024607833005759242f, 0.0015501963398126947f, 0.0009765625f
};

// ---------------- helpers ----------------
__device__ __forceinline__ uint32_t smem_u32(const void* p) {
    uint32_t a;
    asm("{ .reg .u64 t; cvta.to.shared.u64 t, %1; cvt.u32.u64 %0, t; }" : "=r"(a) : "l"(p));
    return a;
}
__device__ __forceinline__ uint32_t sw128(uint32_t off) { return off ^ ((off >> 3) & 0x70); }

__device__ __forceinline__ void cpa16(uint32_t d, const void* s) {
    asm volatile("cp.async.cg.shared.global [%0], [%1], 16;" :: "r"(d), "l"(s) : "memory");
}
#define CPA_COMMIT() asm volatile("cp.async.commit_group;" ::: "memory")
#define CPA_WAIT(n)  asm volatile("cp.async.wait_group %0;" :: "n"(n) : "memory")

__device__ __forceinline__ void split4(float4 v, uint2& hv, uint2& lv) {
    bf16 h0 = __float2bfloat16_rn(v.x), h1 = __float2bfloat16_rn(v.y);
    bf16 h2 = __float2bfloat16_rn(v.z), h3 = __float2bfloat16_rn(v.w);
    bf162 hp0; hp0.x = h0; hp0.y = h1;
    bf162 hp1; hp1.x = h2; hp1.y = h3;
    bf162 lp0 = __floats2bfloat162_rn(v.x - __bfloat162float(h0), v.y - __bfloat162float(h1));
    bf162 lp1 = __floats2bfloat162_rn(v.z - __bfloat162float(h2), v.w - __bfloat162float(h3));
    hv.x = *(uint32_t*)&hp0; hv.y = *(uint32_t*)&hp1;
    lv.x = *(uint32_t*)&lp0; lv.y = *(uint32_t*)&lp1;
}

#if USE_TC
__device__ __forceinline__ uint32_t elect_one() {
    uint32_t p;
    asm volatile("{\n\t.reg .pred p;\n\telect.sync _|p, 0xFFFFFFFF;\n\tselp.b32 %0, 1, 0, p;\n\t}" : "=r"(p));
    return p;
}
#define MBAR_INIT(addr, cnt) \
    asm volatile("mbarrier.init.shared.b64 [%0], %1;" :: "r"(addr), "r"(cnt) : "memory")
__device__ __forceinline__ void mbar_wait(uint32_t addr, int phase) {
    uint32_t done = 0;
    while (!done) {
        asm volatile("{\n\t.reg .pred p;\n\t"
            "mbarrier.try_wait.parity.acquire.cta.shared::cta.b64 p, [%1], %2, 0x989680;\n\t"
            "selp.b32 %0, 1, 0, p;\n\t}" : "=r"(done) : "r"(addr), "r"(phase) : "memory");
    }
}
#define TC_ALLOC(addr, n) \
    asm volatile("tcgen05.alloc.cta_group::1.sync.aligned.shared::cta.b32 [%0], %1;" :: "r"(addr), "r"(n) : "memory")
#define TC_DEALLOC(tm, n) \
    asm volatile("tcgen05.dealloc.cta_group::1.sync.aligned.b32 %0, %1;" :: "r"(tm), "r"(n))
#define TC_RELINQ() \
    asm volatile("tcgen05.relinquish_alloc_permit.cta_group::1.sync.aligned;")
#define TC_COMMIT(mbar) \
    asm volatile("tcgen05.commit.cta_group::1.mbarrier::arrive::one.shared::cluster.b64 [%0];" :: "r"(mbar) : "memory")
#define TC_FENCE_AFTER()  asm volatile("tcgen05.fence::after_thread_sync;" ::: "memory")
#define TC_FENCE_BEFORE() asm volatile("tcgen05.fence::before_thread_sync;" ::: "memory")
#define TC_WAIT_LD()      asm volatile("tcgen05.wait::ld.sync.aligned;" ::: "memory")
#define TC_WAIT_ST()      asm volatile("tcgen05.wait::st.sync.aligned;" ::: "memory")

#define TC_LD_X32(r, a) \
    asm volatile("tcgen05.ld.sync.aligned.32x32b.x32.b32 " \
        "{%0,%1,%2,%3,%4,%5,%6,%7,%8,%9,%10,%11,%12,%13,%14,%15," \
        "%16,%17,%18,%19,%20,%21,%22,%23,%24,%25,%26,%27,%28,%29,%30,%31}, [%32];" \
        : "=r"((r)[0]),"=r"((r)[1]),"=r"((r)[2]),"=r"((r)[3]),"=r"((r)[4]),"=r"((r)[5]),"=r"((r)[6]),"=r"((r)[7]), \
          "=r"((r)[8]),"=r"((r)[9]),"=r"((r)[10]),"=r"((r)[11]),"=r"((r)[12]),"=r"((r)[13]),"=r"((r)[14]),"=r"((r)[15]), \
          "=r"((r)[16]),"=r"((r)[17]),"=r"((r)[18]),"=r"((r)[19]),"=r"((r)[20]),"=r"((r)[21]),"=r"((r)[22]),"=r"((r)[23]), \
          "=r"((r)[24]),"=r"((r)[25]),"=r"((r)[26]),"=r"((r)[27]),"=r"((r)[28]),"=r"((r)[29]),"=r"((r)[30]),"=r"((r)[31]) \
        : "r"(a))

#define TC_ST_X32(a, r) \
    asm volatile("tcgen05.st.sync.aligned.32x32b.x32.b32 [%0], " \
        "{%1,%2,%3,%4,%5,%6,%7,%8,%9,%10,%11,%12,%13,%14,%15,%16," \
        "%17,%18,%19,%20,%21,%22,%23,%24,%25,%26,%27,%28,%29,%30,%31,%32};" \
        :: "r"(a), \
           "r"((r)[0]),"r"((r)[1]),"r"((r)[2]),"r"((r)[3]),"r"((r)[4]),"r"((r)[5]),"r"((r)[6]),"r"((r)[7]), \
           "r"((r)[8]),"r"((r)[9]),"r"((r)[10]),"r"((r)[11]),"r"((r)[12]),"r"((r)[13]),"r"((r)[14]),"r"((r)[15]), \
           "r"((r)[16]),"r"((r)[17]),"r"((r)[18]),"r"((r)[19]),"r"((r)[20]),"r"((r)[21]),"r"((r)[22]),"r"((r)[23]), \
           "r"((r)[24]),"r"((r)[25]),"r"((r)[26]),"r"((r)[27]),"r"((r)[28]),"r"((r)[29]),"r"((r)[30]),"r"((r)[31]) \
        : "memory")

__device__ __forceinline__ void mma_ss_bf16(uint32_t d, uint64_t ad, uint64_t bd,
                                            uint32_t idesc, uint32_t en) {
    asm volatile("{\n\t.reg .pred p;\n\tsetp.ne.u32 p, %4, 0;\n\t"
        "tcgen05.mma.cta_group::1.kind::f16 [%0], %1, %2, %3, {%5,%5,%5,%5}, p;\n\t}"
        :: "r"(d), "l"(ad), "l"(bd), "r"(idesc), "r"(en), "r"(0u) : "memory");
}
__device__ __forceinline__ void mma_ts_bf16(uint32_t d, uint32_t a, uint64_t bd,
                                            uint32_t idesc, uint32_t en) {
    asm volatile("{\n\t.reg .pred p;\n\tsetp.ne.u32 p, %4, 0;\n\t"
        "tcgen05.mma.cta_group::1.kind::f16 [%0], [%1], %2, %3, {%5,%5,%5,%5}, p;\n\t}"
        :: "r"(d), "r"(a), "l"(bd), "r"(idesc), "r"(en), "r"(0u) : "memory");
}
__device__ __forceinline__ uint64_t make_desc(uint32_t base) {
    const uint64_t B = (uint64_t(2) << 61) | (uint64_t(1) << 46) | (uint64_t(64) << 32) | (uint64_t(1) << 16);
    return B | ((uint64_t)(base >> 4) & 0x3FFF);
}
#endif // USE_TC

// ---------------- fp32 -> hi/lo bf16 ----------------
__global__ void conv_kernel(const float* __restrict__ src, bf16* __restrict__ hi,
                            bf16* __restrict__ lo, long n4) {
    long i = (long)blockIdx.x * blockDim.x + threadIdx.x;
    if (i >= n4) return;
    float4 v = ((const float4*)src)[i];
    uint2 hv, lv; split4(v, hv, lv);
    ((uint2*)hi)[i] = hv; ((uint2*)lo)[i] = lv;
}

// ======= bf16 GEMM: 128x256 tile, 3-term hi/lo split, prefetch-ahead pipeline =======
#define A_PL 16384
#define B_PL 32768
#define BUF_BYTES 98304
#define SMEM_TOTAL_TC (1024 + 2*BUF_BYTES)

template<int EPI, bool GATHER, bool SKIP>
__global__ __launch_bounds__(256)
void gemm_bf(const bf16* __restrict__ Ahi, const bf16* __restrict__ Alo, long aStride,
             const bf16* __restrict__ Bhi, const bf16* __restrict__ Blo, long bStride,
             float* __restrict__ Cf, bf16* __restrict__ Chi, bf16* __restrict__ Clo, long cStride,
             const float* __restrict__ bias, int biasStride,
             const float* __restrict__ resid,
             const int* __restrict__ rowIdx,
             const int* __restrict__ counts,
             const float* __restrict__ g0,
             int Nt, int Kd) {
    extern __shared__ char smem[];
    const int z = blockIdx.z;
    const int m0 = blockIdx.y * 128, n0 = blockIdx.x * 256;
    int cnt = 0;
    if (SKIP) { cnt = counts[z]; if (m0 >= cnt) return; }
    int tid = threadIdx.x, wid = tid >> 5, lane = tid & 31;

    const uint32_t OFF_MB = 8, OFF_RID = 64, OFF_TILE = 1024;
    int* s_rid = (int*)(smem + OFF_RID);
    if (tid < 128) {
        int r;
        if (GATHER) r = min(rowIdx[z * CAPX + m0 + tid], NTOK - 1);
        else        r = m0 + tid;
        s_rid[tid] = r;
    }
    const bf16* Ahz = Ahi + (size_t)z * aStride;
    const bf16* Alz = Alo + (size_t)z * aStride;
    const bf16* Bhz = Bhi + (size_t)z * bStride;
    const bf16* Blz = Blo + (size_t)z * bStride;

#if USE_TC
    uint32_t sbase = smem_u32(smem);
    if (tid == 0) { MBAR_INIT(sbase + OFF_MB, 1); MBAR_INIT(sbase + OFF_MB + 8, 1); }
    if (wid == 0) { TC_ALLOC(sbase + 0, 256u); }
    __syncthreads();
    uint32_t tmem = *(uint32_t*)(smem + 0);

    const uint32_t idesc = (1u << 4) | (1u << 7) | (1u << 10) | (32u << 17) | (8u << 24); // N=256

    int nchunks = Kd >> 6;
    int ph0 = 0, ph1 = 0;

    auto issue_chunk = [&](int c, uint32_t tb) {
        int k0 = c * 64;
        #pragma unroll
        for (int i = 0; i < 4; i++) {
            int f = tid + i * 256;
            int row = f >> 3, c8 = f & 7;
            uint32_t so = sw128((uint32_t)(row * 128 + c8 * 16));
            size_t aoff = (size_t)s_rid[row] * Kd + k0 + c8 * 8;
            cpa16(tb + so,        Ahz + aoff);
            cpa16(tb + A_PL + so, Alz + aoff);
        }
        #pragma unroll
        for (int i = 0; i < 8; i++) {
            int f = tid + i * 256;
            int row = f >> 3, c8 = f & 7;
            uint32_t so = sw128((uint32_t)(row * 128 + c8 * 16));
            size_t boff = (size_t)(n0 + row) * Kd + k0 + c8 * 8;
            cpa16(tb + 2 * A_PL + so,        Bhz + boff);
            cpa16(tb + 2 * A_PL + B_PL + so, Blz + boff);
        }
        CPA_COMMIT();
    };

    // prolog: loads(0)
    issue_chunk(0, sbase + OFF_TILE);

    for (int c = 0; c < nchunks; c++) {
        int buf = c & 1;
        uint32_t tb = sbase + OFF_TILE + buf * BUF_BYTES;
        if (c + 1 < nchunks) {
            // buf^1 is written by loads(c+1); MMA(c-1) read it
            if (c >= 1) {
                if ((buf ^ 1) == 0) { mbar_wait(sbase + OFF_MB, ph0); ph0 ^= 1; }
                else                { mbar_wait(sbase + OFF_MB + 8, ph1); ph1 ^= 1; }
            }
            issue_chunk(c + 1, sbase + OFF_TILE + (buf ^ 1) * BUF_BYTES);
            CPA_WAIT(1);          // loads(c) done; loads(c+1) in flight
        } else {
            CPA_WAIT(0);
        }
        asm volatile("fence.proxy.async.shared::cta;" ::: "memory");
        __syncthreads();
        if (wid == 0) {
            if (elect_one()) {
                uint64_t ah = make_desc(tb);
                uint64_t al = make_desc(tb + A_PL);
                uint64_t bh = make_desc(tb + 2 * A_PL);
                uint64_t bl = make_desc(tb + 2 * A_PL + B_PL);
                #pragma unroll
                for (int ks = 0; ks < 4; ks++) {
                    uint64_t o = ks * 2;
                    mma_ss_bf16(tmem, ah + o, bh + o, idesc, (c > 0 || ks > 0) ? 1u : 0u);
                    mma_ss_bf16(tmem, ah + o, bl + o, idesc, 1u);
                    mma_ss_bf16(tmem, al + o, bh + o, idesc, 1u);
                }
                TC_COMMIT(sbase + OFF_MB + 8 * buf);
            }
        }
    }
    mbar_wait(sbase + OFF_MB, ph0);
    mbar_wait(sbase + OFF_MB + 8, ph1);
    TC_FENCE_AFTER();

    int colbase = (wid >> 2) * 128;
    int row = (wid & 3) * 32 + lane;
    int gm = m0 + row;

    int token = 0; float gg = 0.f; bool valid4 = true;
    if (EPI == 4) {
        valid4 = (gm < cnt);
        if (valid4) { token = rowIdx[z * CAPX + gm]; gg = g0[token]; }
    }

    #pragma unroll
    for (int g2 = 0; g2 < 2; g2++) {
        int co = colbase + g2 * 64;
        uint32_t dr[64];
        TC_LD_X32(dr,      tmem + co);
        TC_LD_X32(dr + 32, tmem + co + 32);
        TC_WAIT_LD();

        const float* bp = (EPI >= 1) ? (bias + (size_t)z * biasStride + n0 + co) : nullptr;
        if (EPI == 3) {
            bf16* chp = Chi + (size_t)z * cStride + (size_t)gm * Nt + n0 + co;
            bf16* clp = Clo + (size_t)z * cStride + (size_t)gm * Nt + n0 + co;
            #pragma unroll
            for (int j = 0; j < 64; j += 4) {
                float4 v;
                float t0 = __uint_as_float(dr[j+0]) + bp[j+0];
                float t1 = __uint_as_float(dr[j+1]) + bp[j+1];
                float t2 = __uint_as_float(dr[j+2]) + bp[j+2];
                float t3 = __uint_as_float(dr[j+3]) + bp[j+3];
                v.x = t0 > 0.f ? t0*t0 : 0.f; v.y = t1 > 0.f ? t1*t1 : 0.f;
                v.z = t2 > 0.f ? t2*t2 : 0.f; v.w = t3 > 0.f ? t3*t3 : 0.f;
                uint2 hv, lv; split4(v, hv, lv);
                *(uint2*)(chp + j) = hv; *(uint2*)(clp + j) = lv;
            }
        } else if (EPI == 4) {
            if (valid4) {
                float* op = Cf + (size_t)token * Nt + n0 + co;
                #pragma unroll
                for (int j = 0; j < 64; j += 4) {
                    float4 o = *(float4*)(op + j);
                    o.x += gg * (__uint_as_float(dr[j+0]) + bp[j+0]);
                    o.y += gg * (__uint_as_float(dr[j+1]) + bp[j+1]);
                    o.z += gg * (__uint_as_float(dr[j+2]) + bp[j+2]);
                    o.w += gg * (__uint_as_float(dr[j+3]) + bp[j+3]);
                    *(float4*)(op + j) = o;
                }
            }
        } else {
            const float* rp = (EPI == 2) ? (resid + (size_t)gm * Nt + n0 + co) : nullptr;
            float* cp = Cf + (size_t)z * cStride + (size_t)gm * Nt + n0 + co;
            #pragma unroll
            for (int j = 0; j < 64; j += 4) {
                float vv[4];
                #pragma unroll
                for (int q = 0; q < 4; q++) {
                    float t = __uint_as_float(dr[j + q]);
                    if (EPI == 1)      t += bp[j + q];
                    else if (EPI == 2) t += bp[j + q] + rp[j + q];
                    vv[q] = t;
                }
                float4 v4; v4.x = vv[0]; v4.y = vv[1]; v4.z = vv[2]; v4.w = vv[3];
                *(float4*)(cp + j) = v4;
            }
        }
    }

    TC_FENCE_BEFORE();
    __syncthreads();
    if (wid == 0) { TC_RELINQ(); TC_DEALLOC(tmem, 256u); }

#else  // SIMT fallback (compute_103 pass; never selected at runtime)
    float* As = (float*)(smem + OFF_TILE);
    float* Bs = (float*)(smem + OFF_TILE + 16 * 128 * 4);
    __syncthreads();
    int tm = (tid >> 4) * 8, tn = (tid & 15) * 8;
    for (int nsub = 0; nsub < 2; nsub++) {
        int n0s = n0 + nsub * 128;
        float acc[8][8];
        #pragma unroll
        for (int i = 0; i < 8; i++)
            #pragma unroll
            for (int j = 0; j < 8; j++) acc[i][j] = 0.f;
        for (int k0 = 0; k0 < Kd; k0 += 16) {
            #pragma unroll
            for (int i = 0; i < 2; i++) {
                int f = tid + i * 256;
                int row = f >> 2, c4 = (f & 3) * 4;
                #pragma unroll
                for (int q = 0; q < 4; q++) {
                    size_t ao = (size_t)s_rid[row] * Kd + k0 + c4 + q;
                    size_t bo = (size_t)(n0s + row) * Kd + k0 + c4 + q;
                    As[(c4+q)*128 + row] = __bfloat162float(Ahz[ao]) + __bfloat162float(Alz[ao]);
                    Bs[(c4+q)*128 + row] = __bfloat162float(Bhz[bo]) + __bfloat162float(Blz[bo]);
                }
            }
            __syncthreads();
            #pragma unroll
            for (int kk = 0; kk < 16; kk++) {
                float a_[8], b_[8];
                #pragma unroll
                for (int q = 0; q < 8; q++) { a_[q] = As[kk*128 + tm + q]; b_[q] = Bs[kk*128 + tn + q]; }
                #pragma unroll
                for (int i = 0; i < 8; i++)
                    #pragma unroll
                    for (int j = 0; j < 8; j++)
                        acc[i][j] += a_[i] * b_[j];
            }
            __syncthreads();
        }
        #pragma unroll
        for (int i = 0; i < 8; i++) {
            int gm = m0 + tm + i;
            #pragma unroll
            for (int j = 0; j < 8; j++) {
                float t = acc[i][j];
                int col = n0s + tn + j;
                if (EPI >= 1) t += bias[(size_t)z * biasStride + col];
                if (EPI == 2) t += resid[(size_t)gm * Nt + col];
                if (EPI == 3) {
                    t = t > 0.f ? t * t : 0.f;
                    bf16 hv = __float2bfloat16_rn(t);
                    Chi[(size_t)z * cStride + (size_t)gm * Nt + col] = hv;
                    Clo[(size_t)z * cStride + (size_t)gm * Nt + col] = __float2bfloat16_rn(t - __bfloat162float(hv));
                } else if (EPI == 4) {
                    if (gm < cnt) {
                        int token = rowIdx[z * CAPX + gm];
                        atomicAdd(&Cf[(size_t)token * Nt + col], g0[token] * t);
                    }
                } else {
                    Cf[(size_t)z * cStride + (size_t)gm * Nt + col] = t;
                }
            }
        }
    }
#endif
}

// ---------------- block reduce ----------------
__device__ __forceinline__ float blockReduceSum(float v) {
    __shared__ float sh[32];
    int lane = threadIdx.x & 31, w = threadIdx.x >> 5;
    #pragma unroll
    for (int o = 16; o; o >>= 1) v += __shfl_down_sync(0xffffffffu, v, o);
    if (lane == 0) sh[w] = v;
    __syncthreads();
    int nw = blockDim.x >> 5;
    if (w == 0) {
        v = (lane < nw) ? sh[lane] : 0.f;
        #pragma unroll
        for (int o = 16; o; o >>= 1) v += __shfl_down_sync(0xffffffffu, v, o);
        if (lane == 0) sh[0] = v;
    }
    __syncthreads();
    return sh[0];
}

// ---------------- 1) residual mix + rmsnorm ----------------
__global__ void mix_rms_kernel(const float* __restrict__ x, const float* __restrict__ x0,
                               const float* __restrict__ lambdas) {
    int row = blockIdx.x;
    float l0 = lambdas[0], l1 = lambdas[1];
    size_t off = (size_t)row * CC + threadIdx.x * 4;
    float4 a = *(const float4*)(x + off);
    float4 b = *(const float4*)(x0 + off);
    float4 v;
    v.x = l0*a.x + l1*b.x; v.y = l0*a.y + l1*b.y;
    v.z = l0*a.z + l1*b.z; v.w = l0*a.w + l1*b.w;
    *(float4*)(g_xmix + off) = v;
    float ss = v.x*v.x + v.y*v.y + v.z*v.z + v.w*v.w;
    float tot = blockReduceSum(ss);
    float sc = rsqrtf(tot * (1.0f/CC) + 1e-6f);
    float4 o; o.x = v.x*sc; o.y = v.y*sc; o.z = v.z*sc; o.w = v.w*sc;
    uint2 hv, lv; split4(o, hv, lv);
    *(uint2*)(&g_abf[0][off]) = hv;
    *(uint2*)(&g_abf[1][off]) = lv;
}

// ---------------- 6) rmsnorm of x2 ----------------
__global__ void rms2_kernel(const float* __restrict__ src) {
    int row = blockIdx.x;
    size_t off = (size_t)row * CC + threadIdx.x * 4;
    float4 v = *(const float4*)(src + off);
    float ss = v.x*v.x + v.y*v.y + v.z*v.z + v.w*v.w;
    float tot = blockReduceSum(ss);
    float sc = rsqrtf(tot * (1.0f/CC) + 1e-6f);
    float4 o; o.x = v.x*sc; o.y = v.y*sc; o.z = v.z*sc; o.w = v.w*sc;
    *(float4*)(g_h + off) = o;
    uint2 hv, lv; split4(o, hv, lv);
    *(uint2*)(&g_hbf[0][off]) = hv;
    *(uint2*)(&g_hbf[1][off]) = lv;
}

// ---------------- 3) per-head rmsnorm + rotary ----------------
__global__ void qk_rot_kernel() {
    int gw = blockIdx.x * (blockDim.x >> 5) + (threadIdx.x >> 5);
    int lane = threadIdx.x & 31;
    int qk = gw >> 16;
    int r  = gw & 65535;
    int n  = r >> 4;
    int h  = r & 15;
    const float* p = g_qkv + (size_t)qk * NTOK * CC + (size_t)n * CC + h * HD;
    float x1 = p[lane], x2 = p[lane + 32];
    float ss = x1 * x1 + x2 * x2;
    #pragma unroll
    for (int o = 16; o; o >>= 1) ss += __shfl_xor_sync(0xffffffffu, ss, o);
    float sc = rsqrtf(ss * (1.0f/HD) + 1e-6f);
    x1 *= sc; x2 *= sc;
    int b = n >> 11, t = n & (TT - 1);
    float invj = (lane < 16) ? c_rotinv[lane] : 0.f;
    float th = (float)t * invj;
    float c = cosf(th), s = sinf(th);
    float y1 =  x1 * c + x2 * s;
    float y2 = -x1 * s + x2 * c;
    size_t base = ((size_t)(b * HH + h) * TT + t) * HD;
    bf16* hi = qk ? g_kbf[0] : g_qbf[0];
    bf16* lo = qk ? g_kbf[1] : g_qbf[1];
    bf16 h1 = __float2bfloat16_rn(y1), h2 = __float2bfloat16_rn(y2);
    hi[base + lane]      = h1;
    hi[base + lane + 32] = h2;
    lo[base + lane]      = __float2bfloat16_rn(y1 - __bfloat162float(h1));
    lo[base + lane + 32] = __float2bfloat16_rn(y2 - __bfloat162float(h2));
}

// ---------------- 3b) V transpose+convert ----------------
__global__ __launch_bounds__(256) void vT_kernel() {
    __shared__ float s[128][65];
    int tblk = blockIdx.x, bh = blockIdx.y;
    int b = bh >> 4, h = bh & 15;
    int t0 = tblk * 128;
    const float* vsrc = g_qkv + (size_t)2 * NTOK * CC;
    #pragma unroll
    for (int i = 0; i < 32; i++) {
        int f = threadIdx.x + i * 256;
        int t = f >> 6, d = f & 63;
        s[t][d] = vsrc[((size_t)(b * TT + t0 + t)) * CC + h * HD + d];
    }
    __syncthreads();
    #pragma unroll
    for (int i = 0; i < 32; i++) {
        int f = threadIdx.x + i * 256;
        int d = f >> 7, t = f & 127;
        float v = s[t][d];
        bf16 hv = __float2bfloat16_rn(v);
        size_t off = ((size_t)(bh * HD + d)) * TT + t0 + t;
        g_vT[0][off] = hv;
        g_vT[1][off] = __float2bfloat16_rn(v - __bfloat162float(hv));
    }
}

// ---------------- 4) pipelined tensor-core causal attention ----------------
// smem: Q 32K @2048, K 3x32K @34816, V 2x32K @133120 -> total 198656
#define AT_QHI 2048
#define AT_QLO (AT_QHI + 16384)
#define AT_KBUF 34816
#define AT_VBUF (AT_KBUF + 3*32768)
#define SMEM_ATT (AT_VBUF + 2*32768)
#define AT_L2 128

__global__ __launch_bounds__(256) void attn_tc() {
    extern __shared__ char smem[];
    int qtile = gridDim.x - 1 - blockIdx.x;   // LPT
    int bh = blockIdx.y;
    int b = bh >> 4, h = bh & 15;
    int q0 = qtile * 128;
    int tid = threadIdx.x, wid = tid >> 5, lane = tid & 31;
    int half = wid >> 2;
    int row = (wid & 3) * 32 + lane;

    const bf16* qh_g = g_qbf[0] + ((size_t)bh * TT + q0) * HD;
    const bf16* ql_g = g_qbf[1] + ((size_t)bh * TT + q0) * HD;

#if USE_TC
    uint32_t sbase = smem_u32(smem);
    const uint32_t MBS = sbase + 8, MBA = sbase + 16;
    float* l2s = (float*)(smem + AT_L2);
    if (tid == 0) { MBAR_INIT(MBS, 1); MBAR_INIT(MBA, 1); }

    auto load_K = [&](int kt) {
        uint32_t kb = sbase + AT_KBUF + (uint32_t)(kt % 3) * 32768;
        const bf16* kh_g = g_kbf[0] + ((size_t)bh * TT + kt * 128) * HD;
        const bf16* kl_g = g_kbf[1] + ((size_t)bh * TT + kt * 128) * HD;
        #pragma unroll
        for (int i = 0; i < 4; i++) {
            int f = tid + i * 256;
            int r = f >> 3, c8 = f & 7;
            uint32_t so = sw128((uint32_t)(r * 128 + c8 * 16));
            cpa16(kb + so,         kh_g + (size_t)r * HD + c8 * 8);
            cpa16(kb + 16384 + so, kl_g + (size_t)r * HD + c8 * 8);
        }
    };
    auto load_V = [&](int kt) {
        uint32_t vb = sbase + AT_VBUF + (uint32_t)(kt & 1) * 32768;
        const bf16* vh_g = g_vT[0] + (size_t)bh * HD * TT + kt * 128;
        const bf16* vl_g = g_vT[1] + (size_t)bh * HD * TT + kt * 128;
        #pragma unroll
        for (int i = 0; i < 4; i++) {
            int f = tid + i * 256;
            int d = f >> 4, c16 = f & 15;
            uint32_t byte = (uint32_t)((d >> 3) * 1024 + (c16 >> 3) * 8192 + (d & 7) * 128 + (c16 & 7) * 16);
            uint32_t so = sw128(byte);
            cpa16(vb + so,         vh_g + (size_t)d * TT + c16 * 8);
            cpa16(vb + 16384 + so, vl_g + (size_t)d * TT + c16 * 8);
        }
    };

    // prolog: Q + K(0) + V(0) [+ K(1)]
    {
        #pragma unroll
        for (int i = 0; i < 4; i++) {
            int f = tid + i * 256;
            int r = f >> 3, c8 = f & 7;
            uint32_t so = sw128((uint32_t)(r * 128 + c8 * 16));
            cpa16(sbase + AT_QHI + so, qh_g + (size_t)r * HD + c8 * 8);
            cpa16(sbase + AT_QLO + so, ql_g + (size_t)r * HD + c8 * 8);
        }
        load_K(0);
        load_V(0);
        CPA_COMMIT();
        if (qtile >= 1) { load_K(1); CPA_COMMIT(); }
    }
    if (wid == 0) { TC_ALLOC(sbase + 0, 512u); }
    __syncthreads();
    uint32_t tmem = *(uint32_t*)(smem + 0);
    const uint32_t S0 = 0, O_OFF = 256, P0 = 320;
    const uint32_t IDS = (1u<<4)|(1u<<7)|(1u<<10)|(16u<<17)|(8u<<24);  // N=128
    const uint32_t IDA = (1u<<4)|(1u<<7)|(1u<<10)|( 8u<<17)|(8u<<24);  // N=64

    CPA_WAIT(0);
    asm volatile("fence.proxy.async.shared::cta;" ::: "memory");
    __syncthreads();

    uint64_t qhd = make_desc(sbase + AT_QHI);
    uint64_t qld = make_desc(sbase + AT_QLO);

    auto issue_S = [&](int kt) {
        uint32_t kb = sbase + AT_KBUF + (uint32_t)(kt % 3) * 32768;
        uint64_t kh = make_desc(kb);
        uint64_t kl = make_desc(kb + 16384);
        uint32_t sd = tmem + S0 + (uint32_t)(kt & 1) * 128;
        #pragma unroll
        for (int ks = 0; ks < 4; ks++) {
            uint64_t o = ks * 2;
            mma_ss_bf16(sd, qhd + o, kh + o, IDS, ks > 0 ? 1u : 0u);
            mma_ss_bf16(sd, qhd + o, kl + o, IDS, 1u);
            mma_ss_bf16(sd, qld + o, kh + o, IDS, 1u);
        }
        TC_COMMIT(MBS);
    };

    // S(0)
    if (wid == 0 && elect_one()) issue_S(0);

    float l = 0.f;
    int phS = 0, phA = 0;

    for (int kt = 0; kt <= qtile; kt++) {
        int sbuf = kt & 1;
        // s1: prefetch K(kt+2)
        if (kt + 2 <= qtile) { load_K(kt + 2); CPA_COMMIT(); }
        // s2: wait S(kt)
        mbar_wait(MBS, phS); phS ^= 1;
        TC_FENCE_AFTER();
        // s3: ensure K(kt+1) and V(kt) resident
        if (kt + 2 <= qtile) { CPA_WAIT(1); } else { CPA_WAIT(0); }
        asm volatile("fence.proxy.async.shared::cta;" ::: "memory");
        __syncthreads();
        // s4: issue S(kt+1) NOW — overlaps with softmax(kt)
        if (kt < qtile && wid == 0) {
            if (elect_one()) { TC_FENCE_AFTER(); issue_S(kt + 1); }
        }

        // s5: softmax(kt): LDTM + exp
        uint32_t sr[64];
        TC_LD_X32(sr, tmem + S0 + sbuf * 128 + half * 64);
        TC_WAIT_LD();
        TC_LD_X32(sr + 32, tmem + S0 + sbuf * 128 + half * 64 + 32);

        int qg = q0 + row;
        int kbase = kt * 128 + half * 64;
        bool maskTile = (kt == qtile);
        uint32_t pw[32];
        float lacc = 0.f;
        #pragma unroll
        for (int j2 = 0; j2 < 16; j2++) {
            float s0v = __uint_as_float(sr[2*j2])   * 0.125f;
            float s1v = __uint_as_float(sr[2*j2+1]) * 0.125f;
            float p0 = __expf(s0v), p1 = __expf(s1v);
            if (maskTile) {
                if (kbase + 2*j2     > qg) p0 = 0.f;
                if (kbase + 2*j2 + 1 > qg) p1 = 0.f;
            }
            bf162 pb = __floats2bfloat162_rn(p0, p1);
            lacc += __bfloat162float(pb.x) + __bfloat162float(pb.y);
            pw[j2] = *(uint32_t*)&pb;
        }
        TC_WAIT_LD();
        #pragma unroll
        for (int j2 = 16; j2 < 32; j2++) {
            float s0v = __uint_as_float(sr[2*j2])   * 0.125f;
            float s1v = __uint_as_float(sr[2*j2+1]) * 0.125f;
            float p0 = __expf(s0v), p1 = __expf(s1v);
            if (maskTile) {
                if (kbase + 2*j2     > qg) p0 = 0.f;
                if (kbase + 2*j2 + 1 > qg) p1 = 0.f;
            }
            bf162 pb = __floats2bfloat162_rn(p0, p1);
            lacc += __bfloat162float(pb.x) + __bfloat162float(pb.y);
            pw[j2] = *(uint32_t*)&pb;
        }
        l += lacc;

        // s6: wait AV(kt-1) (frees V buf (kt+1)&1)
        if (kt > 0) { mbar_wait(MBA, phA); phA ^= 1; }

        // s7: prefetch V(kt+1)
        if (kt < qtile) { load_V(kt + 1); CPA_COMMIT(); }

        // s8: store P(kt)
        TC_ST_X32(tmem + P0 + sbuf * 64 + half * 32 + ((uint32_t)(wid & 3) << 21), pw);
        TC_WAIT_ST();
        TC_FENCE_BEFORE();
        __syncthreads();

        // s9: issue AV(kt)
        if (wid == 0 && elect_one()) {
            TC_FENCE_AFTER();
            uint32_t vb = sbase + AT_VBUF + (uint32_t)sbuf * 32768;
            uint64_t vh = make_desc(vb);
            uint64_t vl = make_desc(vb + 16384);
            #pragma unroll
            for (int ks = 0; ks < 8; ks++) {
                uint64_t vo = (uint64_t)((ks & 3) * 2 + (ks >> 2) * 512);
                uint32_t at = tmem + P0 + sbuf * 64 + ks * 8;
                mma_ts_bf16(tmem + O_OFF, at, vh + vo, IDA, (kt > 0 || ks > 0) ? 1u : 0u);
                mma_ts_bf16(tmem + O_OFF, at, vl + vo, IDA, 1u);
            }
            TC_COMMIT(MBA);
        }
    }
    mbar_wait(MBA, phA);
    TC_FENCE_AFTER();

    l2s[half * 128 + row] = l;
    __syncthreads();
    float inv = 1.f / (l2s[row] + l2s[128 + row]);

    uint32_t od[32];
    TC_LD_X32(od, tmem + O_OFF + half * 32);
    TC_WAIT_LD();
    int token = b * TT + q0 + row;
    bf16* ohp = g_obf[0] + (size_t)token * CC + h * HD + half * 32;
    bf16* olp = g_obf[1] + (size_t)token * CC + h * HD + half * 32;
    #pragma unroll
    for (int j = 0; j < 32; j += 4) {
        float4 v;
        v.x = __uint_as_float(od[j+0]) * inv;
        v.y = __uint_as_float(od[j+1]) * inv;
        v.z = __uint_as_float(od[j+2]) * inv;
        v.w = __uint_as_float(od[j+3]) * inv;
        uint2 hv, lv; split4(v, hv, lv);
        *(uint2*)(ohp + j) = hv; *(uint2*)(olp + j) = lv;
    }
    TC_FENCE_BEFORE();
    __syncthreads();
    if (wid == 0) { TC_RELINQ(); TC_DEALLOC(tmem, 512u); }

#else // SIMT fallback attention
    for (int qq = tid; qq < 128; qq += 256) {
        int qg = q0 + qq;
        float q[HD], o[HD];
        #pragma unroll
        for (int d = 0; d < HD; d++) {
            q[d] = (__bfloat162float(qh_g[(size_t)qq*HD+d]) + __bfloat162float(ql_g[(size_t)qq*HD+d])) * 0.125f;
            o[d] = 0.f;
        }
        float l = 0.f;
        for (int k = 0; k <= qg; k++) {
            const bf16* kh_g = g_kbf[0] + ((size_t)bh * TT + k) * HD;
            const bf16* kl_g = g_kbf[1] + ((size_t)bh * TT + k) * HD;
            float s = 0.f;
            #pragma unroll
            for (int d = 0; d < HD; d++)
                s += q[d] * (__bfloat162float(kh_g[d]) + __bfloat162float(kl_g[d]));
            float p = __expf(s);
            l += p;
            #pragma unroll
            for (int d = 0; d < HD; d++) {
                size_t vo = ((size_t)bh * HD + d) * TT + k;
                o[d] += p * (__bfloat162float(g_vT[0][vo]) + __bfloat162float(g_vT[1][vo]));
            }
        }
        float inv = 1.f / l;
        int token = b * TT + qg;
        #pragma unroll
        for (int d = 0; d < HD; d++) {
            float v = o[d] * inv;
            bf16 hv = __float2bfloat16_rn(v);
            g_obf[0][(size_t)token * CC + h * HD + d] = hv;
            g_obf[1][(size_t)token * CC + h * HD + d] = __float2bfloat16_rn(v - __bfloat162float(hv));
        }
    }
#endif
}

// ---------------- 7) router ----------------
__global__ void router_kernel(const float* __restrict__ rw, const float* __restrict__ rb,
                              const float* __restrict__ nw, const float* __restrict__ nb,
                              const float* __restrict__ noise) {
    int n = blockIdx.x;
    int w = threadIdx.x >> 5, lane = threadIdx.x & 31;
    const float* hr = g_h + (size_t)n * CC;
    const float* wr = rw + (size_t)w * CC;
    const float* wn = nw + (size_t)w * CC;
    float s1 = 0.f, s2 = 0.f;
    for (int c = lane * 4; c < CC; c += 128) {
        float4 hv = *(const float4*)(hr + c);
        float4 r4 = *(const float4*)(wr + c);
        float4 n4 = *(const float4*)(wn + c);
        s1 += hv.x*r4.x + hv.y*r4.y + hv.z*r4.z + hv.w*r4.w;
        s2 += hv.x*n4.x + hv.y*n4.y + hv.z*n4.z + hv.w*n4.w;
    }
    #pragma unroll
    for (int o = 16; o; o >>= 1) {
        s1 += __shfl_xor_sync(0xffffffffu, s1, o);
        s2 += __shfl_xor_sync(0xffffffffu, s2, o);
    }
    __shared__ float lg[8], nl[8];
    if (lane == 0) { lg[w] = s1 + rb[w]; nl[w] = s2 + nb[w]; }
    __syncthreads();
    if (threadIdx.x == 0) {
        float nv[8];
        #pragma unroll
        for (int e = 0; e < 8; e++) {
            float xn = nl[e];
            float sp = (xn > 20.f) ? xn : log1pf(expf(xn));
            nv[e] = lg[e] + noise[(size_t)n * EE + e] * sp;
        }
        int i0 = 0; float v0 = nv[0];
        #pragma unroll
        for (int e = 1; e < 8; e++) if (nv[e] > v0) { v0 = nv[e]; i0 = e; }
        float v1 = -1e30f;
        #pragma unroll
        for (int e = 0; e < 8; e++) if (e != i0 && nv[e] > v1) { v1 = nv[e]; }
        float e1 = expf(v1 - v0);
        g_g0[n] = 1.f / (1.f + e1);
        g_eid[n] = i0;
    }
}

// ---------------- 8) per-expert capacity lists ----------------
__global__ void build_idx_kernel() {
    int w = threadIdx.x >> 5, lane = threadIdx.x & 31;
    int count = 0;
    for (int base = 0; base < NTOK; base += 32) {
        int t = base + lane;
        bool p = (g_eid[t] == w);
        unsigned msk = __ballot_sync(0xffffffffu, p);
        int pos = count + __popc(msk & ((1u << lane) - 1u));
        if (p && pos < CAPX) g_idx[w * CAPX + pos] = t;
        count += __popc(msk);
    }
    int c = min(count, CAPX);
    if (lane == 0) g_cnt[w] = c;
    for (int s = c + lane; s < CAPX; s += 32) g_idx[w * CAPX + s] = NTOK;
}

// ---------------- host launcher ----------------
extern "C" void kernel_launch(void* const* d_in, const int* in_sizes, int n_in,
                              void* d_out, int out_size) {
    const float* x        = (const float*)d_in[0];
    const float* x0       = (const float*)d_in[1];
    const float* noise    = (const float*)d_in[2];
    const float* lambdas  = (const float*)d_in[3];
    const float* qkv_w    = (const float*)d_in[5];
    const float* c_proj_w = (const float*)d_in[6];
    const float* c_proj_b = (const float*)d_in[7];
    const float* router_w = (const float*)d_in[8];
    const float* router_b = (const float*)d_in[9];
    const float* noise_w  = (const float*)d_in[10];
    const float* noise_b  = (const float*)d_in[11];
    const float* ew1      = (const float*)d_in[12];
    const float* eb1      = (const float*)d_in[13];
    const float* ew2      = (const float*)d_in[14];
    const float* eb2      = (const float*)d_in[15];
    float* out = (float*)d_out;

    void *p_qkv, *p_xmix, *p_h, *p_idx, *p_cnt, *p_g0;
    void *p_abf, *p_obf, *p_hbf, *p_h1bf, *p_wqkv, *p_wcp, *p_we1, *p_we2;
    cudaGetSymbolAddress(&p_qkv,  g_qkv);
    cudaGetSymbolAddress(&p_xmix, g_xmix);
    cudaGetSymbolAddress(&p_h,    g_h);
    cudaGetSymbolAddress(&p_idx,  g_idx);
    cudaGetSymbolAddress(&p_cnt,  g_cnt);
    cudaGetSymbolAddress(&p_g0,   g_g0);
    cudaGetSymbolAddress(&p_abf,  g_abf);
    cudaGetSymbolAddress(&p_obf,  g_obf);
    cudaGetSymbolAddress(&p_hbf,  g_hbf);
    cudaGetSymbolAddress(&p_h1bf, g_h1bf);
    cudaGetSymbolAddress(&p_wqkv, g_wqkv);
    cudaGetSymbolAddress(&p_wcp,  g_wcp);
    cudaGetSymbolAddress(&p_we1,  g_we1);
    cudaGetSymbolAddress(&p_we2,  g_we2);

    bf16* abf_h  = (bf16*)p_abf;   bf16* abf_l  = abf_h  + (size_t)NTOK*CC;
    bf16* obf_h  = (bf16*)p_obf;   bf16* obf_l  = obf_h  + (size_t)NTOK*CC;
    bf16* hbf_h  = (bf16*)p_hbf;   bf16* hbf_l  = hbf_h  + (size_t)NTOK*CC;
    bf16* h1_h   = (bf16*)p_h1bf;  bf16* h1_l   = h1_h   + (size_t)EE*CAPX*HID;
    bf16* wqkv_h = (bf16*)p_wqkv;  bf16* wqkv_l = wqkv_h + (size_t)3*CC*CC;
    bf16* wcp_h  = (bf16*)p_wcp;   bf16* wcp_l  = wcp_h  + (size_t)CC*CC;
    bf16* we1_h  = (bf16*)p_we1;   bf16* we1_l  = we1_h  + (size_t)EE*HID*CC;
    bf16* we2_h  = (bf16*)p_we2;   bf16* we2_l  = we2_h  + (size_t)EE*CC*HID;

    cudaFuncSetAttribute(gemm_bf<0,false,false>, cudaFuncAttributeMaxDynamicSharedMemorySize, SMEM_TOTAL_TC);
    cudaFuncSetAttribute(gemm_bf<2,false,false>, cudaFuncAttributeMaxDynamicSharedMemorySize, SMEM_TOTAL_TC);
    cudaFuncSetAttribute(gemm_bf<3,true, true >, cudaFuncAttributeMaxDynamicSharedMemorySize, SMEM_TOTAL_TC);
    cudaFuncSetAttribute(gemm_bf<4,false,true >, cudaFuncAttributeMaxDynamicSharedMemorySize, SMEM_TOTAL_TC);
    cudaFuncSetAttribute(attn_tc, cudaFuncAttributeMaxDynamicSharedMemorySize, SMEM_ATT);

    conv_kernel<<<(3*CC*CC/4 + 255)/256, 256>>>(qkv_w,    wqkv_h, wqkv_l, (long)3*CC*CC/4);
    conv_kernel<<<(CC*CC/4 + 255)/256, 256>>>(c_proj_w, wcp_h,  wcp_l,  (long)CC*CC/4);
    conv_kernel<<<((long)EE*HID*CC/4 + 255)/256, 256>>>(ew1, we1_h, we1_l, (long)EE*HID*CC/4);
    conv_kernel<<<((long)EE*CC*HID/4 + 255)/256, 256>>>(ew2, we2_h, we2_l, (long)EE*CC*HID/4);

    mix_rms_kernel<<<NTOK, 256>>>(x, x0, lambdas);

    gemm_bf<0,false,false><<<dim3(CC/256, NTOK/128, 3), 256, SMEM_TOTAL_TC>>>(
        abf_h, abf_l, 0L, wqkv_h, wqkv_l, (long)CC*CC,
        (float*)p_qkv, nullptr, nullptr, (long)NTOK*CC,
        nullptr, 0, nullptr, nullptr, nullptr, nullptr, CC, CC);

    qk_rot_kernel<<<(2 * NTOK * HH) / 8, 256>>>();
    vT_kernel<<<dim3(TT/128, 2*HH), 256>>>();

    attn_tc<<<dim3(TT/128, 2*HH), 256, SMEM_ATT>>>();

    gemm_bf<2,false,false><<<dim3(CC/256, NTOK/128, 1), 256, SMEM_TOTAL_TC>>>(
        obf_h, obf_l, 0L, wcp_h, wcp_l, 0L,
        out, nullptr, nullptr, 0L,
        c_proj_b, 0, (const float*)p_xmix, nullptr, nullptr, nullptr, CC, CC);

    rms2_kernel<<<NTOK, 256>>>(out);

    router_kernel<<<NTOK, 256>>>(router_w, router_b, noise_w, noise_b, noise);
    build_idx_kernel<<<1, 256>>>();

    gemm_bf<3,true,true><<<dim3(HID/256, CAPX/128, EE), 256, SMEM_TOTAL_TC>>>(
        hbf_h, hbf_l, 0L, we1_h, we1_l, (long)HID*CC,
        nullptr, h1_h, h1_l, (long)CAPX*HID,
        eb1, HID, nullptr, (const int*)p_idx, (const int*)p_cnt, nullptr, HID, CC);

    gemm_bf<4,false,true><<<dim3(CC/256, CAPX/128, EE), 256, SMEM_TOTAL_TC>>>(
        h1_h, h1_l, (long)CAPX*HID, we2_h, we2_l, (long)CC*HID,
        out, nullptr, nullptr, 0L,
        eb2, CC, nullptr, (const int*)p_idx, (const int*)p_cnt, (const float*)p_g0, CC, HID);
}

// round 8
// speedup vs baseline: 12.2991x; 1.0094x over previous
#include <cuda_runtime.h>
#include <cuda_bf16.h>
#include <math.h>
#include <stdint.h>

#define NTOK 4096
#define TT   2048
#define CC   1024
#define HH   16
#define HD   64
#define EE   8
#define CAPX 1024
#define HID  4096

#if defined(__CUDA_ARCH__)
# if (__CUDA_ARCH__ >= 1000) && (defined(__CUDA_ARCH_FEAT_SM103_ALL) || defined(__CUDA_ARCH_FEAT_SM100_ALL) || defined(__CUDA_ARCH_SPECIFIC__) || defined(__CUDA_ARCH_FAMILY_SPECIFIC__))
#  define USE_TC 1
# else
#  define USE_TC 0
# endif
#else
# define USE_TC 0
#endif

typedef __nv_bfloat16 bf16;
typedef __nv_bfloat162 bf162;

// ---------------- scratch ----------------
__device__ float g_xmix[(size_t)NTOK*CC];
__device__ float g_qkv [(size_t)3*NTOK*CC];
__device__ float g_h   [(size_t)NTOK*CC];
__device__ float g_g0  [NTOK];
__device__ int   g_eid [NTOK];
__device__ int   g_idx [EE*CAPX];
__device__ int   g_cnt [EE];
__device__ bf16 g_abf [2][(size_t)NTOK*CC];
__device__ bf16 g_obf [2][(size_t)NTOK*CC];
__device__ bf16 g_hbf [2][(size_t)NTOK*CC];
__device__ bf16 g_qbf [2][(size_t)NTOK*CC];      // [bh][t][d]
__device__ bf16 g_kbf [2][(size_t)NTOK*CC];      // [bh][t][d]
__device__ bf16 g_vT  [2][(size_t)NTOK*CC];      // [bh][d][t]
__device__ bf16 g_h1bf[2][(size_t)EE*CAPX*HID];
__device__ bf16 g_wqkv[2][(size_t)3*CC*CC];
__device__ bf16 g_wcp [2][(size_t)CC*CC];
__device__ bf16 g_we1 [2][(size_t)EE*HID*CC];
__device__ bf16 g_we2 [2][(size_t)EE*CC*HID];

__constant__ float c_rotinv[16] = {
    1.0f, 0.6299605249474366f, 0.39685026299204984f, 0.25f,
    0.15749013123685915f, 0.09921256574801246f, 0.0625f, 0.03937253280921479f,
    0.024803141437003115f, 0.015625f, 0.009843133202303697f, 0.0062007853592507785f,
    0.00390625f, 0.0024607833005759242f, 0.0015501963398126947f, 0.0009765625f
};

// ---------------- helpers ----------------
__device__ __forceinline__ uint32_t smem_u32(const void* p) {
    uint32_t a;
    asm("{ .reg .u64 t; cvta.to.shared.u64 t, %1; cvt.u32.u64 %0, t; }" : "=r"(a) : "l"(p));
    return a;
}
__device__ __forceinline__ uint32_t sw128(uint32_t off) { return off ^ ((off >> 3) & 0x70); }

__device__ __forceinline__ void cpa16(uint32_t d, const void* s) {
    asm volatile("cp.async.cg.shared.global [%0], [%1], 16;" :: "r"(d), "l"(s) : "memory");
}
#define CPA_COMMIT() asm volatile("cp.async.commit_group;" ::: "memory")
#define CPA_WAIT(n)  asm volatile("cp.async.wait_group %0;" :: "n"(n) : "memory")

__device__ __forceinline__ void split4(float4 v, uint2& hv, uint2& lv) {
    bf16 h0 = __float2bfloat16_rn(v.x), h1 = __float2bfloat16_rn(v.y);
    bf16 h2 = __float2bfloat16_rn(v.z), h3 = __float2bfloat16_rn(v.w);
    bf162 hp0; hp0.x = h0; hp0.y = h1;
    bf162 hp1; hp1.x = h2; hp1.y = h3;
    bf162 lp0 = __floats2bfloat162_rn(v.x - __bfloat162float(h0), v.y - __bfloat162float(h1));
    bf162 lp1 = __floats2bfloat162_rn(v.z - __bfloat162float(h2), v.w - __bfloat162float(h3));
    hv.x = *(uint32_t*)&hp0; hv.y = *(uint32_t*)&hp1;
    lv.x = *(uint32_t*)&lp0; lv.y = *(uint32_t*)&lp1;
}

#if USE_TC
__device__ __forceinline__ uint32_t elect_one() {
    uint32_t p;
    asm volatile("{\n\t.reg .pred p;\n\telect.sync _|p, 0xFFFFFFFF;\n\tselp.b32 %0, 1, 0, p;\n\t}" : "=r"(p));
    return p;
}
#define MBAR_INIT(addr, cnt) \
    asm volatile("mbarrier.init.shared.b64 [%0], %1;" :: "r"(addr), "r"(cnt) : "memory")
__device__ __forceinline__ void mbar_wait(uint32_t addr, int phase) {
    uint32_t done = 0;
    while (!done) {
        asm volatile("{\n\t.reg .pred p;\n\t"
            "mbarrier.try_wait.parity.acquire.cta.shared::cta.b64 p, [%1], %2, 0x989680;\n\t"
            "selp.b32 %0, 1, 0, p;\n\t}" : "=r"(done) : "r"(addr), "r"(phase) : "memory");
    }
}
#define TC_ALLOC(addr, n) \
    asm volatile("tcgen05.alloc.cta_group::1.sync.aligned.shared::cta.b32 [%0], %1;" :: "r"(addr), "r"(n) : "memory")
#define TC_DEALLOC(tm, n) \
    asm volatile("tcgen05.dealloc.cta_group::1.sync.aligned.b32 %0, %1;" :: "r"(tm), "r"(n))
#define TC_RELINQ() \
    asm volatile("tcgen05.relinquish_alloc_permit.cta_group::1.sync.aligned;")
#define TC_COMMIT(mbar) \
    asm volatile("tcgen05.commit.cta_group::1.mbarrier::arrive::one.shared::cluster.b64 [%0];" :: "r"(mbar) : "memory")
#define TC_FENCE_AFTER()  asm volatile("tcgen05.fence::after_thread_sync;" ::: "memory")
#define TC_FENCE_BEFORE() asm volatile("tcgen05.fence::before_thread_sync;" ::: "memory")
#define TC_WAIT_LD()      asm volatile("tcgen05.wait::ld.sync.aligned;" ::: "memory")
#define TC_WAIT_ST()      asm volatile("tcgen05.wait::st.sync.aligned;" ::: "memory")

#define TC_LD_X32(r, a) \
    asm volatile("tcgen05.ld.sync.aligned.32x32b.x32.b32 " \
        "{%0,%1,%2,%3,%4,%5,%6,%7,%8,%9,%10,%11,%12,%13,%14,%15," \
        "%16,%17,%18,%19,%20,%21,%22,%23,%24,%25,%26,%27,%28,%29,%30,%31}, [%32];" \
        : "=r"((r)[0]),"=r"((r)[1]),"=r"((r)[2]),"=r"((r)[3]),"=r"((r)[4]),"=r"((r)[5]),"=r"((r)[6]),"=r"((r)[7]), \
          "=r"((r)[8]),"=r"((r)[9]),"=r"((r)[10]),"=r"((r)[11]),"=r"((r)[12]),"=r"((r)[13]),"=r"((r)[14]),"=r"((r)[15]), \
          "=r"((r)[16]),"=r"((r)[17]),"=r"((r)[18]),"=r"((r)[19]),"=r"((r)[20]),"=r"((r)[21]),"=r"((r)[22]),"=r"((r)[23]), \
          "=r"((r)[24]),"=r"((r)[25]),"=r"((r)[26]),"=r"((r)[27]),"=r"((r)[28]),"=r"((r)[29]),"=r"((r)[30]),"=r"((r)[31]) \
        : "r"(a))

#define TC_ST_X32(a, r) \
    asm volatile("tcgen05.st.sync.aligned.32x32b.x32.b32 [%0], " \
        "{%1,%2,%3,%4,%5,%6,%7,%8,%9,%10,%11,%12,%13,%14,%15,%16," \
        "%17,%18,%19,%20,%21,%22,%23,%24,%25,%26,%27,%28,%29,%30,%31,%32};" \
        :: "r"(a), \
           "r"((r)[0]),"r"((r)[1]),"r"((r)[2]),"r"((r)[3]),"r"((r)[4]),"r"((r)[5]),"r"((r)[6]),"r"((r)[7]), \
           "r"((r)[8]),"r"((r)[9]),"r"((r)[10]),"r"((r)[11]),"r"((r)[12]),"r"((r)[13]),"r"((r)[14]),"r"((r)[15]), \
           "r"((r)[16]),"r"((r)[17]),"r"((r)[18]),"r"((r)[19]),"r"((r)[20]),"r"((r)[21]),"r"((r)[22]),"r"((r)[23]), \
           "r"((r)[24]),"r"((r)[25]),"r"((r)[26]),"r"((r)[27]),"r"((r)[28]),"r"((r)[29]),"r"((r)[30]),"r"((r)[31]) \
        : "memory")

__device__ __forceinline__ void mma_ss_bf16(uint32_t d, uint64_t ad, uint64_t bd,
                                            uint32_t idesc, uint32_t en) {
    asm volatile("{\n\t.reg .pred p;\n\tsetp.ne.u32 p, %4, 0;\n\t"
        "tcgen05.mma.cta_group::1.kind::f16 [%0], %1, %2, %3, {%5,%5,%5,%5}, p;\n\t}"
        :: "r"(d), "l"(ad), "l"(bd), "r"(idesc), "r"(en), "r"(0u) : "memory");
}
__device__ __forceinline__ void mma_ts_bf16(uint32_t d, uint32_t a, uint64_t bd,
                                            uint32_t idesc, uint32_t en) {
    asm volatile("{\n\t.reg .pred p;\n\tsetp.ne.u32 p, %4, 0;\n\t"
        "tcgen05.mma.cta_group::1.kind::f16 [%0], [%1], %2, %3, {%5,%5,%5,%5}, p;\n\t}"
        :: "r"(d), "r"(a), "l"(bd), "r"(idesc), "r"(en), "r"(0u) : "memory");
}
__device__ __forceinline__ uint64_t make_desc(uint32_t base) {
    const uint64_t B = (uint64_t(2) << 61) | (uint64_t(1) << 46) | (uint64_t(64) << 32) | (uint64_t(1) << 16);
    return B | ((uint64_t)(base >> 4) & 0x3FFF);
}
#endif // USE_TC

// ---------------- fp32 -> hi/lo bf16 ----------------
__global__ void conv_kernel(const float* __restrict__ src, bf16* __restrict__ hi,
                            bf16* __restrict__ lo, long n4) {
    long i = (long)blockIdx.x * blockDim.x + threadIdx.x;
    if (i >= n4) return;
    float4 v = ((const float4*)src)[i];
    uint2 hv, lv; split4(v, hv, lv);
    ((uint2*)hi)[i] = hv; ((uint2*)lo)[i] = lv;
}

// ======= bf16 GEMM: 128x256 tile, 3-term hi/lo split, prefetch-ahead pipeline =======
#define A_PL 16384
#define B_PL 32768
#define BUF_BYTES 98304
#define SMEM_TOTAL_TC (1024 + 2*BUF_BYTES)

template<int EPI, bool GATHER, bool SKIP>
__global__ __launch_bounds__(256)
void gemm_bf(const bf16* __restrict__ Ahi, const bf16* __restrict__ Alo, long aStride,
             const bf16* __restrict__ Bhi, const bf16* __restrict__ Blo, long bStride,
             float* __restrict__ Cf, bf16* __restrict__ Chi, bf16* __restrict__ Clo, long cStride,
             const float* __restrict__ bias, int biasStride,
             const float* __restrict__ resid,
             const int* __restrict__ rowIdx,
             const int* __restrict__ counts,
             const float* __restrict__ g0,
             int Nt, int Kd) {
    extern __shared__ char smem[];
    const int z = blockIdx.z;
    const int m0 = blockIdx.y * 128, n0 = blockIdx.x * 256;
    int cnt = 0;
    if (SKIP) { cnt = counts[z]; if (m0 >= cnt) return; }
    int tid = threadIdx.x, wid = tid >> 5, lane = tid & 31;

    const uint32_t OFF_MB = 8, OFF_RID = 64, OFF_TILE = 1024;
    int* s_rid = (int*)(smem + OFF_RID);
    if (tid < 128) {
        int r;
        if (GATHER) r = min(rowIdx[z * CAPX + m0 + tid], NTOK - 1);
        else        r = m0 + tid;
        s_rid[tid] = r;
    }
    const bf16* Ahz = Ahi + (size_t)z * aStride;
    const bf16* Alz = Alo + (size_t)z * aStride;
    const bf16* Bhz = Bhi + (size_t)z * bStride;
    const bf16* Blz = Blo + (size_t)z * bStride;

#if USE_TC
    uint32_t sbase = smem_u32(smem);
    if (tid == 0) { MBAR_INIT(sbase + OFF_MB, 1); MBAR_INIT(sbase + OFF_MB + 8, 1); }
    if (wid == 0) { TC_ALLOC(sbase + 0, 256u); }
    __syncthreads();
    uint32_t tmem = *(uint32_t*)(smem + 0);

    const uint32_t idesc = (1u << 4) | (1u << 7) | (1u << 10) | (32u << 17) | (8u << 24); // N=256

    int nchunks = Kd >> 6;
    int ph0 = 0, ph1 = 0;

    auto issue_chunk = [&](int c, uint32_t tb) {
        int k0 = c * 64;
        #pragma unroll
        for (int i = 0; i < 4; i++) {
            int f = tid + i * 256;
            int row = f >> 3, c8 = f & 7;
            uint32_t so = sw128((uint32_t)(row * 128 + c8 * 16));
            size_t aoff = (size_t)s_rid[row] * Kd + k0 + c8 * 8;
            cpa16(tb + so,        Ahz + aoff);
            cpa16(tb + A_PL + so, Alz + aoff);
        }
        #pragma unroll
        for (int i = 0; i < 8; i++) {
            int f = tid + i * 256;
            int row = f >> 3, c8 = f & 7;
            uint32_t so = sw128((uint32_t)(row * 128 + c8 * 16));
            size_t boff = (size_t)(n0 + row) * Kd + k0 + c8 * 8;
            cpa16(tb + 2 * A_PL + so,        Bhz + boff);
            cpa16(tb + 2 * A_PL + B_PL + so, Blz + boff);
        }
        CPA_COMMIT();
    };

    issue_chunk(0, sbase + OFF_TILE);

    for (int c = 0; c < nchunks; c++) {
        int buf = c & 1;
        uint32_t tb = sbase + OFF_TILE + buf * BUF_BYTES;
        if (c + 1 < nchunks) {
            if (c >= 1) {
                if ((buf ^ 1) == 0) { mbar_wait(sbase + OFF_MB, ph0); ph0 ^= 1; }
                else                { mbar_wait(sbase + OFF_MB + 8, ph1); ph1 ^= 1; }
            }
            issue_chunk(c + 1, sbase + OFF_TILE + (buf ^ 1) * BUF_BYTES);
            CPA_WAIT(1);
        } else {
            CPA_WAIT(0);
        }
        asm volatile("fence.proxy.async.shared::cta;" ::: "memory");
        __syncthreads();
        if (wid == 0) {
            if (elect_one()) {
                uint64_t ah = make_desc(tb);
                uint64_t al = make_desc(tb + A_PL);
                uint64_t bh = make_desc(tb + 2 * A_PL);
                uint64_t bl = make_desc(tb + 2 * A_PL + B_PL);
                #pragma unroll
                for (int ks = 0; ks < 4; ks++) {
                    uint64_t o = ks * 2;
                    mma_ss_bf16(tmem, ah + o, bh + o, idesc, (c > 0 || ks > 0) ? 1u : 0u);
                    mma_ss_bf16(tmem, ah + o, bl + o, idesc, 1u);
                    mma_ss_bf16(tmem, al + o, bh + o, idesc, 1u);
                }
                TC_COMMIT(sbase + OFF_MB + 8 * buf);
            }
        }
    }
    mbar_wait(sbase + OFF_MB, ph0);
    mbar_wait(sbase + OFF_MB + 8, ph1);
    TC_FENCE_AFTER();

    int colbase = (wid >> 2) * 128;
    int row = (wid & 3) * 32 + lane;
    int gm = m0 + row;

    int token = 0; float gg = 0.f; bool valid4 = true;
    if (EPI == 4) {
        valid4 = (gm < cnt);
        if (valid4) { token = rowIdx[z * CAPX + gm]; gg = g0[token]; }
    }

    #pragma unroll
    for (int g2 = 0; g2 < 2; g2++) {
        int co = colbase + g2 * 64;
        uint32_t dr[64];
        TC_LD_X32(dr,      tmem + co);
        TC_LD_X32(dr + 32, tmem + co + 32);
        TC_WAIT_LD();

        const float* bp = (EPI >= 1) ? (bias + (size_t)z * biasStride + n0 + co) : nullptr;
        if (EPI == 3) {
            bf16* chp = Chi + (size_t)z * cStride + (size_t)gm * Nt + n0 + co;
            bf16* clp = Clo + (size_t)z * cStride + (size_t)gm * Nt + n0 + co;
            #pragma unroll
            for (int j = 0; j < 64; j += 4) {
                float4 v;
                float t0 = __uint_as_float(dr[j+0]) + bp[j+0];
                float t1 = __uint_as_float(dr[j+1]) + bp[j+1];
                float t2 = __uint_as_float(dr[j+2]) + bp[j+2];
                float t3 = __uint_as_float(dr[j+3]) + bp[j+3];
                v.x = t0 > 0.f ? t0*t0 : 0.f; v.y = t1 > 0.f ? t1*t1 : 0.f;
                v.z = t2 > 0.f ? t2*t2 : 0.f; v.w = t3 > 0.f ? t3*t3 : 0.f;
                uint2 hv, lv; split4(v, hv, lv);
                *(uint2*)(chp + j) = hv; *(uint2*)(clp + j) = lv;
            }
        } else if (EPI == 4) {
            if (valid4) {
                float* op = Cf + (size_t)token * Nt + n0 + co;
                #pragma unroll
                for (int j = 0; j < 64; j += 4) {
                    float4 o = *(float4*)(op + j);
                    o.x += gg * (__uint_as_float(dr[j+0]) + bp[j+0]);
                    o.y += gg * (__uint_as_float(dr[j+1]) + bp[j+1]);
                    o.z += gg * (__uint_as_float(dr[j+2]) + bp[j+2]);
                    o.w += gg * (__uint_as_float(dr[j+3]) + bp[j+3]);
                    *(float4*)(op + j) = o;
                }
            }
        } else {
            const float* rp = (EPI == 2) ? (resid + (size_t)gm * Nt + n0 + co) : nullptr;
            float* cp = Cf + (size_t)z * cStride + (size_t)gm * Nt + n0 + co;
            #pragma unroll
            for (int j = 0; j < 64; j += 4) {
                float vv[4];
                #pragma unroll
                for (int q = 0; q < 4; q++) {
                    float t = __uint_as_float(dr[j + q]);
                    if (EPI == 1)      t += bp[j + q];
                    else if (EPI == 2) t += bp[j + q] + rp[j + q];
                    vv[q] = t;
                }
                float4 v4; v4.x = vv[0]; v4.y = vv[1]; v4.z = vv[2]; v4.w = vv[3];
                *(float4*)(cp + j) = v4;
            }
        }
    }

    TC_FENCE_BEFORE();
    __syncthreads();
    if (wid == 0) { TC_RELINQ(); TC_DEALLOC(tmem, 256u); }

#else  // SIMT fallback (compute_103 pass; never selected at runtime)
    float* As = (float*)(smem + OFF_TILE);
    float* Bs = (float*)(smem + OFF_TILE + 16 * 128 * 4);
    __syncthreads();
    int tm = (tid >> 4) * 8, tn = (tid & 15) * 8;
    for (int nsub = 0; nsub < 2; nsub++) {
        int n0s = n0 + nsub * 128;
        float acc[8][8];
        #pragma unroll
        for (int i = 0; i < 8; i++)
            #pragma unroll
            for (int j = 0; j < 8; j++) acc[i][j] = 0.f;
        for (int k0 = 0; k0 < Kd; k0 += 16) {
            #pragma unroll
            for (int i = 0; i < 2; i++) {
                int f = tid + i * 256;
                int row = f >> 2, c4 = (f & 3) * 4;
                #pragma unroll
                for (int q = 0; q < 4; q++) {
                    size_t ao = (size_t)s_rid[row] * Kd + k0 + c4 + q;
                    size_t bo = (size_t)(n0s + row) * Kd + k0 + c4 + q;
                    As[(c4+q)*128 + row] = __bfloat162float(Ahz[ao]) + __bfloat162float(Alz[ao]);
                    Bs[(c4+q)*128 + row] = __bfloat162float(Bhz[bo]) + __bfloat162float(Blz[bo]);
                }
            }
            __syncthreads();
            #pragma unroll
            for (int kk = 0; kk < 16; kk++) {
                float a_[8], b_[8];
                #pragma unroll
                for (int q = 0; q < 8; q++) { a_[q] = As[kk*128 + tm + q]; b_[q] = Bs[kk*128 + tn + q]; }
                #pragma unroll
                for (int i = 0; i < 8; i++)
                    #pragma unroll
                    for (int j = 0; j < 8; j++)
                        acc[i][j] += a_[i] * b_[j];
            }
            __syncthreads();
        }
        #pragma unroll
        for (int i = 0; i < 8; i++) {
            int gm = m0 + tm + i;
            #pragma unroll
            for (int j = 0; j < 8; j++) {
                float t = acc[i][j];
                int col = n0s + tn + j;
                if (EPI >= 1) t += bias[(size_t)z * biasStride + col];
                if (EPI == 2) t += resid[(size_t)gm * Nt + col];
                if (EPI == 3) {
                    t = t > 0.f ? t * t : 0.f;
                    bf16 hv = __float2bfloat16_rn(t);
                    Chi[(size_t)z * cStride + (size_t)gm * Nt + col] = hv;
                    Clo[(size_t)z * cStride + (size_t)gm * Nt + col] = __float2bfloat16_rn(t - __bfloat162float(hv));
                } else if (EPI == 4) {
                    if (gm < cnt) {
                        int token = rowIdx[z * CAPX + gm];
                        atomicAdd(&Cf[(size_t)token * Nt + col], g0[token] * t);
                    }
                } else {
                    Cf[(size_t)z * cStride + (size_t)gm * Nt + col] = t;
                }
            }
        }
    }
#endif
}

// ---------------- block reduce ----------------
__device__ __forceinline__ float blockReduceSum(float v) {
    __shared__ float sh[32];
    int lane = threadIdx.x & 31, w = threadIdx.x >> 5;
    #pragma unroll
    for (int o = 16; o; o >>= 1) v += __shfl_down_sync(0xffffffffu, v, o);
    if (lane == 0) sh[w] = v;
    __syncthreads();
    int nw = blockDim.x >> 5;
    if (w == 0) {
        v = (lane < nw) ? sh[lane] : 0.f;
        #pragma unroll
        for (int o = 16; o; o >>= 1) v += __shfl_down_sync(0xffffffffu, v, o);
        if (lane == 0) sh[0] = v;
    }
    __syncthreads();
    return sh[0];
}

// ---------------- 1) residual mix + rmsnorm ----------------
__global__ void mix_rms_kernel(const float* __restrict__ x, const float* __restrict__ x0,
                               const float* __restrict__ lambdas) {
    int row = blockIdx.x;
    float l0 = lambdas[0], l1 = lambdas[1];
    size_t off = (size_t)row * CC + threadIdx.x * 4;
    float4 a = *(const float4*)(x + off);
    float4 b = *(const float4*)(x0 + off);
    float4 v;
    v.x = l0*a.x + l1*b.x; v.y = l0*a.y + l1*b.y;
    v.z = l0*a.z + l1*b.z; v.w = l0*a.w + l1*b.w;
    *(float4*)(g_xmix + off) = v;
    float ss = v.x*v.x + v.y*v.y + v.z*v.z + v.w*v.w;
    float tot = blockReduceSum(ss);
    float sc = rsqrtf(tot * (1.0f/CC) + 1e-6f);
    float4 o; o.x = v.x*sc; o.y = v.y*sc; o.z = v.z*sc; o.w = v.w*sc;
    uint2 hv, lv; split4(o, hv, lv);
    *(uint2*)(&g_abf[0][off]) = hv;
    *(uint2*)(&g_abf[1][off]) = lv;
}

// ---------------- 6) rmsnorm of x2 ----------------
__global__ void rms2_kernel(const float* __restrict__ src) {
    int row = blockIdx.x;
    size_t off = (size_t)row * CC + threadIdx.x * 4;
    float4 v = *(const float4*)(src + off);
    float ss = v.x*v.x + v.y*v.y + v.z*v.z + v.w*v.w;
    float tot = blockReduceSum(ss);
    float sc = rsqrtf(tot * (1.0f/CC) + 1e-6f);
    float4 o; o.x = v.x*sc; o.y = v.y*sc; o.z = v.z*sc; o.w = v.w*sc;
    *(float4*)(g_h + off) = o;
    uint2 hv, lv; split4(o, hv, lv);
    *(uint2*)(&g_hbf[0][off]) = hv;
    *(uint2*)(&g_hbf[1][off]) = lv;
}

// ---------------- 3) per-head rmsnorm + rotary ----------------
__global__ void qk_rot_kernel() {
    int gw = blockIdx.x * (blockDim.x >> 5) + (threadIdx.x >> 5);
    int lane = threadIdx.x & 31;
    int qk = gw >> 16;
    int r  = gw & 65535;
    int n  = r >> 4;
    int h  = r & 15;
    const float* p = g_qkv + (size_t)qk * NTOK * CC + (size_t)n * CC + h * HD;
    float x1 = p[lane], x2 = p[lane + 32];
    float ss = x1 * x1 + x2 * x2;
    #pragma unroll
    for (int o = 16; o; o >>= 1) ss += __shfl_xor_sync(0xffffffffu, ss, o);
    float sc = rsqrtf(ss * (1.0f/HD) + 1e-6f);
    x1 *= sc; x2 *= sc;
    int b = n >> 11, t = n & (TT - 1);
    float invj = (lane < 16) ? c_rotinv[lane] : 0.f;
    float th = (float)t * invj;
    float c = cosf(th), s = sinf(th);
    float y1 =  x1 * c + x2 * s;
    float y2 = -x1 * s + x2 * c;
    size_t base = ((size_t)(b * HH + h) * TT + t) * HD;
    bf16* hi = qk ? g_kbf[0] : g_qbf[0];
    bf16* lo = qk ? g_kbf[1] : g_qbf[1];
    bf16 h1 = __float2bfloat16_rn(y1), h2 = __float2bfloat16_rn(y2);
    hi[base + lane]      = h1;
    hi[base + lane + 32] = h2;
    lo[base + lane]      = __float2bfloat16_rn(y1 - __bfloat162float(h1));
    lo[base + lane + 32] = __float2bfloat16_rn(y2 - __bfloat162float(h2));
}

// ---------------- 3b) V transpose+convert ----------------
__global__ __launch_bounds__(256) void vT_kernel() {
    __shared__ float s[128][65];
    int tblk = blockIdx.x, bh = blockIdx.y;
    int b = bh >> 4, h = bh & 15;
    int t0 = tblk * 128;
    const float* vsrc = g_qkv + (size_t)2 * NTOK * CC;
    #pragma unroll
    for (int i = 0; i < 32; i++) {
        int f = threadIdx.x + i * 256;
        int t = f >> 6, d = f & 63;
        s[t][d] = vsrc[((size_t)(b * TT + t0 + t)) * CC + h * HD + d];
    }
    __syncthreads();
    #pragma unroll
    for (int i = 0; i < 32; i++) {
        int f = threadIdx.x + i * 256;
        int d = f >> 7, t = f & 127;
        float v = s[t][d];
        bf16 hv = __float2bfloat16_rn(v);
        size_t off = ((size_t)(bh * HD + d)) * TT + t0 + t;
        g_vT[0][off] = hv;
        g_vT[1][off] = __float2bfloat16_rn(v - __bfloat162float(hv));
    }
}

// ---------------- 4) pipelined tensor-core causal attention ----------------
#define AT_QHI 2048
#define AT_QLO (AT_QHI + 16384)
#define AT_KBUF 34816
#define AT_VBUF (AT_KBUF + 3*32768)
#define SMEM_ATT (AT_VBUF + 2*32768)
#define AT_L2 128

__global__ __launch_bounds__(256) void attn_tc() {
    extern __shared__ char smem[];
    int qtile = gridDim.x - 1 - blockIdx.x;   // LPT
    int bh = blockIdx.y;
    int b = bh >> 4, h = bh & 15;
    int q0 = qtile * 128;
    int tid = threadIdx.x, wid = tid >> 5, lane = tid & 31;
    int half = wid >> 2;
    int row = (wid & 3) * 32 + lane;

    const bf16* qh_g = g_qbf[0] + ((size_t)bh * TT + q0) * HD;
    const bf16* ql_g = g_qbf[1] + ((size_t)bh * TT + q0) * HD;

#if USE_TC
    uint32_t sbase = smem_u32(smem);
    const uint32_t MBS = sbase + 8, MBA = sbase + 16;
    float* l2s = (float*)(smem + AT_L2);
    if (tid == 0) { MBAR_INIT(MBS, 1); MBAR_INIT(MBA, 1); }

    auto load_K = [&](int kt) {
        uint32_t kb = sbase + AT_KBUF + (uint32_t)(kt % 3) * 32768;
        const bf16* kh_g = g_kbf[0] + ((size_t)bh * TT + kt * 128) * HD;
        const bf16* kl_g = g_kbf[1] + ((size_t)bh * TT + kt * 128) * HD;
        #pragma unroll
        for (int i = 0; i < 4; i++) {
            int f = tid + i * 256;
            int r = f >> 3, c8 = f & 7;
            uint32_t so = sw128((uint32_t)(r * 128 + c8 * 16));
            cpa16(kb + so,         kh_g + (size_t)r * HD + c8 * 8);
            cpa16(kb + 16384 + so, kl_g + (size_t)r * HD + c8 * 8);
        }
    };
    auto load_V = [&](int kt) {
        uint32_t vb = sbase + AT_VBUF + (uint32_t)(kt & 1) * 32768;
        const bf16* vh_g = g_vT[0] + (size_t)bh * HD * TT + kt * 128;
        const bf16* vl_g = g_vT[1] + (size_t)bh * HD * TT + kt * 128;
        #pragma unroll
        for (int i = 0; i < 4; i++) {
            int f = tid + i * 256;
            int d = f >> 4, c16 = f & 15;
            uint32_t byte = (uint32_t)((d >> 3) * 1024 + (c16 >> 3) * 8192 + (d & 7) * 128 + (c16 & 7) * 16);
            uint32_t so = sw128(byte);
            cpa16(vb + so,         vh_g + (size_t)d * TT + c16 * 8);
            cpa16(vb + 16384 + so, vl_g + (size_t)d * TT + c16 * 8);
        }
    };

    {
        #pragma unroll
        for (int i = 0; i < 4; i++) {
            int f = tid + i * 256;
            int r = f >> 3, c8 = f & 7;
            uint32_t so = sw128((uint32_t)(r * 128 + c8 * 16));
            cpa16(sbase + AT_QHI + so, qh_g + (size_t)r * HD + c8 * 8);
            cpa16(sbase + AT_QLO + so, ql_g + (size_t)r * HD + c8 * 8);
        }
        load_K(0);
        load_V(0);
        CPA_COMMIT();
        if (qtile >= 1) { load_K(1); CPA_COMMIT(); }
    }
    if (wid == 0) { TC_ALLOC(sbase + 0, 512u); }
    __syncthreads();
    uint32_t tmem = *(uint32_t*)(smem + 0);
    const uint32_t S0 = 0, O_OFF = 256, P0 = 320;
    const uint32_t IDS = (1u<<4)|(1u<<7)|(1u<<10)|(16u<<17)|(8u<<24);  // N=128
    const uint32_t IDA = (1u<<4)|(1u<<7)|(1u<<10)|( 8u<<17)|(8u<<24);  // N=64

    CPA_WAIT(0);
    asm volatile("fence.proxy.async.shared::cta;" ::: "memory");
    __syncthreads();

    uint64_t qhd = make_desc(sbase + AT_QHI);
    uint64_t qld = make_desc(sbase + AT_QLO);

    auto issue_S = [&](int kt) {
        uint32_t kb = sbase + AT_KBUF + (uint32_t)(kt % 3) * 32768;
        uint64_t kh = make_desc(kb);
        uint64_t kl = make_desc(kb + 16384);
        uint32_t sd = tmem + S0 + (uint32_t)(kt & 1) * 128;
        #pragma unroll
        for (int ks = 0; ks < 4; ks++) {
            uint64_t o = ks * 2;
            mma_ss_bf16(sd, qhd + o, kh + o, IDS, ks > 0 ? 1u : 0u);
            mma_ss_bf16(sd, qhd + o, kl + o, IDS, 1u);
            mma_ss_bf16(sd, qld + o, kh + o, IDS, 1u);
        }
        TC_COMMIT(MBS);
    };

    if (wid == 0 && elect_one()) issue_S(0);

    float l = 0.f;
    int phS = 0, phA = 0;

    for (int kt = 0; kt <= qtile; kt++) {
        int sbuf = kt & 1;
        if (kt + 2 <= qtile) { load_K(kt + 2); CPA_COMMIT(); }
        mbar_wait(MBS, phS); phS ^= 1;
        TC_FENCE_AFTER();
        if (kt + 2 <= qtile) { CPA_WAIT(1); } else { CPA_WAIT(0); }
        asm volatile("fence.proxy.async.shared::cta;" ::: "memory");
        __syncthreads();
        if (kt < qtile && wid == 0) {
            if (elect_one()) { TC_FENCE_AFTER(); issue_S(kt + 1); }
        }

        uint32_t sr[64];
        TC_LD_X32(sr, tmem + S0 + sbuf * 128 + half * 64);
        TC_WAIT_LD();
        TC_LD_X32(sr + 32, tmem + S0 + sbuf * 128 + half * 64 + 32);

        int qg = q0 + row;
        int kbase = kt * 128 + half * 64;
        bool maskTile = (kt == qtile);
        uint32_t pw[32];
        float lacc = 0.f;
        #pragma unroll
        for (int j2 = 0; j2 < 16; j2++) {
            float s0v = __uint_as_float(sr[2*j2])   * 0.125f;
            float s1v = __uint_as_float(sr[2*j2+1]) * 0.125f;
            float p0 = __expf(s0v), p1 = __expf(s1v);
            if (maskTile) {
                if (kbase + 2*j2     > qg) p0 = 0.f;
                if (kbase + 2*j2 + 1 > qg) p1 = 0.f;
            }
            bf162 pb = __floats2bfloat162_rn(p0, p1);
            lacc += __bfloat162float(pb.x) + __bfloat162float(pb.y);
            pw[j2] = *(uint32_t*)&pb;
        }
        TC_WAIT_LD();
        #pragma unroll
        for (int j2 = 16; j2 < 32; j2++) {
            float s0v = __uint_as_float(sr[2*j2])   * 0.125f;
            float s1v = __uint_as_float(sr[2*j2+1]) * 0.125f;
            float p0 = __expf(s0v), p1 = __expf(s1v);
            if (maskTile) {
                if (kbase + 2*j2     > qg) p0 = 0.f;
                if (kbase + 2*j2 + 1 > qg) p1 = 0.f;
            }
            bf162 pb = __floats2bfloat162_rn(p0, p1);
            lacc += __bfloat162float(pb.x) + __bfloat162float(pb.y);
            pw[j2] = *(uint32_t*)&pb;
        }
        l += lacc;

        if (kt > 0) { mbar_wait(MBA, phA); phA ^= 1; }

        if (kt < qtile) { load_V(kt + 1); CPA_COMMIT(); }

        TC_ST_X32(tmem + P0 + sbuf * 64 + half * 32 + ((uint32_t)(wid & 3) << 21), pw);
        TC_WAIT_ST();
        TC_FENCE_BEFORE();
        __syncthreads();

        if (wid == 0 && elect_one()) {
            TC_FENCE_AFTER();
            uint32_t vb = sbase + AT_VBUF + (uint32_t)sbuf * 32768;
            uint64_t vh = make_desc(vb);
            uint64_t vl = make_desc(vb + 16384);
            #pragma unroll
            for (int ks = 0; ks < 8; ks++) {
                uint64_t vo = (uint64_t)((ks & 3) * 2 + (ks >> 2) * 512);
                uint32_t at = tmem + P0 + sbuf * 64 + ks * 8;
                mma_ts_bf16(tmem + O_OFF, at, vh + vo, IDA, (kt > 0 || ks > 0) ? 1u : 0u);
                mma_ts_bf16(tmem + O_OFF, at, vl + vo, IDA, 1u);
            }
            TC_COMMIT(MBA);
        }
    }
    mbar_wait(MBA, phA);
    TC_FENCE_AFTER();

    l2s[half * 128 + row] = l;
    __syncthreads();
    float inv = 1.f / (l2s[row] + l2s[128 + row]);

    uint32_t od[32];
    TC_LD_X32(od, tmem + O_OFF + half * 32);
    TC_WAIT_LD();
    int token = b * TT + q0 + row;
    bf16* ohp = g_obf[0] + (size_t)token * CC + h * HD + half * 32;
    bf16* olp = g_obf[1] + (size_t)token * CC + h * HD + half * 32;
    #pragma unroll
    for (int j = 0; j < 32; j += 4) {
        float4 v;
        v.x = __uint_as_float(od[j+0]) * inv;
        v.y = __uint_as_float(od[j+1]) * inv;
        v.z = __uint_as_float(od[j+2]) * inv;
        v.w = __uint_as_float(od[j+3]) * inv;
        uint2 hv, lv; split4(v, hv, lv);
        *(uint2*)(ohp + j) = hv; *(uint2*)(olp + j) = lv;
    }
    TC_FENCE_BEFORE();
    __syncthreads();
    if (wid == 0) { TC_RELINQ(); TC_DEALLOC(tmem, 512u); }

#else // SIMT fallback attention
    for (int qq = tid; qq < 128; qq += 256) {
        int qg = q0 + qq;
        float q[HD], o[HD];
        #pragma unroll
        for (int d = 0; d < HD; d++) {
            q[d] = (__bfloat162float(qh_g[(size_t)qq*HD+d]) + __bfloat162float(ql_g[(size_t)qq*HD+d])) * 0.125f;
            o[d] = 0.f;
        }
        float l = 0.f;
        for (int k = 0; k <= qg; k++) {
            const bf16* kh_g = g_kbf[0] + ((size_t)bh * TT + k) * HD;
            const bf16* kl_g = g_kbf[1] + ((size_t)bh * TT + k) * HD;
            float s = 0.f;
            #pragma unroll
            for (int d = 0; d < HD; d++)
                s += q[d] * (__bfloat162float(kh_g[d]) + __bfloat162float(kl_g[d]));
            float p = __expf(s);
            l += p;
            #pragma unroll
            for (int d = 0; d < HD; d++) {
                size_t vo = ((size_t)bh * HD + d) * TT + k;
                o[d] += p * (__bfloat162float(g_vT[0][vo]) + __bfloat162float(g_vT[1][vo]));
            }
        }
        float inv = 1.f / l;
        int token = b * TT + qg;
        #pragma unroll
        for (int d = 0; d < HD; d++) {
            float v = o[d] * inv;
            bf16 hv = __float2bfloat16_rn(v);
            g_obf[0][(size_t)token * CC + h * HD + d] = hv;
            g_obf[1][(size_t)token * CC + h * HD + d] = __float2bfloat16_rn(v - __bfloat162float(hv));
        }
    }
#endif
}

// ---------------- 7) router ----------------
__global__ void router_kernel(const float* __restrict__ rw, const float* __restrict__ rb,
                              const float* __restrict__ nw, const float* __restrict__ nb,
                              const float* __restrict__ noise) {
    int n = blockIdx.x;
    int w = threadIdx.x >> 5, lane = threadIdx.x & 31;
    const float* hr = g_h + (size_t)n * CC;
    const float* wr = rw + (size_t)w * CC;
    const float* wn = nw + (size_t)w * CC;
    float s1 = 0.f, s2 = 0.f;
    for (int c = lane * 4; c < CC; c += 128) {
        float4 hv = *(const float4*)(hr + c);
        float4 r4 = *(const float4*)(wr + c);
        float4 n4 = *(const float4*)(wn + c);
        s1 += hv.x*r4.x + hv.y*r4.y + hv.z*r4.z + hv.w*r4.w;
        s2 += hv.x*n4.x + hv.y*n4.y + hv.z*n4.z + hv.w*n4.w;
    }
    #pragma unroll
    for (int o = 16; o; o >>= 1) {
        s1 += __shfl_xor_sync(0xffffffffu, s1, o);
        s2 += __shfl_xor_sync(0xffffffffu, s2, o);
    }
    __shared__ float lg[8], nl[8];
    if (lane == 0) { lg[w] = s1 + rb[w]; nl[w] = s2 + nb[w]; }
    __syncthreads();
    if (threadIdx.x == 0) {
        float nv[8];
        #pragma unroll
        for (int e = 0; e < 8; e++) {
            float xn = nl[e];
            float sp = (xn > 20.f) ? xn : log1pf(expf(xn));
            nv[e] = lg[e] + noise[(size_t)n * EE + e] * sp;
        }
        int i0 = 0; float v0 = nv[0];
        #pragma unroll
        for (int e = 1; e < 8; e++) if (nv[e] > v0) { v0 = nv[e]; i0 = e; }
        float v1 = -1e30f;
        #pragma unroll
        for (int e = 0; e < 8; e++) if (e != i0 && nv[e] > v1) { v1 = nv[e]; }
        float e1 = expf(v1 - v0);
        g_g0[n] = 1.f / (1.f + e1);
        g_eid[n] = i0;
    }
}

// ---------------- 8) per-expert capacity lists ----------------
__global__ void build_idx_kernel() {
    int w = threadIdx.x >> 5, lane = threadIdx.x & 31;
    int count = 0;
    for (int base = 0; base < NTOK; base += 32) {
        int t = base + lane;
        bool p = (g_eid[t] == w);
        unsigned msk = __ballot_sync(0xffffffffu, p);
        int pos = count + __popc(msk & ((1u << lane) - 1u));
        if (p && pos < CAPX) g_idx[w * CAPX + pos] = t;
        count += __popc(msk);
    }
    int c = min(count, CAPX);
    if (lane == 0) g_cnt[w] = c;
    for (int s = c + lane; s < CAPX; s += 32) g_idx[w * CAPX + s] = NTOK;
}

// ---------------- host launcher ----------------
extern "C" void kernel_launch(void* const* d_in, const int* in_sizes, int n_in,
                              void* d_out, int out_size) {
    const float* x        = (const float*)d_in[0];
    const float* x0       = (const float*)d_in[1];
    const float* noise    = (const float*)d_in[2];
    const float* lambdas  = (const float*)d_in[3];
    const float* qkv_w    = (const float*)d_in[5];
    const float* c_proj_w = (const float*)d_in[6];
    const float* c_proj_b = (const float*)d_in[7];
    const float* router_w = (const float*)d_in[8];
    const float* router_b = (const float*)d_in[9];
    const float* noise_w  = (const float*)d_in[10];
    const float* noise_b  = (const float*)d_in[11];
    const float* ew1      = (const float*)d_in[12];
    const float* eb1      = (const float*)d_in[13];
    const float* ew2      = (const float*)d_in[14];
    const float* eb2      = (const float*)d_in[15];
    float* out = (float*)d_out;

    void *p_qkv, *p_xmix, *p_h, *p_idx, *p_cnt, *p_g0;
    void *p_abf, *p_obf, *p_hbf, *p_h1bf, *p_wqkv, *p_wcp, *p_we1, *p_we2;
    cudaGetSymbolAddress(&p_qkv,  g_qkv);
    cudaGetSymbolAddress(&p_xmix, g_xmix);
    cudaGetSymbolAddress(&p_h,    g_h);
    cudaGetSymbolAddress(&p_idx,  g_idx);
    cudaGetSymbolAddress(&p_cnt,  g_cnt);
    cudaGetSymbolAddress(&p_g0,   g_g0);
    cudaGetSymbolAddress(&p_abf,  g_abf);
    cudaGetSymbolAddress(&p_obf,  g_obf);
    cudaGetSymbolAddress(&p_hbf,  g_hbf);
    cudaGetSymbolAddress(&p_h1bf, g_h1bf);
    cudaGetSymbolAddress(&p_wqkv, g_wqkv);
    cudaGetSymbolAddress(&p_wcp,  g_wcp);
    cudaGetSymbolAddress(&p_we1,  g_we1);
    cudaGetSymbolAddress(&p_we2,  g_we2);

    bf16* abf_h  = (bf16*)p_abf;   bf16* abf_l  = abf_h  + (size_t)NTOK*CC;
    bf16* obf_h  = (bf16*)p_obf;   bf16* obf_l  = obf_h  + (size_t)NTOK*CC;
    bf16* hbf_h  = (bf16*)p_hbf;   bf16* hbf_l  = hbf_h  + (size_t)NTOK*CC;
    bf16* h1_h   = (bf16*)p_h1bf;  bf16* h1_l   = h1_h   + (size_t)EE*CAPX*HID;
    bf16* wqkv_h = (bf16*)p_wqkv;  bf16* wqkv_l = wqkv_h + (size_t)3*CC*CC;
    bf16* wcp_h  = (bf16*)p_wcp;   bf16* wcp_l  = wcp_h  + (size_t)CC*CC;
    bf16* we1_h  = (bf16*)p_we1;   bf16* we1_l  = we1_h  + (size_t)EE*HID*CC;
    bf16* we2_h  = (bf16*)p_we2;   bf16* we2_l  = we2_h  + (size_t)EE*CC*HID;

    cudaFuncSetAttribute(gemm_bf<0,false,false>, cudaFuncAttributeMaxDynamicSharedMemorySize, SMEM_TOTAL_TC);
    cudaFuncSetAttribute(gemm_bf<2,false,false>, cudaFuncAttributeMaxDynamicSharedMemorySize, SMEM_TOTAL_TC);
    cudaFuncSetAttribute(gemm_bf<3,true, true >, cudaFuncAttributeMaxDynamicSharedMemorySize, SMEM_TOTAL_TC);
    cudaFuncSetAttribute(gemm_bf<4,false,true >, cudaFuncAttributeMaxDynamicSharedMemorySize, SMEM_TOTAL_TC);
    cudaFuncSetAttribute(attn_tc, cudaFuncAttributeMaxDynamicSharedMemorySize, SMEM_ATT);

    // ---- fork a side stream for the big weight conversions (captured as
    // parallel graph branches; created per call — host API, no device alloc)
    cudaStream_t s2;
    cudaStreamCreateWithFlags(&s2, cudaStreamNonBlocking);
    cudaEvent_t evFork, evJoinCp, evJoinMoE;
    cudaEventCreateWithFlags(&evFork,    cudaEventDisableTiming);
    cudaEventCreateWithFlags(&evJoinCp,  cudaEventDisableTiming);
    cudaEventCreateWithFlags(&evJoinMoE, cudaEventDisableTiming);

    cudaEventRecord(evFork, 0);
    cudaStreamWaitEvent(s2, evFork, 0);

    // side stream: c_proj conv (needed at step 5), then MoE weight convs (steps 9/10)
    conv_kernel<<<(CC*CC/4 + 255)/256, 256, 0, s2>>>(c_proj_w, wcp_h, wcp_l, (long)CC*CC/4);
    cudaEventRecord(evJoinCp, s2);
    conv_kernel<<<((long)EE*HID*CC/4 + 255)/256, 256, 0, s2>>>(ew1, we1_h, we1_l, (long)EE*HID*CC/4);
    conv_kernel<<<((long)EE*CC*HID/4 + 255)/256, 256, 0, s2>>>(ew2, we2_h, we2_l, (long)EE*CC*HID/4);
    cudaEventRecord(evJoinMoE, s2);

    // main stream: qkv weight conv (needed immediately) + everything else
    conv_kernel<<<(3*CC*CC/4 + 255)/256, 256>>>(qkv_w, wqkv_h, wqkv_l, (long)3*CC*CC/4);

    mix_rms_kernel<<<NTOK, 256>>>(x, x0, lambdas);

    gemm_bf<0,false,false><<<dim3(CC/256, NTOK/128, 3), 256, SMEM_TOTAL_TC>>>(
        abf_h, abf_l, 0L, wqkv_h, wqkv_l, (long)CC*CC,
        (float*)p_qkv, nullptr, nullptr, (long)NTOK*CC,
        nullptr, 0, nullptr, nullptr, nullptr, nullptr, CC, CC);

    qk_rot_kernel<<<(2 * NTOK * HH) / 8, 256>>>();
    vT_kernel<<<dim3(TT/128, 2*HH), 256>>>();

    attn_tc<<<dim3(TT/128, 2*HH), 256, SMEM_ATT>>>();

    // join: c_proj weights ready
    cudaStreamWaitEvent(0, evJoinCp, 0);
    gemm_bf<2,false,false><<<dim3(CC/256, NTOK/128, 1), 256, SMEM_TOTAL_TC>>>(
        obf_h, obf_l, 0L, wcp_h, wcp_l, 0L,
        out, nullptr, nullptr, 0L,
        c_proj_b, 0, (const float*)p_xmix, nullptr, nullptr, nullptr, CC, CC);

    rms2_kernel<<<NTOK, 256>>>(out);

    router_kernel<<<NTOK, 256>>>(router_w, router_b, noise_w, noise_b, noise);
    build_idx_kernel<<<1, 256>>>();

    // join: MoE weights ready
    cudaStreamWaitEvent(0, evJoinMoE, 0);

    gemm_bf<3,true,true><<<dim3(HID/256, CAPX/128, EE), 256, SMEM_TOTAL_TC>>>(
        hbf_h, hbf_l, 0L, we1_h, we1_l, (long)HID*CC,
        nullptr, h1_h, h1_l, (long)CAPX*HID,
        eb1, HID, nullptr, (const int*)p_idx, (const int*)p_cnt, nullptr, HID, CC);

    gemm_bf<4,false,true><<<dim3(CC/256, CAPX/128, EE), 256, SMEM_TOTAL_TC>>>(
        h1_h, h1_l, (long)CAPX*HID, we2_h, we2_l, (long)CC*HID,
        out, nullptr, nullptr, 0L,
        eb2, CC, nullptr, (const int*)p_idx, (const int*)p_cnt, (const float*)p_g0, CC, HID);

    // release per-call handles (host-side only; safe post-capture of their nodes)
    cudaEventDestroy(evFork);
    cudaEventDestroy(evJoinCp);
    cudaEventDestroy(evJoinMoE);
    cudaStreamDestroy(s2);
}